// round 1
// baseline (speedup 1.0000x reference)
#include <cuda_runtime.h>

// Problem constants
#define B_  4
#define N_  2048
#define D_  512
#define H_  8
#define HD_ 64

// Scratch (allocation-free rule: __device__ globals)
static __device__ float g_q [B_ * N_ * D_];
static __device__ float g_k [B_ * N_ * D_];
static __device__ float g_v [B_ * N_ * D_];
static __device__ float g_ao[B_ * N_ * D_];

// ---------------------------------------------------------------------------
// Tiled SGEMM with bias: C[M,N] = A[M,K] @ W[K,N] + bias[N]
// BM=BN=128, BK=16, 256 threads, 8x8 per thread.
// ---------------------------------------------------------------------------
__global__ __launch_bounds__(256) void gemm_bias_kernel(
    const float* __restrict__ A, const float* __restrict__ W,
    const float* __restrict__ bias, float* __restrict__ C,
    int M, int N, int K)
{
    __shared__ float As[16][132];   // transposed A tile, padded
    __shared__ float Bs[16][128];

    const int tid = threadIdx.x;
    const int block_row = blockIdx.y * 128;
    const int block_col = blockIdx.x * 128;
    const int tr = tid / 16;        // 0..15
    const int tc = tid % 16;        // 0..15

    // A loader: 128 rows x 16 cols, float4, 2 passes of 64 rows
    const int arow = tid / 4;            // 0..63
    const int acol = (tid % 4) * 4;      // 0,4,8,12
    // B loader: 16 rows x 128 cols, float4, 2 passes of 8 rows
    const int brow = tid / 32;           // 0..7
    const int bcol = (tid % 32) * 4;

    float acc[8][8];
    #pragma unroll
    for (int i = 0; i < 8; i++)
        #pragma unroll
        for (int j = 0; j < 8; j++) acc[i][j] = 0.f;

    for (int k0 = 0; k0 < K; k0 += 16) {
        #pragma unroll
        for (int p = 0; p < 2; p++) {
            int r = arow + p * 64;
            float4 av = *(const float4*)(A + (size_t)(block_row + r) * K + k0 + acol);
            As[acol + 0][r] = av.x;
            As[acol + 1][r] = av.y;
            As[acol + 2][r] = av.z;
            As[acol + 3][r] = av.w;
        }
        #pragma unroll
        for (int p = 0; p < 2; p++) {
            int r = brow + p * 8;
            *(float4*)&Bs[r][bcol] =
                *(const float4*)(W + (size_t)(k0 + r) * N + block_col + bcol);
        }
        __syncthreads();

        #pragma unroll
        for (int kk = 0; kk < 16; kk++) {
            float4 a0 = *(const float4*)&As[kk][tr * 8];
            float4 a1 = *(const float4*)&As[kk][tr * 8 + 4];
            float4 b0 = *(const float4*)&Bs[kk][tc * 8];
            float4 b1 = *(const float4*)&Bs[kk][tc * 8 + 4];
            float ra[8] = {a0.x, a0.y, a0.z, a0.w, a1.x, a1.y, a1.z, a1.w};
            float rb[8] = {b0.x, b0.y, b0.z, b0.w, b1.x, b1.y, b1.z, b1.w};
            #pragma unroll
            for (int i = 0; i < 8; i++)
                #pragma unroll
                for (int j = 0; j < 8; j++)
                    acc[i][j] += ra[i] * rb[j];
        }
        __syncthreads();
    }

    #pragma unroll
    for (int i = 0; i < 8; i++) {
        int r = block_row + tr * 8 + i;
        #pragma unroll
        for (int j = 0; j < 8; j += 4) {
            int c = block_col + tc * 8 + j;
            float4 bv = *(const float4*)(bias + c);
            float4 o;
            o.x = acc[i][j + 0] + bv.x;
            o.y = acc[i][j + 1] + bv.y;
            o.z = acc[i][j + 2] + bv.z;
            o.w = acc[i][j + 3] + bv.w;
            *(float4*)(C + (size_t)r * N + c) = o;
        }
    }
}

// ---------------------------------------------------------------------------
// Fused masked flash attention per (b, h, q-tile of 64).
// 256 threads as 16x16; each thread owns a 4x4 micro-tile of S/O.
// Online softmax; mask = (1 - adj) * (-1e9); scale = 1/sqrt(64) = 0.125.
// ---------------------------------------------------------------------------
#define QT_PITCH 68
#define PS_PITCH 68

__global__ __launch_bounds__(256) void attn_kernel(
    const float* __restrict__ q, const float* __restrict__ k,
    const float* __restrict__ v, const float* __restrict__ adj,
    float* __restrict__ o)
{
    extern __shared__ float sm[];
    float* QsT  = sm;                          // [64][68] (d-major)
    float* KsT  = QsT + 64 * QT_PITCH;         // [64][68] (d-major)
    float* Vs   = KsT + 64 * QT_PITCH;         // [64][64] (key-major)
    float* Ps   = Vs  + 64 * 64;               // [64][68]
    float* Adjs = Ps  + 64 * PS_PITCH;         // [64][64]

    const int tid = threadIdx.x;
    const int ty = tid / 16;                   // row group 0..15
    const int tx = tid % 16;                   // col group 0..15
    const int q0 = blockIdx.x * 64;
    const int h  = blockIdx.y;
    const int b  = blockIdx.z;

    const float* qbase = q + (size_t)b * N_ * D_ + h * HD_;
    const float* kbase = k + (size_t)b * N_ * D_ + h * HD_;
    const float* vbase = v + (size_t)b * N_ * D_ + h * HD_;

    // Load Q tile transposed (QsT[d][row])
    for (int i = tid; i < 64 * 16; i += 256) {
        int r  = i / 16;
        int c4 = (i % 16) * 4;
        float4 val = *(const float4*)(qbase + (size_t)(q0 + r) * D_ + c4);
        QsT[(c4 + 0) * QT_PITCH + r] = val.x;
        QsT[(c4 + 1) * QT_PITCH + r] = val.y;
        QsT[(c4 + 2) * QT_PITCH + r] = val.z;
        QsT[(c4 + 3) * QT_PITCH + r] = val.w;
    }

    float Ot[4][4];
    float m_i[4], l_i[4];
    #pragma unroll
    for (int r = 0; r < 4; r++) {
        m_i[r] = -1e30f;
        l_i[r] = 0.f;
        #pragma unroll
        for (int c = 0; c < 4; c++) Ot[r][c] = 0.f;
    }

    for (int k0 = 0; k0 < N_; k0 += 64) {
        __syncthreads();   // previous PV finished reading Vs/Ps
        // Load K tile (transposed), V tile, adj tile
        for (int i = tid; i < 64 * 16; i += 256) {
            int r  = i / 16;
            int c4 = (i % 16) * 4;
            float4 kv = *(const float4*)(kbase + (size_t)(k0 + r) * D_ + c4);
            KsT[(c4 + 0) * QT_PITCH + r] = kv.x;
            KsT[(c4 + 1) * QT_PITCH + r] = kv.y;
            KsT[(c4 + 2) * QT_PITCH + r] = kv.z;
            KsT[(c4 + 3) * QT_PITCH + r] = kv.w;
            *(float4*)&Vs[r * 64 + c4] =
                *(const float4*)(vbase + (size_t)(k0 + r) * D_ + c4);
            *(float4*)&Adjs[r * 64 + c4] =
                *(const float4*)(adj + (size_t)(q0 + r) * N_ + k0 + c4);
        }
        __syncthreads();

        // S = Q @ K^T (4x4 per thread)
        float s[4][4];
        #pragma unroll
        for (int r = 0; r < 4; r++)
            #pragma unroll
            for (int c = 0; c < 4; c++) s[r][c] = 0.f;

        #pragma unroll 8
        for (int d = 0; d < 64; d++) {
            float4 rq4 = *(const float4*)&QsT[d * QT_PITCH + ty * 4];
            float4 rk4 = *(const float4*)&KsT[d * QT_PITCH + tx * 4];
            float rq[4] = {rq4.x, rq4.y, rq4.z, rq4.w};
            float rk[4] = {rk4.x, rk4.y, rk4.z, rk4.w};
            #pragma unroll
            for (int r = 0; r < 4; r++)
                #pragma unroll
                for (int c = 0; c < 4; c++)
                    s[r][c] += rq[r] * rk[c];
        }

        // Scale + mask, then online softmax per row
        #pragma unroll
        for (int r = 0; r < 4; r++) {
            float4 a4 = *(const float4*)&Adjs[(ty * 4 + r) * 64 + tx * 4];
            float am[4] = {a4.x, a4.y, a4.z, a4.w};
            #pragma unroll
            for (int c = 0; c < 4; c++)
                s[r][c] = s[r][c] * 0.125f + (1.0f - am[c]) * (-1e9f);

            float mx = s[r][0];
            #pragma unroll
            for (int c = 1; c < 4; c++) mx = fmaxf(mx, s[r][c]);
            #pragma unroll
            for (int off = 1; off < 16; off <<= 1)
                mx = fmaxf(mx, __shfl_xor_sync(0xffffffffu, mx, off));

            float m_new = fmaxf(m_i[r], mx);
            float alpha = __expf(m_i[r] - m_new);

            float ps[4];
            float rowsum = 0.f;
            #pragma unroll
            for (int c = 0; c < 4; c++) {
                ps[c] = __expf(s[r][c] - m_new);
                rowsum += ps[c];
            }
            #pragma unroll
            for (int off = 1; off < 16; off <<= 1)
                rowsum += __shfl_xor_sync(0xffffffffu, rowsum, off);

            l_i[r] = l_i[r] * alpha + rowsum;
            m_i[r] = m_new;
            #pragma unroll
            for (int c = 0; c < 4; c++) Ot[r][c] *= alpha;

            *(float4*)&Ps[(ty * 4 + r) * PS_PITCH + tx * 4] =
                make_float4(ps[0], ps[1], ps[2], ps[3]);
        }
        __syncthreads();

        // O += P @ V
        #pragma unroll 4
        for (int kk = 0; kk < 64; kk += 4) {
            float rv[4][4];
            #pragma unroll
            for (int u = 0; u < 4; u++)
                *(float4*)rv[u] = *(const float4*)&Vs[(kk + u) * 64 + tx * 4];
            #pragma unroll
            for (int r = 0; r < 4; r++) {
                float4 p4 = *(const float4*)&Ps[(ty * 4 + r) * PS_PITCH + kk];
                float pr[4] = {p4.x, p4.y, p4.z, p4.w};
                #pragma unroll
                for (int u = 0; u < 4; u++)
                    #pragma unroll
                    for (int c = 0; c < 4; c++)
                        Ot[r][c] += pr[u] * rv[u][c];
            }
        }
    }

    // Finalize: divide by l and store to attention-out scratch [b, q, h, hd]
    float* obase = o + (size_t)b * N_ * D_ + h * HD_;
    #pragma unroll
    for (int r = 0; r < 4; r++) {
        float inv = 1.0f / l_i[r];
        int row = q0 + ty * 4 + r;
        float4 ov = make_float4(Ot[r][0] * inv, Ot[r][1] * inv,
                                Ot[r][2] * inv, Ot[r][3] * inv);
        *(float4*)(obase + (size_t)row * D_ + tx * 4) = ov;
    }
}

// ---------------------------------------------------------------------------
extern "C" void kernel_launch(void* const* d_in, const int* in_sizes, int n_in,
                              void* d_out, int out_size)
{
    const float* x   = (const float*)d_in[0];
    const float* adj = (const float*)d_in[1];
    const float* Wq  = (const float*)d_in[2];
    const float* bq  = (const float*)d_in[3];
    const float* Wk  = (const float*)d_in[4];
    const float* bk  = (const float*)d_in[5];
    const float* Wv  = (const float*)d_in[6];
    const float* bv  = (const float*)d_in[7];
    const float* Wo  = (const float*)d_in[8];
    const float* bo  = (const float*)d_in[9];
    float* out = (float*)d_out;

    float *pq, *pk, *pv, *pa;
    cudaGetSymbolAddress((void**)&pq, g_q);
    cudaGetSymbolAddress((void**)&pk, g_k);
    cudaGetSymbolAddress((void**)&pv, g_v);
    cudaGetSymbolAddress((void**)&pa, g_ao);

    const int M = B_ * N_;           // 8192
    dim3 ggrid(D_ / 128, M / 128);   // (4, 64)

    gemm_bias_kernel<<<ggrid, 256>>>(x, Wq, bq, pq, M, D_, D_);
    gemm_bias_kernel<<<ggrid, 256>>>(x, Wk, bk, pk, M, D_, D_);
    gemm_bias_kernel<<<ggrid, 256>>>(x, Wv, bv, pv, M, D_, D_);

    size_t smem = (size_t)(64 * QT_PITCH * 2 + 64 * 64 * 2 + 64 * PS_PITCH)
                  * sizeof(float);   // ~85 KB
    cudaFuncSetAttribute(attn_kernel,
                         cudaFuncAttributeMaxDynamicSharedMemorySize,
                         (int)smem);
    attn_kernel<<<dim3(N_ / 64, H_, B_), 256, smem>>>(pq, pk, pv, adj, pa);

    gemm_bias_kernel<<<ggrid, 256>>>(pa, Wo, bo, out, M, D_, D_);
}

// round 2
// speedup vs baseline: 1.0002x; 1.0002x over previous
#include <cuda_runtime.h>

// Problem constants
#define B_  4
#define N_  2048
#define D_  512
#define H_  8
#define HD_ 64

// Scratch (allocation-free rule: __device__ globals)
static __device__ float g_q [B_ * N_ * D_];
static __device__ float g_k [B_ * N_ * D_];
static __device__ float g_v [B_ * N_ * D_];
static __device__ float g_ao[B_ * N_ * D_];

// ---------------------------------------------------------------------------
// Tiled SGEMM with bias: C[M,N] = A[M,K] @ W[K,N] + bias[N]
// BM=BN=128, BK=16, 256 threads, 8x8 per thread.
// ---------------------------------------------------------------------------
__global__ __launch_bounds__(256) void gemm_bias_kernel(
    const float* __restrict__ A, const float* __restrict__ W,
    const float* __restrict__ bias, float* __restrict__ C,
    int M, int N, int K)
{
    __shared__ float As[16][132];   // transposed A tile, padded
    __shared__ float Bs[16][128];

    const int tid = threadIdx.x;
    const int block_row = blockIdx.y * 128;
    const int block_col = blockIdx.x * 128;
    const int tr = tid / 16;        // 0..15
    const int tc = tid % 16;        // 0..15

    // A loader: 128 rows x 16 cols, float4, 2 passes of 64 rows
    const int arow = tid / 4;            // 0..63
    const int acol = (tid % 4) * 4;      // 0,4,8,12
    // B loader: 16 rows x 128 cols, float4, 2 passes of 8 rows
    const int brow = tid / 32;           // 0..7
    const int bcol = (tid % 32) * 4;

    float acc[8][8];
    #pragma unroll
    for (int i = 0; i < 8; i++)
        #pragma unroll
        for (int j = 0; j < 8; j++) acc[i][j] = 0.f;

    for (int k0 = 0; k0 < K; k0 += 16) {
        #pragma unroll
        for (int p = 0; p < 2; p++) {
            int r = arow + p * 64;
            float4 av = *(const float4*)(A + (size_t)(block_row + r) * K + k0 + acol);
            As[acol + 0][r] = av.x;
            As[acol + 1][r] = av.y;
            As[acol + 2][r] = av.z;
            As[acol + 3][r] = av.w;
        }
        #pragma unroll
        for (int p = 0; p < 2; p++) {
            int r = brow + p * 8;
            *(float4*)&Bs[r][bcol] =
                *(const float4*)(W + (size_t)(k0 + r) * N + block_col + bcol);
        }
        __syncthreads();

        #pragma unroll
        for (int kk = 0; kk < 16; kk++) {
            float4 a0 = *(const float4*)&As[kk][tr * 8];
            float4 a1 = *(const float4*)&As[kk][tr * 8 + 4];
            float4 b0 = *(const float4*)&Bs[kk][tc * 8];
            float4 b1 = *(const float4*)&Bs[kk][tc * 8 + 4];
            float ra[8] = {a0.x, a0.y, a0.z, a0.w, a1.x, a1.y, a1.z, a1.w};
            float rb[8] = {b0.x, b0.y, b0.z, b0.w, b1.x, b1.y, b1.z, b1.w};
            #pragma unroll
            for (int i = 0; i < 8; i++)
                #pragma unroll
                for (int j = 0; j < 8; j++)
                    acc[i][j] += ra[i] * rb[j];
        }
        __syncthreads();
    }

    #pragma unroll
    for (int i = 0; i < 8; i++) {
        int r = block_row + tr * 8 + i;
        #pragma unroll
        for (int j = 0; j < 8; j += 4) {
            int c = block_col + tc * 8 + j;
            float4 bv = *(const float4*)(bias + c);
            float4 o;
            o.x = acc[i][j + 0] + bv.x;
            o.y = acc[i][j + 1] + bv.y;
            o.z = acc[i][j + 2] + bv.z;
            o.w = acc[i][j + 3] + bv.w;
            *(float4*)(C + (size_t)r * N + c) = o;
        }
    }
}

// ---------------------------------------------------------------------------
// Fused masked flash attention per (b, h, q-tile of 64).
// 256 threads as 16x16; each thread owns a 4x4 micro-tile of S/O.
// Online softmax; mask = (1 - adj) * (-1e9); scale = 1/sqrt(64) = 0.125.
// ---------------------------------------------------------------------------
#define QT_PITCH 68
#define PS_PITCH 68

__global__ __launch_bounds__(256) void attn_kernel(
    const float* __restrict__ q, const float* __restrict__ k,
    const float* __restrict__ v, const float* __restrict__ adj,
    float* __restrict__ o)
{
    extern __shared__ float sm[];
    float* QsT  = sm;                          // [64][68] (d-major)
    float* KsT  = QsT + 64 * QT_PITCH;         // [64][68] (d-major)
    float* Vs   = KsT + 64 * QT_PITCH;         // [64][64] (key-major)
    float* Ps   = Vs  + 64 * 64;               // [64][68]
    float* Adjs = Ps  + 64 * PS_PITCH;         // [64][64]

    const int tid = threadIdx.x;
    const int ty = tid / 16;                   // row group 0..15
    const int tx = tid % 16;                   // col group 0..15
    const int q0 = blockIdx.x * 64;
    const int h  = blockIdx.y;
    const int b  = blockIdx.z;

    const float* qbase = q + (size_t)b * N_ * D_ + h * HD_;
    const float* kbase = k + (size_t)b * N_ * D_ + h * HD_;
    const float* vbase = v + (size_t)b * N_ * D_ + h * HD_;

    // Load Q tile transposed (QsT[d][row])
    for (int i = tid; i < 64 * 16; i += 256) {
        int r  = i / 16;
        int c4 = (i % 16) * 4;
        float4 val = *(const float4*)(qbase + (size_t)(q0 + r) * D_ + c4);
        QsT[(c4 + 0) * QT_PITCH + r] = val.x;
        QsT[(c4 + 1) * QT_PITCH + r] = val.y;
        QsT[(c4 + 2) * QT_PITCH + r] = val.z;
        QsT[(c4 + 3) * QT_PITCH + r] = val.w;
    }

    float Ot[4][4];
    float m_i[4], l_i[4];
    #pragma unroll
    for (int r = 0; r < 4; r++) {
        m_i[r] = -1e30f;
        l_i[r] = 0.f;
        #pragma unroll
        for (int c = 0; c < 4; c++) Ot[r][c] = 0.f;
    }

    for (int k0 = 0; k0 < N_; k0 += 64) {
        __syncthreads();   // previous PV finished reading Vs/Ps
        // Load K tile (transposed), V tile, adj tile
        for (int i = tid; i < 64 * 16; i += 256) {
            int r  = i / 16;
            int c4 = (i % 16) * 4;
            float4 kv = *(const float4*)(kbase + (size_t)(k0 + r) * D_ + c4);
            KsT[(c4 + 0) * QT_PITCH + r] = kv.x;
            KsT[(c4 + 1) * QT_PITCH + r] = kv.y;
            KsT[(c4 + 2) * QT_PITCH + r] = kv.z;
            KsT[(c4 + 3) * QT_PITCH + r] = kv.w;
            *(float4*)&Vs[r * 64 + c4] =
                *(const float4*)(vbase + (size_t)(k0 + r) * D_ + c4);
            *(float4*)&Adjs[r * 64 + c4] =
                *(const float4*)(adj + (size_t)(q0 + r) * N_ + k0 + c4);
        }
        __syncthreads();

        // S = Q @ K^T (4x4 per thread)
        float s[4][4];
        #pragma unroll
        for (int r = 0; r < 4; r++)
            #pragma unroll
            for (int c = 0; c < 4; c++) s[r][c] = 0.f;

        #pragma unroll 8
        for (int d = 0; d < 64; d++) {
            float4 rq4 = *(const float4*)&QsT[d * QT_PITCH + ty * 4];
            float4 rk4 = *(const float4*)&KsT[d * QT_PITCH + tx * 4];
            float rq[4] = {rq4.x, rq4.y, rq4.z, rq4.w};
            float rk[4] = {rk4.x, rk4.y, rk4.z, rk4.w};
            #pragma unroll
            for (int r = 0; r < 4; r++)
                #pragma unroll
                for (int c = 0; c < 4; c++)
                    s[r][c] += rq[r] * rk[c];
        }

        // Scale + mask, then online softmax per row
        #pragma unroll
        for (int r = 0; r < 4; r++) {
            float4 a4 = *(const float4*)&Adjs[(ty * 4 + r) * 64 + tx * 4];
            float am[4] = {a4.x, a4.y, a4.z, a4.w};
            #pragma unroll
            for (int c = 0; c < 4; c++)
                s[r][c] = s[r][c] * 0.125f + (1.0f - am[c]) * (-1e9f);

            float mx = s[r][0];
            #pragma unroll
            for (int c = 1; c < 4; c++) mx = fmaxf(mx, s[r][c]);
            #pragma unroll
            for (int off = 1; off < 16; off <<= 1)
                mx = fmaxf(mx, __shfl_xor_sync(0xffffffffu, mx, off));

            float m_new = fmaxf(m_i[r], mx);
            float alpha = __expf(m_i[r] - m_new);

            float ps[4];
            float rowsum = 0.f;
            #pragma unroll
            for (int c = 0; c < 4; c++) {
                ps[c] = __expf(s[r][c] - m_new);
                rowsum += ps[c];
            }
            #pragma unroll
            for (int off = 1; off < 16; off <<= 1)
                rowsum += __shfl_xor_sync(0xffffffffu, rowsum, off);

            l_i[r] = l_i[r] * alpha + rowsum;
            m_i[r] = m_new;
            #pragma unroll
            for (int c = 0; c < 4; c++) Ot[r][c] *= alpha;

            *(float4*)&Ps[(ty * 4 + r) * PS_PITCH + tx * 4] =
                make_float4(ps[0], ps[1], ps[2], ps[3]);
        }
        __syncthreads();

        // O += P @ V
        #pragma unroll 4
        for (int kk = 0; kk < 64; kk += 4) {
            float rv[4][4];
            #pragma unroll
            for (int u = 0; u < 4; u++)
                *(float4*)rv[u] = *(const float4*)&Vs[(kk + u) * 64 + tx * 4];
            #pragma unroll
            for (int r = 0; r < 4; r++) {
                float4 p4 = *(const float4*)&Ps[(ty * 4 + r) * PS_PITCH + kk];
                float pr[4] = {p4.x, p4.y, p4.z, p4.w};
                #pragma unroll
                for (int u = 0; u < 4; u++)
                    #pragma unroll
                    for (int c = 0; c < 4; c++)
                        Ot[r][c] += pr[u] * rv[u][c];
            }
        }
    }

    // Finalize: divide by l and store to attention-out scratch [b, q, h, hd]
    float* obase = o + (size_t)b * N_ * D_ + h * HD_;
    #pragma unroll
    for (int r = 0; r < 4; r++) {
        float inv = 1.0f / l_i[r];
        int row = q0 + ty * 4 + r;
        float4 ov = make_float4(Ot[r][0] * inv, Ot[r][1] * inv,
                                Ot[r][2] * inv, Ot[r][3] * inv);
        *(float4*)(obase + (size_t)row * D_ + tx * 4) = ov;
    }
}

// ---------------------------------------------------------------------------
extern "C" void kernel_launch(void* const* d_in, const int* in_sizes, int n_in,
                              void* d_out, int out_size)
{
    const float* x   = (const float*)d_in[0];
    const float* adj = (const float*)d_in[1];
    const float* Wq  = (const float*)d_in[2];
    const float* bq  = (const float*)d_in[3];
    const float* Wk  = (const float*)d_in[4];
    const float* bk  = (const float*)d_in[5];
    const float* Wv  = (const float*)d_in[6];
    const float* bv  = (const float*)d_in[7];
    const float* Wo  = (const float*)d_in[8];
    const float* bo  = (const float*)d_in[9];
    float* out = (float*)d_out;

    float *pq, *pk, *pv, *pa;
    cudaGetSymbolAddress((void**)&pq, g_q);
    cudaGetSymbolAddress((void**)&pk, g_k);
    cudaGetSymbolAddress((void**)&pv, g_v);
    cudaGetSymbolAddress((void**)&pa, g_ao);

    const int M = B_ * N_;           // 8192
    dim3 ggrid(D_ / 128, M / 128);   // (4, 64)

    gemm_bias_kernel<<<ggrid, 256>>>(x, Wq, bq, pq, M, D_, D_);
    gemm_bias_kernel<<<ggrid, 256>>>(x, Wk, bk, pk, M, D_, D_);
    gemm_bias_kernel<<<ggrid, 256>>>(x, Wv, bv, pv, M, D_, D_);

    size_t smem = (size_t)(64 * QT_PITCH * 2 + 64 * 64 * 2 + 64 * PS_PITCH)
                  * sizeof(float);   // ~85 KB
    cudaFuncSetAttribute(attn_kernel,
                         cudaFuncAttributeMaxDynamicSharedMemorySize,
                         (int)smem);
    attn_kernel<<<dim3(N_ / 64, H_, B_), 256, smem>>>(pq, pk, pv, adj, pa);

    gemm_bias_kernel<<<ggrid, 256>>>(pa, Wo, bo, out, M, D_, D_);
}

// round 3
// speedup vs baseline: 2.3274x; 2.3269x over previous
#include <cuda_runtime.h>

// Problem constants
#define B_  4
#define N_  2048
#define D_  512
#define H_  8
#define HD_ 64

// Scratch (allocation-free rule: __device__ globals)
static __device__ float g_q [B_ * N_ * D_];
static __device__ float g_k [B_ * N_ * D_];
static __device__ float g_v [B_ * N_ * D_];
static __device__ float g_ao[B_ * N_ * D_];

// ---------------------------------------------------------------------------
// tf32 helpers
// ---------------------------------------------------------------------------
__device__ __forceinline__ unsigned f2tf32(float x) {
    unsigned r;
    asm("cvt.rna.tf32.f32 %0, %1;" : "=r"(r) : "f"(x));
    return r;
}

// D += A*B, m16n8k8, tf32 inputs, fp32 accum.
// A frag: a0=(r,c) a1=(r+8,c) a2=(r,c+4) a3=(r+8,c+4), r=lane/4, c=lane%4
// B frag: b0=(k=lane%4, n=lane/4) b1=(k=lane%4+4, n=lane/4)
// C frag: c0=(r, 2c) c1=(r, 2c+1) c2=(r+8, 2c) c3=(r+8, 2c+1)
__device__ __forceinline__ void mma_tf32(float c[4],
    unsigned a0, unsigned a1, unsigned a2, unsigned a3,
    unsigned b0, unsigned b1)
{
    asm volatile(
        "mma.sync.aligned.m16n8k8.row.col.f32.tf32.tf32.f32 "
        "{%0,%1,%2,%3}, {%4,%5,%6,%7}, {%8,%9}, {%0,%1,%2,%3};\n"
        : "+f"(c[0]), "+f"(c[1]), "+f"(c[2]), "+f"(c[3])
        : "r"(a0), "r"(a1), "r"(a2), "r"(a3), "r"(b0), "r"(b1));
}

// ---------------------------------------------------------------------------
// TF32 GEMM with bias: C[M,N] = A[M,K] @ W[K,N] + bias
// BM=128, BN=64, BK=32. 256 threads = 8 warps in 4x2, warp tile 32x32.
// ---------------------------------------------------------------------------
#define GA_PITCH 36   // %32 == 4  -> conflict-free A-fragment gathers
#define GB_PITCH 72   // %32 == 8  -> conflict-free B-fragment gathers

__global__ __launch_bounds__(256) void gemm_tf32(
    const float* __restrict__ A, const float* __restrict__ W,
    const float* __restrict__ bias, float* __restrict__ C,
    int M, int N, int K)
{
    __shared__ unsigned As[128 * GA_PITCH];
    __shared__ unsigned Bs[32 * GB_PITCH];

    const int tid  = threadIdx.x;
    const int warp = tid >> 5;
    const int lane = tid & 31;
    const int wm = warp >> 1;        // 0..3
    const int wn = warp & 1;         // 0..1
    const int gid = lane >> 2;       // lane/4
    const int tig = lane & 3;        // lane%4

    const int rowBase = blockIdx.y * 128;
    const int colBase = blockIdx.x * 64;

    const int aRow = tid >> 3;           // 0..31
    const int aCol = (tid & 7) * 4;
    const int bRow = tid >> 4;           // 0..15
    const int bCol = (tid & 15) * 4;

    float acc[2][4][4];
    #pragma unroll
    for (int mt = 0; mt < 2; mt++)
        #pragma unroll
        for (int nt = 0; nt < 4; nt++)
            #pragma unroll
            for (int i = 0; i < 4; i++) acc[mt][nt][i] = 0.f;

    for (int k0 = 0; k0 < K; k0 += 32) {
        __syncthreads();
        #pragma unroll
        for (int p = 0; p < 4; p++) {
            int r = aRow + p * 32;
            float4 v = *(const float4*)(A + (size_t)(rowBase + r) * K + k0 + aCol);
            As[r * GA_PITCH + aCol + 0] = f2tf32(v.x);
            As[r * GA_PITCH + aCol + 1] = f2tf32(v.y);
            As[r * GA_PITCH + aCol + 2] = f2tf32(v.z);
            As[r * GA_PITCH + aCol + 3] = f2tf32(v.w);
        }
        #pragma unroll
        for (int p = 0; p < 2; p++) {
            int r = bRow + p * 16;
            float4 v = *(const float4*)(W + (size_t)(k0 + r) * N + colBase + bCol);
            Bs[r * GB_PITCH + bCol + 0] = f2tf32(v.x);
            Bs[r * GB_PITCH + bCol + 1] = f2tf32(v.y);
            Bs[r * GB_PITCH + bCol + 2] = f2tf32(v.z);
            Bs[r * GB_PITCH + bCol + 3] = f2tf32(v.w);
        }
        __syncthreads();

        #pragma unroll
        for (int ks = 0; ks < 4; ks++) {
            const int c = ks * 8 + tig;
            unsigned a[2][4];
            #pragma unroll
            for (int mt = 0; mt < 2; mt++) {
                int r = wm * 32 + mt * 16 + gid;
                a[mt][0] = As[r * GA_PITCH + c];
                a[mt][1] = As[(r + 8) * GA_PITCH + c];
                a[mt][2] = As[r * GA_PITCH + c + 4];
                a[mt][3] = As[(r + 8) * GA_PITCH + c + 4];
            }
            #pragma unroll
            for (int nt = 0; nt < 4; nt++) {
                int n  = wn * 32 + nt * 8 + gid;
                int kk = ks * 8 + tig;
                unsigned b0 = Bs[kk * GB_PITCH + n];
                unsigned b1 = Bs[(kk + 4) * GB_PITCH + n];
                #pragma unroll
                for (int mt = 0; mt < 2; mt++)
                    mma_tf32(acc[mt][nt], a[mt][0], a[mt][1], a[mt][2], a[mt][3], b0, b1);
            }
        }
    }

    #pragma unroll
    for (int mt = 0; mt < 2; mt++) {
        int r0 = rowBase + wm * 32 + mt * 16 + gid;
        #pragma unroll
        for (int nt = 0; nt < 4; nt++) {
            int col = colBase + wn * 32 + nt * 8 + tig * 2;
            float2 bv = *(const float2*)(bias + col);
            float2 o0 = make_float2(acc[mt][nt][0] + bv.x, acc[mt][nt][1] + bv.y);
            float2 o1 = make_float2(acc[mt][nt][2] + bv.x, acc[mt][nt][3] + bv.y);
            *(float2*)(C + (size_t)r0 * N + col)       = o0;
            *(float2*)(C + (size_t)(r0 + 8) * N + col) = o1;
        }
    }
}

// ---------------------------------------------------------------------------
// Fused masked flash attention, tf32 tensor cores.
// q-tile=128, k-tile=64, 256 threads (8 warps: 4 m-strips x 2 col-halves).
// Warp S tile 32x32; online softmax with cross-warp (2-way) combine via smem.
// ---------------------------------------------------------------------------
#define QS_PITCH 68   // %32==4
#define KS_PITCH 68   // %32==4
#define VS_PITCH 72   // %32==8
#define AJ_PITCH 72
#define PS_PITCH2 68

#define QS_OFF   0
#define KS_OFF   (QS_OFF + 128 * QS_PITCH)          // 8704
#define VS_OFF   (KS_OFF + 64 * KS_PITCH)           // 13056
#define AJ_OFF   (VS_OFF + 64 * VS_PITCH)           // 17664
#define PS_OFF   (AJ_OFF + 128 * AJ_PITCH)          // 26880
#define PMAX_OFF (PS_OFF + 128 * PS_PITCH2)         // 35584
#define PSUM_OFF (PMAX_OFF + 256)                   // 35840
#define ATTN_SMEM_FLOATS (PSUM_OFF + 256)           // 36096 -> 144384 B

__global__ __launch_bounds__(256, 1) void attn_tf32_kernel(
    const float* __restrict__ q, const float* __restrict__ k,
    const float* __restrict__ v, const float* __restrict__ adj,
    float* __restrict__ o)
{
    extern __shared__ float sm[];
    unsigned* smu = (unsigned*)sm;

    const int tid  = threadIdx.x;
    const int warp = tid >> 5;
    const int lane = tid & 31;
    const int wm = warp >> 1;     // m-strip 0..3 (32 rows each)
    const int wn = warp & 1;      // col half 0..1 (32 cols each)
    const int gid = lane >> 2;
    const int tig = lane & 3;

    const int q0 = blockIdx.x * 128;
    const int h  = blockIdx.y;
    const int b  = blockIdx.z;

    const float* qbase = q + (size_t)b * N_ * D_ + h * HD_;
    const float* kbase = k + (size_t)b * N_ * D_ + h * HD_;
    const float* vbase = v + (size_t)b * N_ * D_ + h * HD_;

    // Load Q tile (128 x 64), scaled by 1/sqrt(64)=0.125, tf32.
    #pragma unroll
    for (int p = 0; p < 8; p++) {
        int idx = tid + p * 256;          // 0..2047
        int r   = idx >> 4;               // 0..127
        int c4  = (idx & 15) * 4;
        float4 val = *(const float4*)(qbase + (size_t)(q0 + r) * D_ + c4);
        smu[QS_OFF + r * QS_PITCH + c4 + 0] = f2tf32(val.x * 0.125f);
        smu[QS_OFF + r * QS_PITCH + c4 + 1] = f2tf32(val.y * 0.125f);
        smu[QS_OFF + r * QS_PITCH + c4 + 2] = f2tf32(val.z * 0.125f);
        smu[QS_OFF + r * QS_PITCH + c4 + 3] = f2tf32(val.w * 0.125f);
    }

    float O[2][4][4];
    float m_i[2][2], l_i[2][2], alpha[2][2];
    #pragma unroll
    for (int mt = 0; mt < 2; mt++) {
        #pragma unroll
        for (int hf = 0; hf < 2; hf++) { m_i[mt][hf] = -1e30f; l_i[mt][hf] = 0.f; }
        #pragma unroll
        for (int nt = 0; nt < 4; nt++)
            #pragma unroll
            for (int i = 0; i < 4; i++) O[mt][nt][i] = 0.f;
    }

    for (int k0 = 0; k0 < N_; k0 += 64) {
        __syncthreads();   // A: prev PV done reading Vs/Ps; pmax read done

        // Load K tile (64x64, tf32), V tile (64x64, tf32), adj tile (128x64, f32)
        #pragma unroll
        for (int p = 0; p < 4; p++) {
            int idx = tid + p * 256;      // 0..1023
            int r   = idx >> 4;           // 0..63
            int c4  = (idx & 15) * 4;
            float4 kv = *(const float4*)(kbase + (size_t)(k0 + r) * D_ + c4);
            smu[KS_OFF + r * KS_PITCH + c4 + 0] = f2tf32(kv.x);
            smu[KS_OFF + r * KS_PITCH + c4 + 1] = f2tf32(kv.y);
            smu[KS_OFF + r * KS_PITCH + c4 + 2] = f2tf32(kv.z);
            smu[KS_OFF + r * KS_PITCH + c4 + 3] = f2tf32(kv.w);
            float4 vv = *(const float4*)(vbase + (size_t)(k0 + r) * D_ + c4);
            smu[VS_OFF + r * VS_PITCH + c4 + 0] = f2tf32(vv.x);
            smu[VS_OFF + r * VS_PITCH + c4 + 1] = f2tf32(vv.y);
            smu[VS_OFF + r * VS_PITCH + c4 + 2] = f2tf32(vv.z);
            smu[VS_OFF + r * VS_PITCH + c4 + 3] = f2tf32(vv.w);
        }
        #pragma unroll
        for (int p = 0; p < 8; p++) {
            int idx = tid + p * 256;      // 0..2047
            int r   = idx >> 4;           // 0..127
            int c4  = (idx & 15) * 4;
            *(float4*)&sm[AJ_OFF + r * AJ_PITCH + c4] =
                *(const float4*)(adj + (size_t)(q0 + r) * N_ + k0 + c4);
        }
        __syncthreads();

        // ---- S = Q @ K^T (warp: rows wm*32..+32, cols wn*32..+32) ----
        float s[2][4][4];
        #pragma unroll
        for (int mt = 0; mt < 2; mt++)
            #pragma unroll
            for (int nt = 0; nt < 4; nt++)
                #pragma unroll
                for (int i = 0; i < 4; i++) s[mt][nt][i] = 0.f;

        #pragma unroll
        for (int ks = 0; ks < 8; ks++) {
            const int c = ks * 8 + tig;
            unsigned a[2][4];
            #pragma unroll
            for (int mt = 0; mt < 2; mt++) {
                int r = wm * 32 + mt * 16 + gid;
                a[mt][0] = smu[QS_OFF + r * QS_PITCH + c];
                a[mt][1] = smu[QS_OFF + (r + 8) * QS_PITCH + c];
                a[mt][2] = smu[QS_OFF + r * QS_PITCH + c + 4];
                a[mt][3] = smu[QS_OFF + (r + 8) * QS_PITCH + c + 4];
            }
            #pragma unroll
            for (int nt = 0; nt < 4; nt++) {
                int n = wn * 32 + nt * 8 + gid;
                unsigned b0 = smu[KS_OFF + n * KS_PITCH + c];
                unsigned b1 = smu[KS_OFF + n * KS_PITCH + c + 4];
                #pragma unroll
                for (int mt = 0; mt < 2; mt++)
                    mma_tf32(s[mt][nt], a[mt][0], a[mt][1], a[mt][2], a[mt][3], b0, b1);
            }
        }

        // ---- mask + partial row max ----
        float rmax[2][2];
        #pragma unroll
        for (int mt = 0; mt < 2; mt++) {
            #pragma unroll
            for (int hf = 0; hf < 2; hf++) {
                int row = wm * 32 + mt * 16 + hf * 8 + gid;
                float mx = -1e30f;
                #pragma unroll
                for (int nt = 0; nt < 4; nt++) {
                    int col = wn * 32 + nt * 8 + tig * 2;
                    float2 a2 = *(const float2*)&sm[AJ_OFF + row * AJ_PITCH + col];
                    float v0 = s[mt][nt][hf * 2 + 0] + (1.0f - a2.x) * (-1e9f);
                    float v1 = s[mt][nt][hf * 2 + 1] + (1.0f - a2.y) * (-1e9f);
                    s[mt][nt][hf * 2 + 0] = v0;
                    s[mt][nt][hf * 2 + 1] = v1;
                    mx = fmaxf(mx, fmaxf(v0, v1));
                }
                mx = fmaxf(mx, __shfl_xor_sync(0xffffffffu, mx, 1));
                mx = fmaxf(mx, __shfl_xor_sync(0xffffffffu, mx, 2));
                rmax[mt][hf] = mx;
                if (tig == 0) sm[PMAX_OFF + row * 2 + wn] = mx;
            }
        }
        __syncthreads();   // B

        // ---- combine max, exp, partial sums, write P, rescale O ----
        #pragma unroll
        for (int mt = 0; mt < 2; mt++) {
            #pragma unroll
            for (int hf = 0; hf < 2; hf++) {
                int row = wm * 32 + mt * 16 + hf * 8 + gid;
                float mtile = fmaxf(sm[PMAX_OFF + row * 2 + 0],
                                    sm[PMAX_OFF + row * 2 + 1]);
                float mnew = fmaxf(m_i[mt][hf], mtile);
                float al = __expf(m_i[mt][hf] - mnew);
                alpha[mt][hf] = al;
                m_i[mt][hf] = mnew;
                float rsum = 0.f;
                #pragma unroll
                for (int nt = 0; nt < 4; nt++) {
                    float p0 = __expf(s[mt][nt][hf * 2 + 0] - mnew);
                    float p1 = __expf(s[mt][nt][hf * 2 + 1] - mnew);
                    rsum += p0 + p1;
                    int col = wn * 32 + nt * 8 + tig * 2;
                    uint2 pw = make_uint2(f2tf32(p0), f2tf32(p1));
                    *(uint2*)&smu[PS_OFF + row * PS_PITCH2 + col] = pw;
                    O[mt][nt][hf * 2 + 0] *= al;
                    O[mt][nt][hf * 2 + 1] *= al;
                }
                rsum += __shfl_xor_sync(0xffffffffu, rsum, 1);
                rsum += __shfl_xor_sync(0xffffffffu, rsum, 2);
                if (tig == 0) sm[PSUM_OFF + row * 2 + wn] = rsum;
            }
        }
        __syncthreads();   // C: P + psum complete

        #pragma unroll
        for (int mt = 0; mt < 2; mt++)
            #pragma unroll
            for (int hf = 0; hf < 2; hf++) {
                int row = wm * 32 + mt * 16 + hf * 8 + gid;
                l_i[mt][hf] = l_i[mt][hf] * alpha[mt][hf]
                            + sm[PSUM_OFF + row * 2 + 0]
                            + sm[PSUM_OFF + row * 2 + 1];
            }

        // ---- O += P @ V (warp: rows wm*32..+32, d-cols wn*32..+32) ----
        #pragma unroll
        for (int ks = 0; ks < 8; ks++) {
            const int c = ks * 8 + tig;
            unsigned a[2][4];
            #pragma unroll
            for (int mt = 0; mt < 2; mt++) {
                int r = wm * 32 + mt * 16 + gid;
                a[mt][0] = smu[PS_OFF + r * PS_PITCH2 + c];
                a[mt][1] = smu[PS_OFF + (r + 8) * PS_PITCH2 + c];
                a[mt][2] = smu[PS_OFF + r * PS_PITCH2 + c + 4];
                a[mt][3] = smu[PS_OFF + (r + 8) * PS_PITCH2 + c + 4];
            }
            #pragma unroll
            for (int nt = 0; nt < 4; nt++) {
                int d = wn * 32 + nt * 8 + gid;
                unsigned b0 = smu[VS_OFF + c * VS_PITCH + d];
                unsigned b1 = smu[VS_OFF + (c + 4) * VS_PITCH + d];
                #pragma unroll
                for (int mt = 0; mt < 2; mt++)
                    mma_tf32(O[mt][nt], a[mt][0], a[mt][1], a[mt][2], a[mt][3], b0, b1);
            }
        }
    }

    // Finalize: divide by l, store [b, row, h*64 + col]
    float* obase = o + (size_t)b * N_ * D_ + h * HD_;
    #pragma unroll
    for (int mt = 0; mt < 2; mt++) {
        #pragma unroll
        for (int hf = 0; hf < 2; hf++) {
            float inv = 1.0f / l_i[mt][hf];
            int grow = q0 + wm * 32 + mt * 16 + hf * 8 + gid;
            #pragma unroll
            for (int nt = 0; nt < 4; nt++) {
                int col = wn * 32 + nt * 8 + tig * 2;
                float2 ov = make_float2(O[mt][nt][hf * 2 + 0] * inv,
                                        O[mt][nt][hf * 2 + 1] * inv);
                *(float2*)(obase + (size_t)grow * D_ + col) = ov;
            }
        }
    }
}

// ---------------------------------------------------------------------------
extern "C" void kernel_launch(void* const* d_in, const int* in_sizes, int n_in,
                              void* d_out, int out_size)
{
    const float* x   = (const float*)d_in[0];
    const float* adj = (const float*)d_in[1];
    const float* Wq  = (const float*)d_in[2];
    const float* bq  = (const float*)d_in[3];
    const float* Wk  = (const float*)d_in[4];
    const float* bk  = (const float*)d_in[5];
    const float* Wv  = (const float*)d_in[6];
    const float* bv  = (const float*)d_in[7];
    const float* Wo  = (const float*)d_in[8];
    const float* bo  = (const float*)d_in[9];
    float* out = (float*)d_out;

    float *pq, *pk, *pv, *pa;
    cudaGetSymbolAddress((void**)&pq, g_q);
    cudaGetSymbolAddress((void**)&pk, g_k);
    cudaGetSymbolAddress((void**)&pv, g_v);
    cudaGetSymbolAddress((void**)&pa, g_ao);

    const int M = B_ * N_;               // 8192
    dim3 ggrid(D_ / 64, M / 128);        // (8, 64)

    gemm_tf32<<<ggrid, 256>>>(x, Wq, bq, pq, M, D_, D_);
    gemm_tf32<<<ggrid, 256>>>(x, Wk, bk, pk, M, D_, D_);
    gemm_tf32<<<ggrid, 256>>>(x, Wv, bv, pv, M, D_, D_);

    const int smem = ATTN_SMEM_FLOATS * 4;   // 144384
    cudaFuncSetAttribute(attn_tf32_kernel,
                         cudaFuncAttributeMaxDynamicSharedMemorySize, smem);
    attn_tf32_kernel<<<dim3(N_ / 128, H_, B_), 256, smem>>>(pq, pk, pv, adj, pa);

    gemm_tf32<<<ggrid, 256>>>(pa, Wo, bo, out, M, D_, D_);
}

// round 4
// speedup vs baseline: 2.3394x; 1.0052x over previous
#include <cuda_runtime.h>

// Problem constants
#define B_  4
#define N_  2048
#define D_  512
#define H_  8
#define HD_ 64

// Scratch (allocation-free rule: __device__ globals)
static __device__ float g_q [B_ * N_ * D_];
static __device__ float g_k [B_ * N_ * D_];
static __device__ float g_v [B_ * N_ * D_];
static __device__ float g_ao[B_ * N_ * D_];

// ---------------------------------------------------------------------------
// tf32 helpers
// ---------------------------------------------------------------------------
__device__ __forceinline__ unsigned f2tf32(float x) {
    unsigned r;
    asm("cvt.rna.tf32.f32 %0, %1;" : "=r"(r) : "f"(x));
    return r;
}

// D += A*B, m16n8k8, tf32 inputs, fp32 accum.
// A frag: a0=(r,c) a1=(r+8,c) a2=(r,c+4) a3=(r+8,c+4), r=lane/4, c=lane%4
// B frag: b0=(k=lane%4, n=lane/4) b1=(k=lane%4+4, n=lane/4)
// C frag: c0=(r, 2c) c1=(r, 2c+1) c2=(r+8, 2c) c3=(r+8, 2c+1)
__device__ __forceinline__ void mma_tf32(float c[4],
    unsigned a0, unsigned a1, unsigned a2, unsigned a3,
    unsigned b0, unsigned b1)
{
    asm volatile(
        "mma.sync.aligned.m16n8k8.row.col.f32.tf32.tf32.f32 "
        "{%0,%1,%2,%3}, {%4,%5,%6,%7}, {%8,%9}, {%0,%1,%2,%3};\n"
        : "+f"(c[0]), "+f"(c[1]), "+f"(c[2]), "+f"(c[3])
        : "r"(a0), "r"(a1), "r"(a2), "r"(a3), "r"(b0), "r"(b1));
}

// ---------------------------------------------------------------------------
// TF32 GEMM with bias: C[M,N] = A[M,K] @ W[K,N] + bias
// BM=128, BN=64, BK=32. 256 threads = 8 warps in 4x2, warp tile 32x32.
// ---------------------------------------------------------------------------
#define GA_PITCH 36   // %32 == 4  -> conflict-free A-fragment gathers
#define GB_PITCH 72   // %32 == 8  -> conflict-free B-fragment gathers

__global__ __launch_bounds__(256) void gemm_tf32(
    const float* __restrict__ A, const float* __restrict__ W,
    const float* __restrict__ bias, float* __restrict__ C,
    int M, int N, int K)
{
    __shared__ unsigned As[128 * GA_PITCH];
    __shared__ unsigned Bs[32 * GB_PITCH];

    const int tid  = threadIdx.x;
    const int warp = tid >> 5;
    const int lane = tid & 31;
    const int wm = warp >> 1;        // 0..3
    const int wn = warp & 1;         // 0..1
    const int gid = lane >> 2;       // lane/4
    const int tig = lane & 3;        // lane%4

    const int rowBase = blockIdx.y * 128;
    const int colBase = blockIdx.x * 64;

    const int aRow = tid >> 3;           // 0..31
    const int aCol = (tid & 7) * 4;
    const int bRow = tid >> 4;           // 0..15
    const int bCol = (tid & 15) * 4;

    float acc[2][4][4];
    #pragma unroll
    for (int mt = 0; mt < 2; mt++)
        #pragma unroll
        for (int nt = 0; nt < 4; nt++)
            #pragma unroll
            for (int i = 0; i < 4; i++) acc[mt][nt][i] = 0.f;

    for (int k0 = 0; k0 < K; k0 += 32) {
        __syncthreads();
        #pragma unroll
        for (int p = 0; p < 4; p++) {
            int r = aRow + p * 32;
            float4 v = *(const float4*)(A + (size_t)(rowBase + r) * K + k0 + aCol);
            As[r * GA_PITCH + aCol + 0] = f2tf32(v.x);
            As[r * GA_PITCH + aCol + 1] = f2tf32(v.y);
            As[r * GA_PITCH + aCol + 2] = f2tf32(v.z);
            As[r * GA_PITCH + aCol + 3] = f2tf32(v.w);
        }
        #pragma unroll
        for (int p = 0; p < 2; p++) {
            int r = bRow + p * 16;
            float4 v = *(const float4*)(W + (size_t)(k0 + r) * N + colBase + bCol);
            Bs[r * GB_PITCH + bCol + 0] = f2tf32(v.x);
            Bs[r * GB_PITCH + bCol + 1] = f2tf32(v.y);
            Bs[r * GB_PITCH + bCol + 2] = f2tf32(v.z);
            Bs[r * GB_PITCH + bCol + 3] = f2tf32(v.w);
        }
        __syncthreads();

        #pragma unroll
        for (int ks = 0; ks < 4; ks++) {
            const int c = ks * 8 + tig;
            unsigned a[2][4];
            #pragma unroll
            for (int mt = 0; mt < 2; mt++) {
                int r = wm * 32 + mt * 16 + gid;
                a[mt][0] = As[r * GA_PITCH + c];
                a[mt][1] = As[(r + 8) * GA_PITCH + c];
                a[mt][2] = As[r * GA_PITCH + c + 4];
                a[mt][3] = As[(r + 8) * GA_PITCH + c + 4];
            }
            #pragma unroll
            for (int nt = 0; nt < 4; nt++) {
                int n  = wn * 32 + nt * 8 + gid;
                int kk = ks * 8 + tig;
                unsigned b0 = Bs[kk * GB_PITCH + n];
                unsigned b1 = Bs[(kk + 4) * GB_PITCH + n];
                #pragma unroll
                for (int mt = 0; mt < 2; mt++)
                    mma_tf32(acc[mt][nt], a[mt][0], a[mt][1], a[mt][2], a[mt][3], b0, b1);
            }
        }
    }

    #pragma unroll
    for (int mt = 0; mt < 2; mt++) {
        int r0 = rowBase + wm * 32 + mt * 16 + gid;
        #pragma unroll
        for (int nt = 0; nt < 4; nt++) {
            int col = colBase + wn * 32 + nt * 8 + tig * 2;
            float2 bv = *(const float2*)(bias + col);
            float2 o0 = make_float2(acc[mt][nt][0] + bv.x, acc[mt][nt][1] + bv.y);
            float2 o1 = make_float2(acc[mt][nt][2] + bv.x, acc[mt][nt][3] + bv.y);
            *(float2*)(C + (size_t)r0 * N + col)       = o0;
            *(float2*)(C + (size_t)(r0 + 8) * N + col) = o1;
        }
    }
}

// ---------------------------------------------------------------------------
// Fused masked flash attention, tf32 tensor cores.
// q-tile=128, k-tile=64, 256 threads (8 warps: 4 m-strips x 2 col-halves).
// Warp S tile 32x32; online softmax with cross-warp (2-way) combine via smem.
// ---------------------------------------------------------------------------
#define QS_PITCH 68   // %32==4
#define KS_PITCH 68   // %32==4
#define VS_PITCH 72   // %32==8
#define AJ_PITCH 72
#define PS_PITCH2 68

#define QS_OFF   0
#define KS_OFF   (QS_OFF + 128 * QS_PITCH)          // 8704
#define VS_OFF   (KS_OFF + 64 * KS_PITCH)           // 13056
#define AJ_OFF   (VS_OFF + 64 * VS_PITCH)           // 17664
#define PS_OFF   (AJ_OFF + 128 * AJ_PITCH)          // 26880
#define PMAX_OFF (PS_OFF + 128 * PS_PITCH2)         // 35584
#define PSUM_OFF (PMAX_OFF + 256)                   // 35840
#define ATTN_SMEM_FLOATS (PSUM_OFF + 256)           // 36096 -> 144384 B

__global__ __launch_bounds__(256, 1) void attn_tf32_kernel(
    const float* __restrict__ q, const float* __restrict__ k,
    const float* __restrict__ v, const float* __restrict__ adj,
    float* __restrict__ o)
{
    extern __shared__ float sm[];
    unsigned* smu = (unsigned*)sm;

    const int tid  = threadIdx.x;
    const int warp = tid >> 5;
    const int lane = tid & 31;
    const int wm = warp >> 1;     // m-strip 0..3 (32 rows each)
    const int wn = warp & 1;      // col half 0..1 (32 cols each)
    const int gid = lane >> 2;
    const int tig = lane & 3;

    const int q0 = blockIdx.x * 128;
    const int h  = blockIdx.y;
    const int b  = blockIdx.z;

    const float* qbase = q + (size_t)b * N_ * D_ + h * HD_;
    const float* kbase = k + (size_t)b * N_ * D_ + h * HD_;
    const float* vbase = v + (size_t)b * N_ * D_ + h * HD_;

    // Load Q tile (128 x 64), scaled by 1/sqrt(64)=0.125, tf32.
    #pragma unroll
    for (int p = 0; p < 8; p++) {
        int idx = tid + p * 256;          // 0..2047
        int r   = idx >> 4;               // 0..127
        int c4  = (idx & 15) * 4;
        float4 val = *(const float4*)(qbase + (size_t)(q0 + r) * D_ + c4);
        smu[QS_OFF + r * QS_PITCH + c4 + 0] = f2tf32(val.x * 0.125f);
        smu[QS_OFF + r * QS_PITCH + c4 + 1] = f2tf32(val.y * 0.125f);
        smu[QS_OFF + r * QS_PITCH + c4 + 2] = f2tf32(val.z * 0.125f);
        smu[QS_OFF + r * QS_PITCH + c4 + 3] = f2tf32(val.w * 0.125f);
    }

    float O[2][4][4];
    float m_i[2][2], l_i[2][2], alpha[2][2];
    #pragma unroll
    for (int mt = 0; mt < 2; mt++) {
        #pragma unroll
        for (int hf = 0; hf < 2; hf++) { m_i[mt][hf] = -1e30f; l_i[mt][hf] = 0.f; }
        #pragma unroll
        for (int nt = 0; nt < 4; nt++)
            #pragma unroll
            for (int i = 0; i < 4; i++) O[mt][nt][i] = 0.f;
    }

    for (int k0 = 0; k0 < N_; k0 += 64) {
        __syncthreads();   // A: prev PV done reading Vs/Ps; pmax read done

        // Load K tile (64x64, tf32), V tile (64x64, tf32), adj tile (128x64, f32)
        #pragma unroll
        for (int p = 0; p < 4; p++) {
            int idx = tid + p * 256;      // 0..1023
            int r   = idx >> 4;           // 0..63
            int c4  = (idx & 15) * 4;
            float4 kv = *(const float4*)(kbase + (size_t)(k0 + r) * D_ + c4);
            smu[KS_OFF + r * KS_PITCH + c4 + 0] = f2tf32(kv.x);
            smu[KS_OFF + r * KS_PITCH + c4 + 1] = f2tf32(kv.y);
            smu[KS_OFF + r * KS_PITCH + c4 + 2] = f2tf32(kv.z);
            smu[KS_OFF + r * KS_PITCH + c4 + 3] = f2tf32(kv.w);
            float4 vv = *(const float4*)(vbase + (size_t)(k0 + r) * D_ + c4);
            smu[VS_OFF + r * VS_PITCH + c4 + 0] = f2tf32(vv.x);
            smu[VS_OFF + r * VS_PITCH + c4 + 1] = f2tf32(vv.y);
            smu[VS_OFF + r * VS_PITCH + c4 + 2] = f2tf32(vv.z);
            smu[VS_OFF + r * VS_PITCH + c4 + 3] = f2tf32(vv.w);
        }
        #pragma unroll
        for (int p = 0; p < 8; p++) {
            int idx = tid + p * 256;      // 0..2047
            int r   = idx >> 4;           // 0..127
            int c4  = (idx & 15) * 4;
            *(float4*)&sm[AJ_OFF + r * AJ_PITCH + c4] =
                *(const float4*)(adj + (size_t)(q0 + r) * N_ + k0 + c4);
        }
        __syncthreads();

        // ---- S = Q @ K^T (warp: rows wm*32..+32, cols wn*32..+32) ----
        float s[2][4][4];
        #pragma unroll
        for (int mt = 0; mt < 2; mt++)
            #pragma unroll
            for (int nt = 0; nt < 4; nt++)
                #pragma unroll
                for (int i = 0; i < 4; i++) s[mt][nt][i] = 0.f;

        #pragma unroll
        for (int ks = 0; ks < 8; ks++) {
            const int c = ks * 8 + tig;
            unsigned a[2][4];
            #pragma unroll
            for (int mt = 0; mt < 2; mt++) {
                int r = wm * 32 + mt * 16 + gid;
                a[mt][0] = smu[QS_OFF + r * QS_PITCH + c];
                a[mt][1] = smu[QS_OFF + (r + 8) * QS_PITCH + c];
                a[mt][2] = smu[QS_OFF + r * QS_PITCH + c + 4];
                a[mt][3] = smu[QS_OFF + (r + 8) * QS_PITCH + c + 4];
            }
            #pragma unroll
            for (int nt = 0; nt < 4; nt++) {
                int n = wn * 32 + nt * 8 + gid;
                unsigned b0 = smu[KS_OFF + n * KS_PITCH + c];
                unsigned b1 = smu[KS_OFF + n * KS_PITCH + c + 4];
                #pragma unroll
                for (int mt = 0; mt < 2; mt++)
                    mma_tf32(s[mt][nt], a[mt][0], a[mt][1], a[mt][2], a[mt][3], b0, b1);
            }
        }

        // ---- mask + partial row max ----
        float rmax[2][2];
        #pragma unroll
        for (int mt = 0; mt < 2; mt++) {
            #pragma unroll
            for (int hf = 0; hf < 2; hf++) {
                int row = wm * 32 + mt * 16 + hf * 8 + gid;
                float mx = -1e30f;
                #pragma unroll
                for (int nt = 0; nt < 4; nt++) {
                    int col = wn * 32 + nt * 8 + tig * 2;
                    float2 a2 = *(const float2*)&sm[AJ_OFF + row * AJ_PITCH + col];
                    float v0 = s[mt][nt][hf * 2 + 0] + (1.0f - a2.x) * (-1e9f);
                    float v1 = s[mt][nt][hf * 2 + 1] + (1.0f - a2.y) * (-1e9f);
                    s[mt][nt][hf * 2 + 0] = v0;
                    s[mt][nt][hf * 2 + 1] = v1;
                    mx = fmaxf(mx, fmaxf(v0, v1));
                }
                mx = fmaxf(mx, __shfl_xor_sync(0xffffffffu, mx, 1));
                mx = fmaxf(mx, __shfl_xor_sync(0xffffffffu, mx, 2));
                rmax[mt][hf] = mx;
                if (tig == 0) sm[PMAX_OFF + row * 2 + wn] = mx;
            }
        }
        __syncthreads();   // B

        // ---- combine max, exp, partial sums, write P, rescale O ----
        #pragma unroll
        for (int mt = 0; mt < 2; mt++) {
            #pragma unroll
            for (int hf = 0; hf < 2; hf++) {
                int row = wm * 32 + mt * 16 + hf * 8 + gid;
                float mtile = fmaxf(sm[PMAX_OFF + row * 2 + 0],
                                    sm[PMAX_OFF + row * 2 + 1]);
                float mnew = fmaxf(m_i[mt][hf], mtile);
                float al = __expf(m_i[mt][hf] - mnew);
                alpha[mt][hf] = al;
                m_i[mt][hf] = mnew;
                float rsum = 0.f;
                #pragma unroll
                for (int nt = 0; nt < 4; nt++) {
                    float p0 = __expf(s[mt][nt][hf * 2 + 0] - mnew);
                    float p1 = __expf(s[mt][nt][hf * 2 + 1] - mnew);
                    rsum += p0 + p1;
                    int col = wn * 32 + nt * 8 + tig * 2;
                    uint2 pw = make_uint2(f2tf32(p0), f2tf32(p1));
                    *(uint2*)&smu[PS_OFF + row * PS_PITCH2 + col] = pw;
                    O[mt][nt][hf * 2 + 0] *= al;
                    O[mt][nt][hf * 2 + 1] *= al;
                }
                rsum += __shfl_xor_sync(0xffffffffu, rsum, 1);
                rsum += __shfl_xor_sync(0xffffffffu, rsum, 2);
                if (tig == 0) sm[PSUM_OFF + row * 2 + wn] = rsum;
            }
        }
        __syncthreads();   // C: P + psum complete

        #pragma unroll
        for (int mt = 0; mt < 2; mt++)
            #pragma unroll
            for (int hf = 0; hf < 2; hf++) {
                int row = wm * 32 + mt * 16 + hf * 8 + gid;
                l_i[mt][hf] = l_i[mt][hf] * alpha[mt][hf]
                            + sm[PSUM_OFF + row * 2 + 0]
                            + sm[PSUM_OFF + row * 2 + 1];
            }

        // ---- O += P @ V (warp: rows wm*32..+32, d-cols wn*32..+32) ----
        #pragma unroll
        for (int ks = 0; ks < 8; ks++) {
            const int c = ks * 8 + tig;
            unsigned a[2][4];
            #pragma unroll
            for (int mt = 0; mt < 2; mt++) {
                int r = wm * 32 + mt * 16 + gid;
                a[mt][0] = smu[PS_OFF + r * PS_PITCH2 + c];
                a[mt][1] = smu[PS_OFF + (r + 8) * PS_PITCH2 + c];
                a[mt][2] = smu[PS_OFF + r * PS_PITCH2 + c + 4];
                a[mt][3] = smu[PS_OFF + (r + 8) * PS_PITCH2 + c + 4];
            }
            #pragma unroll
            for (int nt = 0; nt < 4; nt++) {
                int d = wn * 32 + nt * 8 + gid;
                unsigned b0 = smu[VS_OFF + c * VS_PITCH + d];
                unsigned b1 = smu[VS_OFF + (c + 4) * VS_PITCH + d];
                #pragma unroll
                for (int mt = 0; mt < 2; mt++)
                    mma_tf32(O[mt][nt], a[mt][0], a[mt][1], a[mt][2], a[mt][3], b0, b1);
            }
        }
    }

    // Finalize: divide by l, store [b, row, h*64 + col]
    float* obase = o + (size_t)b * N_ * D_ + h * HD_;
    #pragma unroll
    for (int mt = 0; mt < 2; mt++) {
        #pragma unroll
        for (int hf = 0; hf < 2; hf++) {
            float inv = 1.0f / l_i[mt][hf];
            int grow = q0 + wm * 32 + mt * 16 + hf * 8 + gid;
            #pragma unroll
            for (int nt = 0; nt < 4; nt++) {
                int col = wn * 32 + nt * 8 + tig * 2;
                float2 ov = make_float2(O[mt][nt][hf * 2 + 0] * inv,
                                        O[mt][nt][hf * 2 + 1] * inv);
                *(float2*)(obase + (size_t)grow * D_ + col) = ov;
            }
        }
    }
}

// ---------------------------------------------------------------------------
extern "C" void kernel_launch(void* const* d_in, const int* in_sizes, int n_in,
                              void* d_out, int out_size)
{
    const float* x   = (const float*)d_in[0];
    const float* adj = (const float*)d_in[1];
    const float* Wq  = (const float*)d_in[2];
    const float* bq  = (const float*)d_in[3];
    const float* Wk  = (const float*)d_in[4];
    const float* bk  = (const float*)d_in[5];
    const float* Wv  = (const float*)d_in[6];
    const float* bv  = (const float*)d_in[7];
    const float* Wo  = (const float*)d_in[8];
    const float* bo  = (const float*)d_in[9];
    float* out = (float*)d_out;

    float *pq, *pk, *pv, *pa;
    cudaGetSymbolAddress((void**)&pq, g_q);
    cudaGetSymbolAddress((void**)&pk, g_k);
    cudaGetSymbolAddress((void**)&pv, g_v);
    cudaGetSymbolAddress((void**)&pa, g_ao);

    const int M = B_ * N_;               // 8192
    dim3 ggrid(D_ / 64, M / 128);        // (8, 64)

    gemm_tf32<<<ggrid, 256>>>(x, Wq, bq, pq, M, D_, D_);
    gemm_tf32<<<ggrid, 256>>>(x, Wk, bk, pk, M, D_, D_);
    gemm_tf32<<<ggrid, 256>>>(x, Wv, bv, pv, M, D_, D_);

    const int smem = ATTN_SMEM_FLOATS * 4;   // 144384
    cudaFuncSetAttribute(attn_tf32_kernel,
                         cudaFuncAttributeMaxDynamicSharedMemorySize, smem);
    attn_tf32_kernel<<<dim3(N_ / 128, H_, B_), 256, smem>>>(pq, pk, pv, adj, pa);

    gemm_tf32<<<ggrid, 256>>>(pa, Wo, bo, out, M, D_, D_);
}

// round 9
// speedup vs baseline: 2.7437x; 1.1728x over previous
#include <cuda_runtime.h>
#include <cstdint>

// Problem constants
#define B_  4
#define N_  2048
#define D_  512
#define H_  8
#define HD_ 64

// Scratch (allocation-free rule: __device__ globals)
static __device__ float g_q [B_ * N_ * D_];
static __device__ float g_k [B_ * N_ * D_];
static __device__ float g_v [B_ * N_ * D_];
static __device__ float g_ao[B_ * N_ * D_];
static __device__ unsigned g_adjbits[N_ * (N_ / 32)];   // 512 KB bitmask

// ---------------------------------------------------------------------------
// helpers
// ---------------------------------------------------------------------------
__device__ __forceinline__ unsigned f2tf32(float x) {
    unsigned r;
    asm("cvt.rna.tf32.f32 %0, %1;" : "=r"(r) : "f"(x));
    return r;
}

__device__ __forceinline__ void mma_tf32(float c[4],
    unsigned a0, unsigned a1, unsigned a2, unsigned a3,
    unsigned b0, unsigned b1)
{
    asm volatile(
        "mma.sync.aligned.m16n8k8.row.col.f32.tf32.tf32.f32 "
        "{%0,%1,%2,%3}, {%4,%5,%6,%7}, {%8,%9}, {%0,%1,%2,%3};\n"
        : "+f"(c[0]), "+f"(c[1]), "+f"(c[2]), "+f"(c[3])
        : "r"(a0), "r"(a1), "r"(a2), "r"(a3), "r"(b0), "r"(b1));
}

// ldmatrix x4: each 8x8xb16 matrix == 8 rows x 4 f32. reg j of lane l =
// element (l/4, l%4) of matrix j.
__device__ __forceinline__ void ldsm_x4(unsigned r[4], const unsigned* p) {
    unsigned addr = (unsigned)__cvta_generic_to_shared(p);
    asm volatile(
        "ldmatrix.sync.aligned.m8n8.x4.shared.b16 {%0,%1,%2,%3}, [%4];\n"
        : "=r"(r[0]), "=r"(r[1]), "=r"(r[2]), "=r"(r[3]) : "r"(addr));
}

// ---------------------------------------------------------------------------
// adj -> bitmask pack (adj is exactly 0.0f / 1.0f)
// ---------------------------------------------------------------------------
__global__ __launch_bounds__(256) void pack_adj_kernel(
    const float* __restrict__ adj, unsigned* __restrict__ bits)
{
    int idx = blockIdx.x * 256 + threadIdx.x;        // 131072 words
    const float* p = adj + (size_t)idx * 32;
    unsigned m = 0;
    #pragma unroll
    for (int j = 0; j < 32; j += 4) {
        float4 v = *(const float4*)(p + j);
        m |= (v.x != 0.f ? 1u : 0u) << (j + 0);
        m |= (v.y != 0.f ? 1u : 0u) << (j + 1);
        m |= (v.z != 0.f ? 1u : 0u) << (j + 2);
        m |= (v.w != 0.f ? 1u : 0u) << (j + 3);
    }
    bits[idx] = m;
}

// ---------------------------------------------------------------------------
// TF32 GEMM with bias: C[M,N] = A[M,K] @ W[K,N] + bias
// BM=128, BN=64, BK=32; 8 warps (4x2), warp tile 32x32.
// Double-buffered smem + register prefetch, ldmatrix A-frags.
// ---------------------------------------------------------------------------
#define GA_PITCH 36   // %32==4 -> conflict-free LDSM / gathers
#define GB_PITCH 72   // %32==8 -> conflict-free B scalar gathers
#define GA_WORDS (128 * GA_PITCH)
#define GB_WORDS (32 * GB_PITCH)
#define GEMM_SMEM_BYTES ((GA_WORDS + GB_WORDS) * 2 * 4)   // 55296

__global__ __launch_bounds__(256, 2) void gemm_tf32(
    const float* __restrict__ A, const float* __restrict__ W,
    const float* __restrict__ bias, float* __restrict__ C,
    int M, int N, int K)
{
    extern __shared__ unsigned gsm[];
    unsigned* As[2] = { gsm, gsm + GA_WORDS };
    unsigned* Bs[2] = { gsm + 2 * GA_WORDS, gsm + 2 * GA_WORDS + GB_WORDS };

    const int tid  = threadIdx.x;
    const int warp = tid >> 5;
    const int lane = tid & 31;
    const int wm = warp >> 1, wn = warp & 1;
    const int gid = lane >> 2, tig = lane & 3;
    const int lr = lane & 7, lm = lane >> 3;

    const int rowBase = blockIdx.y * 128;
    const int colBase = blockIdx.x * 64;

    const int aRow = tid >> 3;           // 0..31
    const int aCol = (tid & 7) * 4;
    const int bRow = tid >> 4;           // 0..15
    const int bCol = (tid & 15) * 4;

    float acc[2][4][4];
    #pragma unroll
    for (int mt = 0; mt < 2; mt++)
        #pragma unroll
        for (int nt = 0; nt < 4; nt++)
            #pragma unroll
            for (int i = 0; i < 4; i++) acc[mt][nt][i] = 0.f;

    float4 aReg[4], bReg[2];
    #pragma unroll
    for (int p = 0; p < 4; p++)
        aReg[p] = *(const float4*)(A + (size_t)(rowBase + aRow + p * 32) * K + aCol);
    #pragma unroll
    for (int p = 0; p < 2; p++)
        bReg[p] = *(const float4*)(W + (size_t)(bRow + p * 16) * N + colBase + bCol);

    #pragma unroll
    for (int p = 0; p < 4; p++) {
        uint4 t = make_uint4(f2tf32(aReg[p].x), f2tf32(aReg[p].y),
                             f2tf32(aReg[p].z), f2tf32(aReg[p].w));
        *(uint4*)&As[0][(aRow + p * 32) * GA_PITCH + aCol] = t;
    }
    #pragma unroll
    for (int p = 0; p < 2; p++) {
        uint4 t = make_uint4(f2tf32(bReg[p].x), f2tf32(bReg[p].y),
                             f2tf32(bReg[p].z), f2tf32(bReg[p].w));
        *(uint4*)&Bs[0][(bRow + p * 16) * GB_PITCH + bCol] = t;
    }
    __syncthreads();

    const int aFragRowOff = lr + (lm & 1) * 8;
    const int aFragColOff = (lm >> 1) * 4;

    for (int k0 = 0; k0 < K; k0 += 32) {
        const int cur = (k0 >> 5) & 1;
        const int nxt = cur ^ 1;
        const bool hasNext = (k0 + 32 < K);

        if (hasNext) {
            #pragma unroll
            for (int p = 0; p < 4; p++)
                aReg[p] = *(const float4*)(A + (size_t)(rowBase + aRow + p * 32) * K + k0 + 32 + aCol);
            #pragma unroll
            for (int p = 0; p < 2; p++)
                bReg[p] = *(const float4*)(W + (size_t)(k0 + 32 + bRow + p * 16) * N + colBase + bCol);
        }

        #pragma unroll
        for (int ks = 0; ks < 4; ks++) {
            unsigned a[2][4];
            #pragma unroll
            for (int mt = 0; mt < 2; mt++)
                ldsm_x4(a[mt], &As[cur][(wm * 32 + mt * 16 + aFragRowOff) * GA_PITCH
                                        + ks * 8 + aFragColOff]);
            #pragma unroll
            for (int nt = 0; nt < 4; nt++) {
                int n = wn * 32 + nt * 8 + gid;
                unsigned b0 = Bs[cur][(ks * 8 + tig) * GB_PITCH + n];
                unsigned b1 = Bs[cur][(ks * 8 + tig + 4) * GB_PITCH + n];
                #pragma unroll
                for (int mt = 0; mt < 2; mt++)
                    mma_tf32(acc[mt][nt], a[mt][0], a[mt][1], a[mt][2], a[mt][3], b0, b1);
            }
        }

        if (hasNext) {
            #pragma unroll
            for (int p = 0; p < 4; p++) {
                uint4 t = make_uint4(f2tf32(aReg[p].x), f2tf32(aReg[p].y),
                                     f2tf32(aReg[p].z), f2tf32(aReg[p].w));
                *(uint4*)&As[nxt][(aRow + p * 32) * GA_PITCH + aCol] = t;
            }
            #pragma unroll
            for (int p = 0; p < 2; p++) {
                uint4 t = make_uint4(f2tf32(bReg[p].x), f2tf32(bReg[p].y),
                                     f2tf32(bReg[p].z), f2tf32(bReg[p].w));
                *(uint4*)&Bs[nxt][(bRow + p * 16) * GB_PITCH + bCol] = t;
            }
        }
        __syncthreads();
    }

    #pragma unroll
    for (int mt = 0; mt < 2; mt++) {
        int r0 = rowBase + wm * 32 + mt * 16 + gid;
        #pragma unroll
        for (int nt = 0; nt < 4; nt++) {
            int col = colBase + wn * 32 + nt * 8 + tig * 2;
            float2 bv = *(const float2*)(bias + col);
            *(float2*)(C + (size_t)r0 * N + col) =
                make_float2(acc[mt][nt][0] + bv.x, acc[mt][nt][1] + bv.y);
            *(float2*)(C + (size_t)(r0 + 8) * N + col) =
                make_float2(acc[mt][nt][2] + bv.x, acc[mt][nt][3] + bv.y);
        }
    }
}

// ---------------------------------------------------------------------------
// Fused masked flash attention, tf32 mma, warp-local softmax.
// q-tile=128 (8 warps x 16 rows), k-tile=64. 2 syncthreads per k-tile.
// Q fragments live in registers. adj read as bitmask straight from gmem/L2.
// ---------------------------------------------------------------------------
#define KS_PITCH 68   // %32==4: LDSM-friendly (rows = key)
#define VS_PITCH 72   // %32==8: conflict-free scalar B gathers (rows = key)
#define PS_PITCH 68
#define KS_OFF 0
#define VS_OFF (64 * KS_PITCH)                 // 4352
#define PS_OFF (VS_OFF + 64 * VS_PITCH)        // 8960
#define ATTN_SMEM_WORDS (PS_OFF + 128 * PS_PITCH)   // 17664 -> 70656 B

__global__ __launch_bounds__(256, 1) void attn_tf32_kernel(
    const float* __restrict__ q, const float* __restrict__ k,
    const float* __restrict__ v, const unsigned* __restrict__ mbits,
    float* __restrict__ o)
{
    extern __shared__ unsigned smu[];

    const int tid  = threadIdx.x;
    const int warp = tid >> 5;
    const int lane = tid & 31;
    const int gid = lane >> 2, tig = lane & 3;
    const int lr = lane & 7, lm = lane >> 3;

    const int q0 = blockIdx.x * 128;
    const int h  = blockIdx.y;
    const int b  = blockIdx.z;
    const int row0 = warp * 16;

    const float* qbase = q + (size_t)b * N_ * D_ + h * HD_;
    const float* kbase = k + (size_t)b * N_ * D_ + h * HD_;
    const float* vbase = v + (size_t)b * N_ * D_ + h * HD_;

    // Stage Q tile (scaled, tf32) in PS region, then hoist frags to registers.
    #pragma unroll
    for (int p = 0; p < 8; p++) {
        int idx = tid + p * 256;
        int r = idx >> 4;
        int c4 = (idx & 15) * 4;
        float4 val = *(const float4*)(qbase + (size_t)(q0 + r) * D_ + c4);
        uint4 t = make_uint4(f2tf32(val.x * 0.125f), f2tf32(val.y * 0.125f),
                             f2tf32(val.z * 0.125f), f2tf32(val.w * 0.125f));
        *(uint4*)&smu[PS_OFF + r * PS_PITCH + c4] = t;
    }
    __syncthreads();

    const int aFragRow = row0 + lr + (lm & 1) * 8;   // A-frag LDSM row
    const int aFragCol = (lm >> 1) * 4;              // A-frag LDSM col offset

    unsigned qf[8][4];
    #pragma unroll
    for (int ks = 0; ks < 8; ks++)
        ldsm_x4(qf[ks], &smu[PS_OFF + aFragRow * PS_PITCH + ks * 8 + aFragCol]);

    float O[8][4];
    #pragma unroll
    for (int nt = 0; nt < 8; nt++)
        #pragma unroll
        for (int i = 0; i < 4; i++) O[nt][i] = 0.f;
    float mA = -1e30f, mB = -1e30f, lA = 0.f, lB = 0.f;

    const int rowA = q0 + row0 + gid;
    const int rowB = rowA + 8;
    const unsigned* mrowA = mbits + (size_t)rowA * (N_ / 32);
    const unsigned* mrowB = mbits + (size_t)rowB * (N_ / 32);

    for (int k0 = 0; k0 < N_; k0 += 64) {
        // mask bits for this tile (L2-resident, independent of smem)
        uint2 ma2 = *(const uint2*)(mrowA + (k0 >> 5));
        uint2 mb2 = *(const uint2*)(mrowB + (k0 >> 5));
        uint64_t maskA = (uint64_t)ma2.x | ((uint64_t)ma2.y << 32);
        uint64_t maskB = (uint64_t)mb2.x | ((uint64_t)mb2.y << 32);

        __syncthreads();   // all warps done reading prev KS/VS
        #pragma unroll
        for (int p = 0; p < 4; p++) {
            int idx = tid + p * 256;
            int r = idx >> 4;
            int c4 = (idx & 15) * 4;
            float4 kv = *(const float4*)(kbase + (size_t)(k0 + r) * D_ + c4);
            *(uint4*)&smu[KS_OFF + r * KS_PITCH + c4] =
                make_uint4(f2tf32(kv.x), f2tf32(kv.y), f2tf32(kv.z), f2tf32(kv.w));
            float4 vv = *(const float4*)(vbase + (size_t)(k0 + r) * D_ + c4);
            *(uint4*)&smu[VS_OFF + r * VS_PITCH + c4] =
                make_uint4(f2tf32(vv.x), f2tf32(vv.y), f2tf32(vv.z), f2tf32(vv.w));
        }
        __syncthreads();

        // ---- S = Q @ K^T : warp rows row0..row0+15, all 64 keys ----
        float s[8][4];
        #pragma unroll
        for (int nt = 0; nt < 8; nt++)
            #pragma unroll
            for (int i = 0; i < 4; i++) s[nt][i] = 0.f;

        const int bFragRow = lr + (lm >> 1) * 8;     // B-frag LDSM row-in-group
        const int bFragColB = (lm & 1) * 4;
        #pragma unroll
        for (int ks = 0; ks < 8; ks++) {
            unsigned kb[4][4];
            #pragma unroll
            for (int ntp = 0; ntp < 4; ntp++)
                ldsm_x4(kb[ntp], &smu[KS_OFF + (ntp * 16 + bFragRow) * KS_PITCH
                                      + ks * 8 + bFragColB]);
            #pragma unroll
            for (int nt = 0; nt < 8; nt++)
                mma_tf32(s[nt], qf[ks][0], qf[ks][1], qf[ks][2], qf[ks][3],
                         kb[nt >> 1][(nt & 1) * 2], kb[nt >> 1][(nt & 1) * 2 + 1]);
        }

        // ---- mask (same arithmetic as reference: s + (-1e9)) ----
        #pragma unroll
        for (int nt = 0; nt < 8; nt++) {
            int c = nt * 8 + tig * 2;
            if (!((maskA >> c) & 1))       s[nt][0] -= 1e9f;
            if (!((maskA >> (c + 1)) & 1)) s[nt][1] -= 1e9f;
            if (!((maskB >> c) & 1))       s[nt][2] -= 1e9f;
            if (!((maskB >> (c + 1)) & 1)) s[nt][3] -= 1e9f;
        }

        // ---- warp-local online softmax (rows rowA, rowB) ----
        float mxA = -1e30f, mxB = -1e30f;
        #pragma unroll
        for (int nt = 0; nt < 8; nt++) {
            mxA = fmaxf(mxA, fmaxf(s[nt][0], s[nt][1]));
            mxB = fmaxf(mxB, fmaxf(s[nt][2], s[nt][3]));
        }
        mxA = fmaxf(mxA, __shfl_xor_sync(0xffffffffu, mxA, 1));
        mxA = fmaxf(mxA, __shfl_xor_sync(0xffffffffu, mxA, 2));
        mxB = fmaxf(mxB, __shfl_xor_sync(0xffffffffu, mxB, 1));
        mxB = fmaxf(mxB, __shfl_xor_sync(0xffffffffu, mxB, 2));

        float mnA = fmaxf(mA, mxA), mnB = fmaxf(mB, mxB);
        float alA = __expf(mA - mnA), alB = __expf(mB - mnB);
        mA = mnA; mB = mnB;

        float rsA = 0.f, rsB = 0.f;
        #pragma unroll
        for (int nt = 0; nt < 8; nt++) {
            float p0 = __expf(s[nt][0] - mnA);
            float p1 = __expf(s[nt][1] - mnA);
            float p2 = __expf(s[nt][2] - mnB);
            float p3 = __expf(s[nt][3] - mnB);
            rsA += p0 + p1;
            rsB += p2 + p3;
            int c = nt * 8 + tig * 2;
            *(uint2*)&smu[PS_OFF + (row0 + gid) * PS_PITCH + c] =
                make_uint2(f2tf32(p0), f2tf32(p1));
            *(uint2*)&smu[PS_OFF + (row0 + gid + 8) * PS_PITCH + c] =
                make_uint2(f2tf32(p2), f2tf32(p3));
            O[nt][0] *= alA; O[nt][1] *= alA;
            O[nt][2] *= alB; O[nt][3] *= alB;
        }
        rsA += __shfl_xor_sync(0xffffffffu, rsA, 1);
        rsA += __shfl_xor_sync(0xffffffffu, rsA, 2);
        rsB += __shfl_xor_sync(0xffffffffu, rsB, 1);
        rsB += __shfl_xor_sync(0xffffffffu, rsB, 2);
        lA = lA * alA + rsA;
        lB = lB * alB + rsB;
        __syncwarp();      // P rows are warp-private: warp sync suffices

        // ---- O += P @ V ----
        #pragma unroll
        for (int ks = 0; ks < 8; ks++) {
            unsigned pf[4];
            ldsm_x4(pf, &smu[PS_OFF + aFragRow * PS_PITCH + ks * 8 + aFragCol]);
            #pragma unroll
            for (int nt = 0; nt < 8; nt++) {
                int d = nt * 8 + gid;
                unsigned b0 = smu[VS_OFF + (ks * 8 + tig) * VS_PITCH + d];
                unsigned b1 = smu[VS_OFF + (ks * 8 + tig + 4) * VS_PITCH + d];
                mma_tf32(O[nt], pf[0], pf[1], pf[2], pf[3], b0, b1);
            }
        }
    }

    // Finalize
    float invA = 1.0f / lA, invB = 1.0f / lB;
    float* obase = o + (size_t)b * N_ * D_ + h * HD_;
    #pragma unroll
    for (int nt = 0; nt < 8; nt++) {
        int c = nt * 8 + tig * 2;
        *(float2*)(obase + (size_t)rowA * D_ + c) =
            make_float2(O[nt][0] * invA, O[nt][1] * invA);
        *(float2*)(obase + (size_t)rowB * D_ + c) =
            make_float2(O[nt][2] * invB, O[nt][3] * invB);
    }
}

// ---------------------------------------------------------------------------
extern "C" void kernel_launch(void* const* d_in, const int* in_sizes, int n_in,
                              void* d_out, int out_size)
{
    const float* x   = (const float*)d_in[0];
    const float* adj = (const float*)d_in[1];
    const float* Wq  = (const float*)d_in[2];
    const float* bq  = (const float*)d_in[3];
    const float* Wk  = (const float*)d_in[4];
    const float* bk  = (const float*)d_in[5];
    const float* Wv  = (const float*)d_in[6];
    const float* bv  = (const float*)d_in[7];
    const float* Wo  = (const float*)d_in[8];
    const float* bo  = (const float*)d_in[9];
    float* out = (float*)d_out;

    float *pq, *pk, *pv, *pa;
    unsigned* pbits;
    cudaGetSymbolAddress((void**)&pq, g_q);
    cudaGetSymbolAddress((void**)&pk, g_k);
    cudaGetSymbolAddress((void**)&pv, g_v);
    cudaGetSymbolAddress((void**)&pa, g_ao);
    cudaGetSymbolAddress((void**)&pbits, g_adjbits);

    pack_adj_kernel<<<(N_ * (N_ / 32)) / 256, 256>>>(adj, pbits);

    const int M = B_ * N_;               // 8192
    dim3 ggrid(D_ / 64, M / 128);        // (8, 64)

    cudaFuncSetAttribute(gemm_tf32,
                         cudaFuncAttributeMaxDynamicSharedMemorySize,
                         GEMM_SMEM_BYTES);
    gemm_tf32<<<ggrid, 256, GEMM_SMEM_BYTES>>>(x, Wq, bq, pq, M, D_, D_);
    gemm_tf32<<<ggrid, 256, GEMM_SMEM_BYTES>>>(x, Wk, bk, pk, M, D_, D_);
    gemm_tf32<<<ggrid, 256, GEMM_SMEM_BYTES>>>(x, Wv, bv, pv, M, D_, D_);

    const int asmem = ATTN_SMEM_WORDS * 4;   // 70656
    cudaFuncSetAttribute(attn_tf32_kernel,
                         cudaFuncAttributeMaxDynamicSharedMemorySize, asmem);
    attn_tf32_kernel<<<dim3(N_ / 128, H_, B_), 256, asmem>>>(pq, pk, pv, pbits, pa);

    gemm_tf32<<<ggrid, 256, GEMM_SMEM_BYTES>>>(pa, Wo, bo, out, M, D_, D_);
}

// round 10
// speedup vs baseline: 4.3082x; 1.5702x over previous
#include <cuda_runtime.h>
#include <cuda_fp16.h>
#include <cstdint>

// Problem constants
#define B_  4
#define N_  2048
#define D_  512
#define H_  8
#define HD_ 64

// Scratch (allocation-free rule: __device__ globals)
static __device__ float g_q [B_ * N_ * D_];
static __device__ float g_k [B_ * N_ * D_];
static __device__ float g_v [B_ * N_ * D_];
static __device__ float g_ao[B_ * N_ * D_];
static __device__ unsigned g_adjbits[N_ * (N_ / 32)];   // 512 KB bitmask

// ---------------------------------------------------------------------------
// helpers
// ---------------------------------------------------------------------------
__device__ __forceinline__ unsigned h2pack(float a, float b) {
    __half2 h = __floats2half2_rn(a, b);   // lo = a, hi = b
    return *reinterpret_cast<unsigned*>(&h);
}

// fp16 mma, fp32 accumulate. m16n8k16.
// A frag (4 regs): a0={(r,2c),(r,2c+1)} a1={(r+8,2c),(r+8,2c+1)}
//                  a2={(r,2c+8),(r,2c+9)} a3={(r+8,2c+8),(r+8,2c+9)}
// B frag (2 regs): b0={(2c,g),(2c+1,g)} b1={(2c+8,g),(2c+9,g)}
// C frag: c0=(r,2c) c1=(r,2c+1) c2=(r+8,2c) c3=(r+8,2c+1); r=lane/4,c=lane%4
__device__ __forceinline__ void mma_f16(float c[4], const unsigned a[4],
                                        unsigned b0, unsigned b1)
{
    asm volatile(
        "mma.sync.aligned.m16n8k16.row.col.f32.f16.f16.f32 "
        "{%0,%1,%2,%3}, {%4,%5,%6,%7}, {%8,%9}, {%0,%1,%2,%3};\n"
        : "+f"(c[0]), "+f"(c[1]), "+f"(c[2]), "+f"(c[3])
        : "r"(a[0]), "r"(a[1]), "r"(a[2]), "r"(a[3]), "r"(b0), "r"(b1));
}

__device__ __forceinline__ void ldsm_x4(unsigned r[4], const __half* p) {
    unsigned addr = (unsigned)__cvta_generic_to_shared(p);
    asm volatile(
        "ldmatrix.sync.aligned.m8n8.x4.shared.b16 {%0,%1,%2,%3}, [%4];\n"
        : "=r"(r[0]), "=r"(r[1]), "=r"(r[2]), "=r"(r[3]) : "r"(addr));
}

__device__ __forceinline__ void ldsm_x4_t(unsigned r[4], const __half* p) {
    unsigned addr = (unsigned)__cvta_generic_to_shared(p);
    asm volatile(
        "ldmatrix.sync.aligned.m8n8.x4.trans.shared.b16 {%0,%1,%2,%3}, [%4];\n"
        : "=r"(r[0]), "=r"(r[1]), "=r"(r[2]), "=r"(r[3]) : "r"(addr));
}

// ---------------------------------------------------------------------------
// adj -> bitmask pack (adj is exactly 0.0f / 1.0f)
// ---------------------------------------------------------------------------
__global__ __launch_bounds__(256) void pack_adj_kernel(
    const float* __restrict__ adj, unsigned* __restrict__ bits)
{
    int idx = blockIdx.x * 256 + threadIdx.x;        // 131072 words
    const float* p = adj + (size_t)idx * 32;
    unsigned m = 0;
    #pragma unroll
    for (int j = 0; j < 32; j += 4) {
        float4 v = *(const float4*)(p + j);
        m |= (v.x != 0.f ? 1u : 0u) << (j + 0);
        m |= (v.y != 0.f ? 1u : 0u) << (j + 1);
        m |= (v.z != 0.f ? 1u : 0u) << (j + 2);
        m |= (v.w != 0.f ? 1u : 0u) << (j + 3);
    }
    bits[idx] = m;
}

// ---------------------------------------------------------------------------
// FP16 GEMM with bias: C[M,N] = A[M,K] @ W[K,N] + bias  (fp32 accum)
// BM=128, BN=64, BK=32; 8 warps (4x2), warp tile 32x32.
// As[m][k] row-major (normal LDSM); Bs[k][n] k-major (trans LDSM).
// Double-buffered smem, register prefetch with immediate f32->f16 convert.
// ---------------------------------------------------------------------------
#define GA_PITCH 40                 // halves; 80B = 5x16B (odd stride, LDSM-safe)
#define GB_PITCH 72                 // halves; 144B = 9x16B
#define GA_HALVES (128 * GA_PITCH)  // 5120
#define GB_HALVES (32 * GB_PITCH)   // 2304
#define GBUF_HALVES (GA_HALVES + GB_HALVES)          // 7424
#define GEMM_SMEM_BYTES (GBUF_HALVES * 2 * 2)        // 29696

__global__ __launch_bounds__(256, 2) void gemm_f16(
    const float* __restrict__ A, const float* __restrict__ W,
    const float* __restrict__ bias, float* __restrict__ C,
    int M, int N, int K)
{
    extern __shared__ __half gsm[];
    __half* As[2] = { gsm, gsm + GBUF_HALVES };
    __half* Bs[2] = { gsm + GA_HALVES, gsm + GBUF_HALVES + GA_HALVES };

    const int tid  = threadIdx.x;
    const int warp = tid >> 5;
    const int lane = tid & 31;
    const int wm = warp >> 1, wn = warp & 1;
    const int gid = lane >> 2, tig = lane & 3;
    const int rsel = (lane & 7) + ((lane >> 3) & 1) * 8;
    const int csel = (lane >> 4) * 8;

    const int rowBase = blockIdx.y * 128;
    const int colBase = blockIdx.x * 64;

    const int aRow = tid >> 3;           // 0..31, 4 passes stride 32
    const int aCol = (tid & 7) * 4;
    const int bRow = tid >> 4;           // 0..15, 2 passes stride 16
    const int bCol = (tid & 15) * 4;

    float acc[2][4][4];
    #pragma unroll
    for (int mt = 0; mt < 2; mt++)
        #pragma unroll
        for (int nt = 0; nt < 4; nt++)
            #pragma unroll
            for (int i = 0; i < 4; i++) acc[mt][nt][i] = 0.f;

    uint2 ah[4], bh[2];
    #pragma unroll
    for (int p = 0; p < 4; p++) {
        float4 v = *(const float4*)(A + (size_t)(rowBase + aRow + p * 32) * K + aCol);
        ah[p] = make_uint2(h2pack(v.x, v.y), h2pack(v.z, v.w));
    }
    #pragma unroll
    for (int p = 0; p < 2; p++) {
        float4 v = *(const float4*)(W + (size_t)(bRow + p * 16) * N + colBase + bCol);
        bh[p] = make_uint2(h2pack(v.x, v.y), h2pack(v.z, v.w));
    }
    #pragma unroll
    for (int p = 0; p < 4; p++)
        *(uint2*)&As[0][(aRow + p * 32) * GA_PITCH + aCol] = ah[p];
    #pragma unroll
    for (int p = 0; p < 2; p++)
        *(uint2*)&Bs[0][(bRow + p * 16) * GB_PITCH + bCol] = bh[p];
    __syncthreads();

    for (int k0 = 0; k0 < K; k0 += 32) {
        const int cur = (k0 >> 5) & 1;
        const int nxt = cur ^ 1;
        const bool hasNext = (k0 + 32 < K);

        if (hasNext) {
            #pragma unroll
            for (int p = 0; p < 4; p++) {
                float4 v = *(const float4*)(A + (size_t)(rowBase + aRow + p * 32) * K + k0 + 32 + aCol);
                ah[p] = make_uint2(h2pack(v.x, v.y), h2pack(v.z, v.w));
            }
            #pragma unroll
            for (int p = 0; p < 2; p++) {
                float4 v = *(const float4*)(W + (size_t)(k0 + 32 + bRow + p * 16) * N + colBase + bCol);
                bh[p] = make_uint2(h2pack(v.x, v.y), h2pack(v.z, v.w));
            }
        }

        #pragma unroll
        for (int ks = 0; ks < 2; ks++) {
            unsigned a[2][4];
            #pragma unroll
            for (int mt = 0; mt < 2; mt++)
                ldsm_x4(a[mt], &As[cur][(wm * 32 + mt * 16 + rsel) * GA_PITCH
                                        + ks * 16 + csel]);
            unsigned bb[2][4];
            #pragma unroll
            for (int np = 0; np < 2; np++)
                ldsm_x4_t(bb[np], &Bs[cur][(ks * 16 + rsel) * GB_PITCH
                                           + wn * 32 + np * 16 + csel]);
            #pragma unroll
            for (int nt = 0; nt < 4; nt++)
                #pragma unroll
                for (int mt = 0; mt < 2; mt++)
                    mma_f16(acc[mt][nt], a[mt],
                            bb[nt >> 1][(nt & 1) * 2], bb[nt >> 1][(nt & 1) * 2 + 1]);
        }

        if (hasNext) {
            #pragma unroll
            for (int p = 0; p < 4; p++)
                *(uint2*)&As[nxt][(aRow + p * 32) * GA_PITCH + aCol] = ah[p];
            #pragma unroll
            for (int p = 0; p < 2; p++)
                *(uint2*)&Bs[nxt][(bRow + p * 16) * GB_PITCH + bCol] = bh[p];
        }
        __syncthreads();
    }

    #pragma unroll
    for (int mt = 0; mt < 2; mt++) {
        int r0 = rowBase + wm * 32 + mt * 16 + gid;
        #pragma unroll
        for (int nt = 0; nt < 4; nt++) {
            int col = colBase + wn * 32 + nt * 8 + tig * 2;
            float2 bv = *(const float2*)(bias + col);
            *(float2*)(C + (size_t)r0 * N + col) =
                make_float2(acc[mt][nt][0] + bv.x, acc[mt][nt][1] + bv.y);
            *(float2*)(C + (size_t)(r0 + 8) * N + col) =
                make_float2(acc[mt][nt][2] + bv.x, acc[mt][nt][3] + bv.y);
        }
    }
}

// ---------------------------------------------------------------------------
// Fused masked flash attention, fp16 mma, warp-local softmax, P in registers.
// q-tile=128 (8 warps x 16 rows), k-tile=64, double-buffered K/V smem,
// 1 syncthreads per k-tile. adj as bitmask from gmem/L2.
// KS[key][d] (normal LDSM -> B frags of S), VS[key][d] (trans LDSM -> B of PV).
// ---------------------------------------------------------------------------
#define KV_PITCH 72                           // halves; 144B = 9x16B
#define KV_TILE_HALVES (64 * KV_PITCH)        // 4608
#define KV_BUF_HALVES (2 * KV_TILE_HALVES)    // K + V = 9216
#define ATTN_SMEM_BYTES (KV_BUF_HALVES * 2 * 2)   // 36864

__global__ __launch_bounds__(256, 2) void attn_f16_kernel(
    const float* __restrict__ q, const float* __restrict__ k,
    const float* __restrict__ v, const unsigned* __restrict__ mbits,
    float* __restrict__ o)
{
    extern __shared__ __half smh[];
    __half* KS[2] = { smh,                 smh + KV_BUF_HALVES };
    __half* VS[2] = { smh + KV_TILE_HALVES, smh + KV_BUF_HALVES + KV_TILE_HALVES };

    const int tid  = threadIdx.x;
    const int warp = tid >> 5;
    const int lane = tid & 31;
    const int gid = lane >> 2, tig = lane & 3;
    const int rsel = (lane & 7) + ((lane >> 3) & 1) * 8;
    const int csel = (lane >> 4) * 8;

    const int q0 = blockIdx.x * 128;
    const int h  = blockIdx.y;
    const int b  = blockIdx.z;
    const int row0 = warp * 16;

    const float* qbase = q + (size_t)b * N_ * D_ + h * HD_;
    const float* kbase = k + (size_t)b * N_ * D_ + h * HD_;
    const float* vbase = v + (size_t)b * N_ * D_ + h * HD_;

    // ---- stage Q (scaled 0.125, fp16) into smem (overlays buf0), hoist ----
    #pragma unroll
    for (int p = 0; p < 8; p++) {
        int idx = tid + p * 256;              // 0..2047
        int r = idx >> 4;                     // 0..127
        int c4 = (idx & 15) * 4;
        float4 val = *(const float4*)(qbase + (size_t)(q0 + r) * D_ + c4);
        *(uint2*)&smh[r * KV_PITCH + c4] =
            make_uint2(h2pack(val.x * 0.125f, val.y * 0.125f),
                       h2pack(val.z * 0.125f, val.w * 0.125f));
    }
    __syncthreads();

    unsigned qf[4][4];
    #pragma unroll
    for (int ks = 0; ks < 4; ks++)
        ldsm_x4(qf[ks], &smh[(row0 + rsel) * KV_PITCH + ks * 16 + csel]);

    // prefetch tile 0 from gmem (convert immediately; 16 regs)
    uint2 kh[4], vh[4];
    #pragma unroll
    for (int p = 0; p < 4; p++) {
        int idx = tid + p * 256;              // 0..1023
        int r = idx >> 4;                     // 0..63
        int c4 = (idx & 15) * 4;
        float4 kv = *(const float4*)(kbase + (size_t)r * D_ + c4);
        kh[p] = make_uint2(h2pack(kv.x, kv.y), h2pack(kv.z, kv.w));
        float4 vv = *(const float4*)(vbase + (size_t)r * D_ + c4);
        vh[p] = make_uint2(h2pack(vv.x, vv.y), h2pack(vv.z, vv.w));
    }
    __syncthreads();   // all warps finished hoisting Q before overwrite

    #pragma unroll
    for (int p = 0; p < 4; p++) {
        int idx = tid + p * 256;
        int r = idx >> 4;
        int c4 = (idx & 15) * 4;
        *(uint2*)&KS[0][r * KV_PITCH + c4] = kh[p];
        *(uint2*)&VS[0][r * KV_PITCH + c4] = vh[p];
    }
    __syncthreads();

    float O[8][4];
    #pragma unroll
    for (int nt = 0; nt < 8; nt++)
        #pragma unroll
        for (int i = 0; i < 4; i++) O[nt][i] = 0.f;
    float mA = -1e30f, mB = -1e30f, lA = 0.f, lB = 0.f;

    const int rowA = q0 + row0 + gid;
    const int rowB = rowA + 8;
    const unsigned* mrowA = mbits + (size_t)rowA * (N_ / 32);
    const unsigned* mrowB = mbits + (size_t)rowB * (N_ / 32);

    for (int it = 0; it < N_ / 64; it++) {
        const int k0 = it * 64;
        const int cur = it & 1;
        const bool hasNext = (it < N_ / 64 - 1);

        // mask bits (L2-resident)
        uint2 ma2 = *(const uint2*)(mrowA + (k0 >> 5));
        uint2 mb2 = *(const uint2*)(mrowB + (k0 >> 5));
        uint64_t maskA = (uint64_t)ma2.x | ((uint64_t)ma2.y << 32);
        uint64_t maskB = (uint64_t)mb2.x | ((uint64_t)mb2.y << 32);

        // prefetch next tile (gmem latency overlaps mma below)
        if (hasNext) {
            #pragma unroll
            for (int p = 0; p < 4; p++) {
                int idx = tid + p * 256;
                int r = idx >> 4;
                int c4 = (idx & 15) * 4;
                float4 kv = *(const float4*)(kbase + (size_t)(k0 + 64 + r) * D_ + c4);
                kh[p] = make_uint2(h2pack(kv.x, kv.y), h2pack(kv.z, kv.w));
                float4 vv = *(const float4*)(vbase + (size_t)(k0 + 64 + r) * D_ + c4);
                vh[p] = make_uint2(h2pack(vv.x, vv.y), h2pack(vv.z, vv.w));
            }
        }

        // ---- S = Q @ K^T : warp rows row0..+15, keys k0..k0+63 ----
        float s[8][4];
        #pragma unroll
        for (int nt = 0; nt < 8; nt++)
            #pragma unroll
            for (int i = 0; i < 4; i++) s[nt][i] = 0.f;

        #pragma unroll
        for (int ks = 0; ks < 4; ks++) {
            unsigned kb[4][4];
            #pragma unroll
            for (int np = 0; np < 4; np++)
                ldsm_x4(kb[np], &KS[cur][(np * 16 + rsel) * KV_PITCH + ks * 16 + csel]);
            #pragma unroll
            for (int nt = 0; nt < 8; nt++)
                mma_f16(s[nt], qf[ks],
                        kb[nt >> 1][nt & 1], kb[nt >> 1][2 + (nt & 1)]);
        }

        // ---- mask (s + (-1e9), same arithmetic as reference) ----
        #pragma unroll
        for (int nt = 0; nt < 8; nt++) {
            int c = nt * 8 + tig * 2;
            if (!((maskA >> c) & 1))       s[nt][0] -= 1e9f;
            if (!((maskA >> (c + 1)) & 1)) s[nt][1] -= 1e9f;
            if (!((maskB >> c) & 1))       s[nt][2] -= 1e9f;
            if (!((maskB >> (c + 1)) & 1)) s[nt][3] -= 1e9f;
        }

        // ---- warp-local online softmax ----
        float mxA = -1e30f, mxB = -1e30f;
        #pragma unroll
        for (int nt = 0; nt < 8; nt++) {
            mxA = fmaxf(mxA, fmaxf(s[nt][0], s[nt][1]));
            mxB = fmaxf(mxB, fmaxf(s[nt][2], s[nt][3]));
        }
        mxA = fmaxf(mxA, __shfl_xor_sync(0xffffffffu, mxA, 1));
        mxA = fmaxf(mxA, __shfl_xor_sync(0xffffffffu, mxA, 2));
        mxB = fmaxf(mxB, __shfl_xor_sync(0xffffffffu, mxB, 1));
        mxB = fmaxf(mxB, __shfl_xor_sync(0xffffffffu, mxB, 2));

        float mnA = fmaxf(mA, mxA), mnB = fmaxf(mB, mxB);
        float alA = __expf(mA - mnA), alB = __expf(mB - mnB);
        mA = mnA; mB = mnB;

        // exp, pack P into registers (S C-frag layout == fp16 A-frag layout)
        unsigned ph[8][2];
        float rsA = 0.f, rsB = 0.f;
        #pragma unroll
        for (int nt = 0; nt < 8; nt++) {
            float p0 = __expf(s[nt][0] - mnA);
            float p1 = __expf(s[nt][1] - mnA);
            float p2 = __expf(s[nt][2] - mnB);
            float p3 = __expf(s[nt][3] - mnB);
            rsA += p0 + p1;
            rsB += p2 + p3;
            ph[nt][0] = h2pack(p0, p1);
            ph[nt][1] = h2pack(p2, p3);
            O[nt][0] *= alA; O[nt][1] *= alA;
            O[nt][2] *= alB; O[nt][3] *= alB;
        }
        rsA += __shfl_xor_sync(0xffffffffu, rsA, 1);
        rsA += __shfl_xor_sync(0xffffffffu, rsA, 2);
        rsB += __shfl_xor_sync(0xffffffffu, rsB, 1);
        rsB += __shfl_xor_sync(0xffffffffu, rsB, 2);
        lA = lA * alA + rsA;
        lB = lB * alB + rsB;

        // ---- O += P @ V (P straight from registers) ----
        #pragma unroll
        for (int ks = 0; ks < 4; ks++) {
            unsigned vb[4][4];
            #pragma unroll
            for (int dp = 0; dp < 4; dp++)
                ldsm_x4_t(vb[dp], &VS[cur][(ks * 16 + rsel) * KV_PITCH + dp * 16 + csel]);
            unsigned pa[4] = { ph[2 * ks][0], ph[2 * ks][1],
                               ph[2 * ks + 1][0], ph[2 * ks + 1][1] };
            #pragma unroll
            for (int nt = 0; nt < 8; nt++)
                mma_f16(O[nt], pa,
                        vb[nt >> 1][(nt & 1) * 2], vb[nt >> 1][(nt & 1) * 2 + 1]);
        }

        // store next tile into the other buffer
        if (hasNext) {
            #pragma unroll
            for (int p = 0; p < 4; p++) {
                int idx = tid + p * 256;
                int r = idx >> 4;
                int c4 = (idx & 15) * 4;
                *(uint2*)&KS[cur ^ 1][r * KV_PITCH + c4] = kh[p];
                *(uint2*)&VS[cur ^ 1][r * KV_PITCH + c4] = vh[p];
            }
        }
        __syncthreads();
    }

    // Finalize
    float invA = 1.0f / lA, invB = 1.0f / lB;
    float* obase = o + (size_t)b * N_ * D_ + h * HD_;
    #pragma unroll
    for (int nt = 0; nt < 8; nt++) {
        int c = nt * 8 + tig * 2;
        *(float2*)(obase + (size_t)rowA * D_ + c) =
            make_float2(O[nt][0] * invA, O[nt][1] * invA);
        *(float2*)(obase + (size_t)rowB * D_ + c) =
            make_float2(O[nt][2] * invB, O[nt][3] * invB);
    }
}

// ---------------------------------------------------------------------------
extern "C" void kernel_launch(void* const* d_in, const int* in_sizes, int n_in,
                              void* d_out, int out_size)
{
    const float* x   = (const float*)d_in[0];
    const float* adj = (const float*)d_in[1];
    const float* Wq  = (const float*)d_in[2];
    const float* bq  = (const float*)d_in[3];
    const float* Wk  = (const float*)d_in[4];
    const float* bk  = (const float*)d_in[5];
    const float* Wv  = (const float*)d_in[6];
    const float* bv  = (const float*)d_in[7];
    const float* Wo  = (const float*)d_in[8];
    const float* bo  = (const float*)d_in[9];
    float* out = (float*)d_out;

    float *pq, *pk, *pv, *pa;
    unsigned* pbits;
    cudaGetSymbolAddress((void**)&pq, g_q);
    cudaGetSymbolAddress((void**)&pk, g_k);
    cudaGetSymbolAddress((void**)&pv, g_v);
    cudaGetSymbolAddress((void**)&pa, g_ao);
    cudaGetSymbolAddress((void**)&pbits, g_adjbits);

    pack_adj_kernel<<<(N_ * (N_ / 32)) / 256, 256>>>(adj, pbits);

    const int M = B_ * N_;               // 8192
    dim3 ggrid(D_ / 64, M / 128);        // (8, 64)

    cudaFuncSetAttribute(gemm_f16,
                         cudaFuncAttributeMaxDynamicSharedMemorySize,
                         GEMM_SMEM_BYTES);
    gemm_f16<<<ggrid, 256, GEMM_SMEM_BYTES>>>(x, Wq, bq, pq, M, D_, D_);
    gemm_f16<<<ggrid, 256, GEMM_SMEM_BYTES>>>(x, Wk, bk, pk, M, D_, D_);
    gemm_f16<<<ggrid, 256, GEMM_SMEM_BYTES>>>(x, Wv, bv, pv, M, D_, D_);

    cudaFuncSetAttribute(attn_f16_kernel,
                         cudaFuncAttributeMaxDynamicSharedMemorySize,
                         ATTN_SMEM_BYTES);
    attn_f16_kernel<<<dim3(N_ / 128, H_, B_), 256, ATTN_SMEM_BYTES>>>(
        pq, pk, pv, pbits, pa);

    gemm_f16<<<ggrid, 256, GEMM_SMEM_BYTES>>>(pa, Wo, bo, out, M, D_, D_);
}

// round 11
// speedup vs baseline: 5.9087x; 1.3715x over previous
#include <cuda_runtime.h>
#include <cuda_fp16.h>
#include <cstdint>

// Problem constants
#define B_  4
#define N_  2048
#define D_  512
#define H_  8
#define HD_ 64

// Scratch (allocation-free rule: __device__ globals)
static __device__ __half g_xh [B_ * N_ * D_];
static __device__ __half g_wqh[D_ * D_];
static __device__ __half g_wkh[D_ * D_];
static __device__ __half g_wvh[D_ * D_];
static __device__ __half g_woh[D_ * D_];
static __device__ __half g_q  [B_ * N_ * D_];
static __device__ __half g_k  [B_ * N_ * D_];
static __device__ __half g_v  [B_ * N_ * D_];
static __device__ __half g_ao [B_ * N_ * D_];
static __device__ unsigned g_adjbits[N_ * (N_ / 32)];   // 512 KB bitmask

// ---------------------------------------------------------------------------
// helpers
// ---------------------------------------------------------------------------
__device__ __forceinline__ unsigned h2pack(float a, float b) {
    __half2 h = __floats2half2_rn(a, b);   // lo = a, hi = b
    return *reinterpret_cast<unsigned*>(&h);
}

__device__ __forceinline__ void mma_f16(float c[4], const unsigned a[4],
                                        unsigned b0, unsigned b1)
{
    asm volatile(
        "mma.sync.aligned.m16n8k16.row.col.f32.f16.f16.f32 "
        "{%0,%1,%2,%3}, {%4,%5,%6,%7}, {%8,%9}, {%0,%1,%2,%3};\n"
        : "+f"(c[0]), "+f"(c[1]), "+f"(c[2]), "+f"(c[3])
        : "r"(a[0]), "r"(a[1]), "r"(a[2]), "r"(a[3]), "r"(b0), "r"(b1));
}

__device__ __forceinline__ void ldsm_x4(unsigned r[4], const __half* p) {
    unsigned addr = (unsigned)__cvta_generic_to_shared(p);
    asm volatile(
        "ldmatrix.sync.aligned.m8n8.x4.shared.b16 {%0,%1,%2,%3}, [%4];\n"
        : "=r"(r[0]), "=r"(r[1]), "=r"(r[2]), "=r"(r[3]) : "r"(addr));
}

__device__ __forceinline__ void ldsm_x4_t(unsigned r[4], const __half* p) {
    unsigned addr = (unsigned)__cvta_generic_to_shared(p);
    asm volatile(
        "ldmatrix.sync.aligned.m8n8.x4.trans.shared.b16 {%0,%1,%2,%3}, [%4];\n"
        : "=r"(r[0]), "=r"(r[1]), "=r"(r[2]), "=r"(r[3]) : "r"(addr));
}

__device__ __forceinline__ void cp_async16(__half* dst, const void* src) {
    unsigned d = (unsigned)__cvta_generic_to_shared(dst);
    asm volatile("cp.async.ca.shared.global [%0], [%1], 16;\n"
                 :: "r"(d), "l"(src));
}
__device__ __forceinline__ void cp_commit() {
    asm volatile("cp.async.commit_group;\n");
}
template<int NMAX> __device__ __forceinline__ void cp_wait() {
    asm volatile("cp.async.wait_group %0;\n" :: "n"(NMAX));
}

// epilogue store (float or half output)
__device__ __forceinline__ void store2(float* C, size_t off, float a, float b) {
    *(float2*)(C + off) = make_float2(a, b);
}
__device__ __forceinline__ void store2(__half* C, size_t off, float a, float b) {
    *(unsigned*)(C + off) = h2pack(a, b);
}

// ---------------------------------------------------------------------------
// f32 -> f16 convert (8 elems / thread)
// ---------------------------------------------------------------------------
__global__ __launch_bounds__(256) void cvt_f16_kernel(
    const float* __restrict__ in, __half* __restrict__ out)
{
    size_t idx = (size_t)(blockIdx.x * 256 + threadIdx.x) * 8;
    float4 a = *(const float4*)(in + idx);
    float4 b = *(const float4*)(in + idx + 4);
    uint4 r = make_uint4(h2pack(a.x, a.y), h2pack(a.z, a.w),
                         h2pack(b.x, b.y), h2pack(b.z, b.w));
    *(uint4*)(out + idx) = r;
}

// ---------------------------------------------------------------------------
// adj -> bitmask pack (adj is exactly 0.0f / 1.0f)
// ---------------------------------------------------------------------------
__global__ __launch_bounds__(256) void pack_adj_kernel(
    const float* __restrict__ adj, unsigned* __restrict__ bits)
{
    int idx = blockIdx.x * 256 + threadIdx.x;        // 131072 words
    const float* p = adj + (size_t)idx * 32;
    unsigned m = 0;
    #pragma unroll
    for (int j = 0; j < 32; j += 4) {
        float4 v = *(const float4*)(p + j);
        m |= (v.x != 0.f ? 1u : 0u) << (j + 0);
        m |= (v.y != 0.f ? 1u : 0u) << (j + 1);
        m |= (v.z != 0.f ? 1u : 0u) << (j + 2);
        m |= (v.w != 0.f ? 1u : 0u) << (j + 3);
    }
    bits[idx] = m;
}

// ---------------------------------------------------------------------------
// FP16 GEMM body: C[M,N] = A[M,K](f16) @ W[K,N](f16) + bias(f32), f32 accum.
// BM=128, BN=64, BK=32; 8 warps (4x2), warp tile 32x32.
// 4-stage cp.async pipeline. As[m][k] (LDSM), Bs[k][n] (trans LDSM).
// ---------------------------------------------------------------------------
#define GSTAGES 4
#define GA_PITCH 40                  // halves (80B = 5x16B)
#define GB_PITCH 72                  // halves (144B = 9x16B)
#define GA_H (128 * GA_PITCH)        // 5120
#define GB_H (32 * GB_PITCH)         // 2304
#define GEMM_SMEM_BYTES (GSTAGES * (GA_H + GB_H) * 2)   // 59392

template<typename OutT>
__device__ __forceinline__ void gemm_body(
    const __half* __restrict__ A, const __half* __restrict__ W,
    const float* __restrict__ bias, OutT* __restrict__ C,
    int M, int N, int K)
{
    extern __shared__ __half gsm[];
    __half* Abase = gsm;
    __half* Bbase = gsm + GSTAGES * GA_H;

    const int tid  = threadIdx.x;
    const int warp = tid >> 5;
    const int lane = tid & 31;
    const int wm = warp >> 1, wn = warp & 1;
    const int gid = lane >> 2, tig = lane & 3;
    const int rsel = (lane & 7) + ((lane >> 3) & 1) * 8;
    const int csel = (lane >> 4) * 8;

    const int rowBase = blockIdx.y * 128;
    const int colBase = blockIdx.x * 64;

    // cp.async chunk mapping
    const int aRow0 = tid >> 2;          // 0..63 (+64 second pass)
    const int aCh   = tid & 3;           // 4 x 16B per 32-half row
    const int bRow  = tid >> 3;          // 0..31
    const int bCh   = tid & 7;           // 8 x 16B per 64-half row

    float acc[2][4][4];
    #pragma unroll
    for (int mt = 0; mt < 2; mt++)
        #pragma unroll
        for (int nt = 0; nt < 4; nt++)
            #pragma unroll
            for (int i = 0; i < 4; i++) acc[mt][nt][i] = 0.f;

    auto load_stage = [&](int st, int k0) {
        __half* As = Abase + st * GA_H;
        __half* Bs = Bbase + st * GB_H;
        #pragma unroll
        for (int p = 0; p < 2; p++) {
            int r = aRow0 + p * 64;
            cp_async16(&As[r * GA_PITCH + aCh * 8],
                       A + (size_t)(rowBase + r) * K + k0 + aCh * 8);
        }
        cp_async16(&Bs[bRow * GB_PITCH + bCh * 8],
                   W + (size_t)(k0 + bRow) * N + colBase + bCh * 8);
    };

    const int iters = K >> 5;            // 16
    #pragma unroll
    for (int s = 0; s < GSTAGES - 1; s++) {
        load_stage(s, s * 32);
        cp_commit();
    }

    for (int it = 0; it < iters; it++) {
        cp_wait<GSTAGES - 2>();
        __syncthreads();

        int pre = it + GSTAGES - 1;
        if (pre < iters) load_stage(pre & (GSTAGES - 1), pre * 32);
        cp_commit();

        const int st = it & (GSTAGES - 1);
        const __half* As = Abase + st * GA_H;
        const __half* Bs = Bbase + st * GB_H;

        #pragma unroll
        for (int ks = 0; ks < 2; ks++) {
            unsigned a[2][4];
            #pragma unroll
            for (int mt = 0; mt < 2; mt++)
                ldsm_x4(a[mt], &As[(wm * 32 + mt * 16 + rsel) * GA_PITCH
                                   + ks * 16 + csel]);
            unsigned bb[2][4];
            #pragma unroll
            for (int np = 0; np < 2; np++)
                ldsm_x4_t(bb[np], &Bs[(ks * 16 + rsel) * GB_PITCH
                                      + wn * 32 + np * 16 + csel]);
            #pragma unroll
            for (int nt = 0; nt < 4; nt++)
                #pragma unroll
                for (int mt = 0; mt < 2; mt++)
                    mma_f16(acc[mt][nt], a[mt],
                            bb[nt >> 1][(nt & 1) * 2], bb[nt >> 1][(nt & 1) * 2 + 1]);
        }
    }

    #pragma unroll
    for (int mt = 0; mt < 2; mt++) {
        int r0 = rowBase + wm * 32 + mt * 16 + gid;
        #pragma unroll
        for (int nt = 0; nt < 4; nt++) {
            int col = colBase + wn * 32 + nt * 8 + tig * 2;
            float2 bv = *(const float2*)(bias + col);
            store2(C, (size_t)r0 * N + col,
                   acc[mt][nt][0] + bv.x, acc[mt][nt][1] + bv.y);
            store2(C, (size_t)(r0 + 8) * N + col,
                   acc[mt][nt][2] + bv.x, acc[mt][nt][3] + bv.y);
        }
    }
}

// fused QKV: blockIdx.z selects weight/bias/output
__global__ __launch_bounds__(256, 2) void gemm_qkv_kernel(
    const __half* __restrict__ A,
    const __half* __restrict__ Wq, const __half* __restrict__ Wk,
    const __half* __restrict__ Wv,
    const float* __restrict__ bq, const float* __restrict__ bk,
    const float* __restrict__ bv,
    __half* __restrict__ Cq, __half* __restrict__ Ck, __half* __restrict__ Cv,
    int M, int N, int K)
{
    const __half* W; const float* bias; __half* C;
    if (blockIdx.z == 0)      { W = Wq; bias = bq; C = Cq; }
    else if (blockIdx.z == 1) { W = Wk; bias = bk; C = Ck; }
    else                      { W = Wv; bias = bv; C = Cv; }
    gemm_body<__half>(A, W, bias, C, M, N, K);
}

__global__ __launch_bounds__(256, 2) void gemm_out_kernel(
    const __half* __restrict__ A, const __half* __restrict__ W,
    const float* __restrict__ bias, float* __restrict__ C,
    int M, int N, int K)
{
    gemm_body<float>(A, W, bias, C, M, N, K);
}

// ---------------------------------------------------------------------------
// Fused masked flash attention, fp16 mma, warp-local softmax, P in registers.
// q-tile=128 (8 warps x 16 rows), k-tile=64, 3-stage cp.async K/V pipeline,
// 1 syncthreads per k-tile. adj as bitmask from gmem/L2.
// KS[key][d] (normal LDSM -> B of S), VS[key][d] (trans LDSM -> B of PV).
// ---------------------------------------------------------------------------
#define KV_PITCH 72                            // halves (144B = 9x16B)
#define KV_TILE_H (64 * KV_PITCH)              // 4608
#define KV_STAGE_H (2 * KV_TILE_H)             // K+V = 9216
#define ASTAGES 3
#define QS_OFF (ASTAGES * KV_STAGE_H)          // 27648
#define ATTN_SMEM_BYTES ((QS_OFF + 128 * KV_PITCH) * 2)   // 73728

__global__ __launch_bounds__(256, 2) void attn_f16_kernel(
    const __half* __restrict__ q, const __half* __restrict__ k,
    const __half* __restrict__ v, const unsigned* __restrict__ mbits,
    __half* __restrict__ o)
{
    extern __shared__ __half smh[];
    __half* QS = smh + QS_OFF;

    const int tid  = threadIdx.x;
    const int warp = tid >> 5;
    const int lane = tid & 31;
    const int gid = lane >> 2, tig = lane & 3;
    const int rsel = (lane & 7) + ((lane >> 3) & 1) * 8;
    const int csel = (lane >> 4) * 8;

    const int q0 = blockIdx.x * 128;
    const int h  = blockIdx.y;
    const int b  = blockIdx.z;
    const int row0 = warp * 16;

    const __half* qbase = q + (size_t)b * N_ * D_ + h * HD_;
    const __half* kbase = k + (size_t)b * N_ * D_ + h * HD_;
    const __half* vbase = v + (size_t)b * N_ * D_ + h * HD_;

    // cp.async mapping for one K/V stage: 1024 x 16B chunks, 4 per thread
    auto load_kv = [&](int st, int k0) {
        __half* KS = smh + st * KV_STAGE_H;
        __half* VS = KS + KV_TILE_H;
        #pragma unroll
        for (int p = 0; p < 4; p++) {
            int idx = tid + p * 256;             // 0..1023
            int mat = idx >> 9;                  // 0 = K, 1 = V
            int rem = idx & 511;
            int r = rem >> 3, ch = rem & 7;
            const __half* src = (mat ? vbase : kbase)
                                + (size_t)(k0 + r) * D_ + ch * 8;
            __half* dst = (mat ? VS : KS) + r * KV_PITCH + ch * 8;
            cp_async16(dst, src);
        }
    };

    // kick off first two K/V stages
    load_kv(0, 0);  cp_commit();
    load_kv(1, 64); cp_commit();

    // stage Q (scaled by 0.125 in half2 — exact) into QS, hoist frags
    const __half2 qscale = __float2half2_rn(0.125f);
    #pragma unroll
    for (int p = 0; p < 4; p++) {
        int idx = tid + p * 256;                 // 0..1023
        int r = idx >> 3, ch = idx & 7;
        uint4 t = *(const uint4*)(qbase + (size_t)(q0 + r) * D_ + ch * 8);
        __half2* th = (__half2*)&t;
        #pragma unroll
        for (int j = 0; j < 4; j++) th[j] = __hmul2(th[j], qscale);
        *(uint4*)&QS[r * KV_PITCH + ch * 8] = t;
    }
    __syncthreads();

    unsigned qf[4][4];
    #pragma unroll
    for (int ks = 0; ks < 4; ks++)
        ldsm_x4(qf[ks], &QS[(row0 + rsel) * KV_PITCH + ks * 16 + csel]);

    float O[8][4];
    #pragma unroll
    for (int nt = 0; nt < 8; nt++)
        #pragma unroll
        for (int i = 0; i < 4; i++) O[nt][i] = 0.f;
    float mA = -1e30f, mB = -1e30f, lA = 0.f, lB = 0.f;

    const int rowA = q0 + row0 + gid;
    const int rowB = rowA + 8;
    const unsigned* mrowA = mbits + (size_t)rowA * (N_ / 32);
    const unsigned* mrowB = mbits + (size_t)rowB * (N_ / 32);

    const int iters = N_ / 64;                   // 32
    for (int it = 0; it < iters; it++) {
        const int k0 = it * 64;

        cp_wait<ASTAGES - 2>();
        __syncthreads();

        int pre = it + ASTAGES - 1;
        if (pre < iters) load_kv(pre % ASTAGES, pre * 64);
        cp_commit();

        // mask bits (L2-resident)
        uint2 ma2 = *(const uint2*)(mrowA + (k0 >> 5));
        uint2 mb2 = *(const uint2*)(mrowB + (k0 >> 5));
        uint64_t maskA = (uint64_t)ma2.x | ((uint64_t)ma2.y << 32);
        uint64_t maskB = (uint64_t)mb2.x | ((uint64_t)mb2.y << 32);

        const int st = it % ASTAGES;
        const __half* KS = smh + st * KV_STAGE_H;
        const __half* VS = KS + KV_TILE_H;

        // ---- S = Q @ K^T ----
        float s[8][4];
        #pragma unroll
        for (int nt = 0; nt < 8; nt++)
            #pragma unroll
            for (int i = 0; i < 4; i++) s[nt][i] = 0.f;

        #pragma unroll
        for (int ks = 0; ks < 4; ks++) {
            unsigned kb[4][4];
            #pragma unroll
            for (int np = 0; np < 4; np++)
                ldsm_x4(kb[np], &KS[(np * 16 + rsel) * KV_PITCH + ks * 16 + csel]);
            #pragma unroll
            for (int nt = 0; nt < 8; nt++)
                mma_f16(s[nt], qf[ks],
                        kb[nt >> 1][nt & 1], kb[nt >> 1][2 + (nt & 1)]);
        }

        // ---- mask (s + (-1e9), same arithmetic as reference) ----
        #pragma unroll
        for (int nt = 0; nt < 8; nt++) {
            int c = nt * 8 + tig * 2;
            if (!((maskA >> c) & 1))       s[nt][0] -= 1e9f;
            if (!((maskA >> (c + 1)) & 1)) s[nt][1] -= 1e9f;
            if (!((maskB >> c) & 1))       s[nt][2] -= 1e9f;
            if (!((maskB >> (c + 1)) & 1)) s[nt][3] -= 1e9f;
        }

        // ---- warp-local online softmax ----
        float mxA = -1e30f, mxB = -1e30f;
        #pragma unroll
        for (int nt = 0; nt < 8; nt++) {
            mxA = fmaxf(mxA, fmaxf(s[nt][0], s[nt][1]));
            mxB = fmaxf(mxB, fmaxf(s[nt][2], s[nt][3]));
        }
        mxA = fmaxf(mxA, __shfl_xor_sync(0xffffffffu, mxA, 1));
        mxA = fmaxf(mxA, __shfl_xor_sync(0xffffffffu, mxA, 2));
        mxB = fmaxf(mxB, __shfl_xor_sync(0xffffffffu, mxB, 1));
        mxB = fmaxf(mxB, __shfl_xor_sync(0xffffffffu, mxB, 2));

        float mnA = fmaxf(mA, mxA), mnB = fmaxf(mB, mxB);
        float alA = __expf(mA - mnA), alB = __expf(mB - mnB);
        mA = mnA; mB = mnB;

        unsigned ph[8][2];
        float rsA = 0.f, rsB = 0.f;
        #pragma unroll
        for (int nt = 0; nt < 8; nt++) {
            float p0 = __expf(s[nt][0] - mnA);
            float p1 = __expf(s[nt][1] - mnA);
            float p2 = __expf(s[nt][2] - mnB);
            float p3 = __expf(s[nt][3] - mnB);
            rsA += p0 + p1;
            rsB += p2 + p3;
            ph[nt][0] = h2pack(p0, p1);
            ph[nt][1] = h2pack(p2, p3);
            O[nt][0] *= alA; O[nt][1] *= alA;
            O[nt][2] *= alB; O[nt][3] *= alB;
        }
        rsA += __shfl_xor_sync(0xffffffffu, rsA, 1);
        rsA += __shfl_xor_sync(0xffffffffu, rsA, 2);
        rsB += __shfl_xor_sync(0xffffffffu, rsB, 1);
        rsB += __shfl_xor_sync(0xffffffffu, rsB, 2);
        lA = lA * alA + rsA;
        lB = lB * alB + rsB;

        // ---- O += P @ V (P straight from registers) ----
        #pragma unroll
        for (int ks = 0; ks < 4; ks++) {
            unsigned vb[4][4];
            #pragma unroll
            for (int dp = 0; dp < 4; dp++)
                ldsm_x4_t(vb[dp], &VS[(ks * 16 + rsel) * KV_PITCH + dp * 16 + csel]);
            unsigned pa[4] = { ph[2 * ks][0], ph[2 * ks][1],
                               ph[2 * ks + 1][0], ph[2 * ks + 1][1] };
            #pragma unroll
            for (int nt = 0; nt < 8; nt++)
                mma_f16(O[nt], pa,
                        vb[nt >> 1][(nt & 1) * 2], vb[nt >> 1][(nt & 1) * 2 + 1]);
        }
    }

    // Finalize -> fp16 attention output
    float invA = 1.0f / lA, invB = 1.0f / lB;
    __half* obase = o + (size_t)b * N_ * D_ + h * HD_;
    #pragma unroll
    for (int nt = 0; nt < 8; nt++) {
        int c = nt * 8 + tig * 2;
        *(unsigned*)(obase + (size_t)rowA * D_ + c) =
            h2pack(O[nt][0] * invA, O[nt][1] * invA);
        *(unsigned*)(obase + (size_t)rowB * D_ + c) =
            h2pack(O[nt][2] * invB, O[nt][3] * invB);
    }
}

// ---------------------------------------------------------------------------
extern "C" void kernel_launch(void* const* d_in, const int* in_sizes, int n_in,
                              void* d_out, int out_size)
{
    const float* x   = (const float*)d_in[0];
    const float* adj = (const float*)d_in[1];
    const float* Wq  = (const float*)d_in[2];
    const float* bq  = (const float*)d_in[3];
    const float* Wk  = (const float*)d_in[4];
    const float* bk  = (const float*)d_in[5];
    const float* Wv  = (const float*)d_in[6];
    const float* bv  = (const float*)d_in[7];
    const float* Wo  = (const float*)d_in[8];
    const float* bo  = (const float*)d_in[9];
    float* out = (float*)d_out;

    __half *pxh, *pwqh, *pwkh, *pwvh, *pwoh, *pq, *pk, *pv, *pa;
    unsigned* pbits;
    cudaGetSymbolAddress((void**)&pxh,  g_xh);
    cudaGetSymbolAddress((void**)&pwqh, g_wqh);
    cudaGetSymbolAddress((void**)&pwkh, g_wkh);
    cudaGetSymbolAddress((void**)&pwvh, g_wvh);
    cudaGetSymbolAddress((void**)&pwoh, g_woh);
    cudaGetSymbolAddress((void**)&pq,   g_q);
    cudaGetSymbolAddress((void**)&pk,   g_k);
    cudaGetSymbolAddress((void**)&pv,   g_v);
    cudaGetSymbolAddress((void**)&pa,   g_ao);
    cudaGetSymbolAddress((void**)&pbits, g_adjbits);

    pack_adj_kernel<<<(N_ * (N_ / 32)) / 256, 256>>>(adj, pbits);
    cvt_f16_kernel<<<(B_ * N_ * D_) / 2048, 256>>>(x,  pxh);
    cvt_f16_kernel<<<(D_ * D_) / 2048, 256>>>(Wq, pwqh);
    cvt_f16_kernel<<<(D_ * D_) / 2048, 256>>>(Wk, pwkh);
    cvt_f16_kernel<<<(D_ * D_) / 2048, 256>>>(Wv, pwvh);
    cvt_f16_kernel<<<(D_ * D_) / 2048, 256>>>(Wo, pwoh);

    const int M = B_ * N_;                    // 8192
    dim3 qkvGrid(D_ / 64, M / 128, 3);        // (8, 64, 3)
    dim3 oGrid(D_ / 64, M / 128);             // (8, 64)

    cudaFuncSetAttribute(gemm_qkv_kernel,
                         cudaFuncAttributeMaxDynamicSharedMemorySize,
                         GEMM_SMEM_BYTES);
    cudaFuncSetAttribute(gemm_out_kernel,
                         cudaFuncAttributeMaxDynamicSharedMemorySize,
                         GEMM_SMEM_BYTES);
    cudaFuncSetAttribute(attn_f16_kernel,
                         cudaFuncAttributeMaxDynamicSharedMemorySize,
                         ATTN_SMEM_BYTES);

    gemm_qkv_kernel<<<qkvGrid, 256, GEMM_SMEM_BYTES>>>(
        pxh, pwqh, pwkh, pwvh, bq, bk, bv, pq, pk, pv, M, D_, D_);

    attn_f16_kernel<<<dim3(N_ / 128, H_, B_), 256, ATTN_SMEM_BYTES>>>(
        pq, pk, pv, pbits, pa);

    gemm_out_kernel<<<oGrid, 256, GEMM_SMEM_BYTES>>>(
        pa, pwoh, bo, out, M, D_, D_);
}

// round 12
// speedup vs baseline: 6.8440x; 1.1583x over previous
#include <cuda_runtime.h>
#include <cuda_fp16.h>
#include <cstdint>

// Problem constants
#define B_  4
#define N_  2048
#define D_  512
#define H_  8
#define HD_ 64

// Q pre-scale: 1/sqrt(HD) * log2(e), applied to Wq/bq in fp32 before rounding
#define QW_SCALE 0.1803368801111137f
// mask constant in log2 domain: 1e9 * log2(e)
#define MASKC 1.4426950408e9f

// Scratch (allocation-free rule: __device__ globals)
static __device__ __half g_xh [B_ * N_ * D_];
static __device__ __half g_wqh[D_ * D_];
static __device__ __half g_wkh[D_ * D_];
static __device__ __half g_wvh[D_ * D_];
static __device__ __half g_woh[D_ * D_];
static __device__ __half g_q  [B_ * N_ * D_];
static __device__ __half g_k  [B_ * N_ * D_];
static __device__ __half g_v  [B_ * N_ * D_];
static __device__ __half g_ao [B_ * N_ * D_];
static __device__ unsigned g_adjbits[N_ * (N_ / 32)];   // 512 KB bitmask

// ---------------------------------------------------------------------------
// helpers
// ---------------------------------------------------------------------------
__device__ __forceinline__ unsigned h2pack(float a, float b) {
    __half2 h = __floats2half2_rn(a, b);
    return *reinterpret_cast<unsigned*>(&h);
}

__device__ __forceinline__ float ex2f(float x) {
    float r;
    asm("ex2.approx.ftz.f32 %0, %1;" : "=f"(r) : "f"(x));
    return r;
}

__device__ __forceinline__ void mma_f16(float c[4], const unsigned a[4],
                                        unsigned b0, unsigned b1)
{
    asm volatile(
        "mma.sync.aligned.m16n8k16.row.col.f32.f16.f16.f32 "
        "{%0,%1,%2,%3}, {%4,%5,%6,%7}, {%8,%9}, {%0,%1,%2,%3};\n"
        : "+f"(c[0]), "+f"(c[1]), "+f"(c[2]), "+f"(c[3])
        : "r"(a[0]), "r"(a[1]), "r"(a[2]), "r"(a[3]), "r"(b0), "r"(b1));
}

__device__ __forceinline__ void ldsm_x4(unsigned r[4], const __half* p) {
    unsigned addr = (unsigned)__cvta_generic_to_shared(p);
    asm volatile(
        "ldmatrix.sync.aligned.m8n8.x4.shared.b16 {%0,%1,%2,%3}, [%4];\n"
        : "=r"(r[0]), "=r"(r[1]), "=r"(r[2]), "=r"(r[3]) : "r"(addr));
}

__device__ __forceinline__ void ldsm_x4_t(unsigned r[4], const __half* p) {
    unsigned addr = (unsigned)__cvta_generic_to_shared(p);
    asm volatile(
        "ldmatrix.sync.aligned.m8n8.x4.trans.shared.b16 {%0,%1,%2,%3}, [%4];\n"
        : "=r"(r[0]), "=r"(r[1]), "=r"(r[2]), "=r"(r[3]) : "r"(addr));
}

__device__ __forceinline__ void cp_async16(__half* dst, const void* src) {
    unsigned d = (unsigned)__cvta_generic_to_shared(dst);
    asm volatile("cp.async.ca.shared.global [%0], [%1], 16;\n"
                 :: "r"(d), "l"(src));
}
__device__ __forceinline__ void cp_commit() {
    asm volatile("cp.async.commit_group;\n");
}
template<int NMAX> __device__ __forceinline__ void cp_wait() {
    asm volatile("cp.async.wait_group %0;\n" :: "n"(NMAX));
}

__device__ __forceinline__ void store2(float* C, size_t off, float a, float b) {
    *(float2*)(C + off) = make_float2(a, b);
}
__device__ __forceinline__ void store2(__half* C, size_t off, float a, float b) {
    *(unsigned*)(C + off) = h2pack(a, b);
}

// ---------------------------------------------------------------------------
// Fused prologue: adj bit-pack + all f32->f16 conversions (Wq pre-scaled).
// Block ranges:
//   [0,512)      : pack adj (131072 words)
//   [512,2560)   : cvt x        (4,194,304 elems, 2048 per block)
//   [2560,2688)  : cvt Wq * QW_SCALE
//   [2688,2816)  : cvt Wk
//   [2816,2944)  : cvt Wv
//   [2944,3072)  : cvt Wo
// ---------------------------------------------------------------------------
__global__ __launch_bounds__(256) void prep_kernel(
    const float* __restrict__ adj, unsigned* __restrict__ bits,
    const float* __restrict__ x,  __half* __restrict__ xh,
    const float* __restrict__ Wq, __half* __restrict__ wqh,
    const float* __restrict__ Wk, __half* __restrict__ wkh,
    const float* __restrict__ Wv, __half* __restrict__ wvh,
    const float* __restrict__ Wo, __half* __restrict__ woh)
{
    const int blk = blockIdx.x;
    const int tid = threadIdx.x;

    if (blk < 512) {
        int idx = blk * 256 + tid;
        const float* p = adj + (size_t)idx * 32;
        unsigned m = 0;
        #pragma unroll
        for (int j = 0; j < 32; j += 4) {
            float4 v = *(const float4*)(p + j);
            m |= (v.x != 0.f ? 1u : 0u) << (j + 0);
            m |= (v.y != 0.f ? 1u : 0u) << (j + 1);
            m |= (v.z != 0.f ? 1u : 0u) << (j + 2);
            m |= (v.w != 0.f ? 1u : 0u) << (j + 3);
        }
        bits[idx] = m;
        return;
    }

    const float* in; __half* out; int rb; float scale = 1.0f;
    if (blk < 2560)      { in = x;  out = xh;  rb = blk - 512; }
    else if (blk < 2688) { in = Wq; out = wqh; rb = blk - 2560; scale = QW_SCALE; }
    else if (blk < 2816) { in = Wk; out = wkh; rb = blk - 2688; }
    else if (blk < 2944) { in = Wv; out = wvh; rb = blk - 2816; }
    else                 { in = Wo; out = woh; rb = blk - 2944; }

    size_t idx = ((size_t)rb * 256 + tid) * 8;
    float4 a = *(const float4*)(in + idx);
    float4 b = *(const float4*)(in + idx + 4);
    uint4 r = make_uint4(h2pack(a.x * scale, a.y * scale),
                         h2pack(a.z * scale, a.w * scale),
                         h2pack(b.x * scale, b.y * scale),
                         h2pack(b.z * scale, b.w * scale));
    *(uint4*)(out + idx) = r;
}

// ---------------------------------------------------------------------------
// FP16 GEMM body: C[M,N] = A[M,K](f16) @ W[K,N](f16) + bias(f32)*bscale.
// BM=128, BN=128, BK=32; 8 warps (4x2), warp tile 32x64.
// 4-stage cp.async pipeline. As[m][k] (LDSM), Bs[k][n] (trans LDSM).
// ---------------------------------------------------------------------------
#define GSTAGES 4
#define GA_PITCH 40                   // halves (80B = 5x16B)
#define GB_PITCH 136                  // halves (272B = 17x16B)
#define GA_H (128 * GA_PITCH)         // 5120
#define GB_H (32 * GB_PITCH)          // 4352
#define GEMM_SMEM_BYTES (GSTAGES * (GA_H + GB_H) * 2)   // 75776

template<typename OutT>
__device__ __forceinline__ void gemm_body(
    const __half* __restrict__ A, const __half* __restrict__ W,
    const float* __restrict__ bias, float bscale, OutT* __restrict__ C,
    int M, int N, int K)
{
    extern __shared__ __half gsm[];
    __half* Abase = gsm;
    __half* Bbase = gsm + GSTAGES * GA_H;

    const int tid  = threadIdx.x;
    const int warp = tid >> 5;
    const int lane = tid & 31;
    const int wm = warp >> 1, wn = warp & 1;
    const int gid = lane >> 2, tig = lane & 3;
    const int rsel = (lane & 7) + ((lane >> 3) & 1) * 8;
    const int csel = (lane >> 4) * 8;

    const int rowBase = blockIdx.y * 128;
    const int colBase = blockIdx.x * 128;

    const int aRow0 = tid >> 2;          // 0..63 (2 passes of 64)
    const int aCh   = tid & 3;
    const int bRow0 = tid >> 4;          // 0..15 (2 passes of 16)
    const int bCh   = tid & 15;

    float acc[2][8][4];
    #pragma unroll
    for (int mt = 0; mt < 2; mt++)
        #pragma unroll
        for (int nt = 0; nt < 8; nt++)
            #pragma unroll
            for (int i = 0; i < 4; i++) acc[mt][nt][i] = 0.f;

    auto load_stage = [&](int st, int k0) {
        __half* As = Abase + st * GA_H;
        __half* Bs = Bbase + st * GB_H;
        #pragma unroll
        for (int p = 0; p < 2; p++) {
            int r = aRow0 + p * 64;
            cp_async16(&As[r * GA_PITCH + aCh * 8],
                       A + (size_t)(rowBase + r) * K + k0 + aCh * 8);
        }
        #pragma unroll
        for (int p = 0; p < 2; p++) {
            int r = bRow0 + p * 16;
            cp_async16(&Bs[r * GB_PITCH + bCh * 8],
                       W + (size_t)(k0 + r) * N + colBase + bCh * 8);
        }
    };

    const int iters = K >> 5;            // 16
    #pragma unroll
    for (int s = 0; s < GSTAGES - 1; s++) {
        load_stage(s, s * 32);
        cp_commit();
    }

    for (int it = 0; it < iters; it++) {
        cp_wait<GSTAGES - 2>();
        __syncthreads();

        int pre = it + GSTAGES - 1;
        if (pre < iters) load_stage(pre & (GSTAGES - 1), pre * 32);
        cp_commit();

        const int st = it & (GSTAGES - 1);
        const __half* As = Abase + st * GA_H;
        const __half* Bs = Bbase + st * GB_H;

        #pragma unroll
        for (int ks = 0; ks < 2; ks++) {
            unsigned a[2][4];
            #pragma unroll
            for (int mt = 0; mt < 2; mt++)
                ldsm_x4(a[mt], &As[(wm * 32 + mt * 16 + rsel) * GA_PITCH
                                   + ks * 16 + csel]);
            unsigned bb[4][4];
            #pragma unroll
            for (int np = 0; np < 4; np++)
                ldsm_x4_t(bb[np], &Bs[(ks * 16 + rsel) * GB_PITCH
                                      + wn * 64 + np * 16 + csel]);
            #pragma unroll
            for (int nt = 0; nt < 8; nt++)
                #pragma unroll
                for (int mt = 0; mt < 2; mt++)
                    mma_f16(acc[mt][nt], a[mt],
                            bb[nt >> 1][(nt & 1) * 2], bb[nt >> 1][(nt & 1) * 2 + 1]);
        }
    }

    #pragma unroll
    for (int mt = 0; mt < 2; mt++) {
        int r0 = rowBase + wm * 32 + mt * 16 + gid;
        #pragma unroll
        for (int nt = 0; nt < 8; nt++) {
            int col = colBase + wn * 64 + nt * 8 + tig * 2;
            float2 bv = *(const float2*)(bias + col);
            store2(C, (size_t)r0 * N + col,
                   acc[mt][nt][0] + bv.x * bscale, acc[mt][nt][1] + bv.y * bscale);
            store2(C, (size_t)(r0 + 8) * N + col,
                   acc[mt][nt][2] + bv.x * bscale, acc[mt][nt][3] + bv.y * bscale);
        }
    }
}

// fused QKV: blockIdx.z selects weight/bias/output; Q path has scaled bias
__global__ __launch_bounds__(256, 2) void gemm_qkv_kernel(
    const __half* __restrict__ A,
    const __half* __restrict__ Wq, const __half* __restrict__ Wk,
    const __half* __restrict__ Wv,
    const float* __restrict__ bq, const float* __restrict__ bk,
    const float* __restrict__ bv,
    __half* __restrict__ Cq, __half* __restrict__ Ck, __half* __restrict__ Cv,
    int M, int N, int K)
{
    const __half* W; const float* bias; __half* C; float bscale = 1.0f;
    if (blockIdx.z == 0)      { W = Wq; bias = bq; C = Cq; bscale = QW_SCALE; }
    else if (blockIdx.z == 1) { W = Wk; bias = bk; C = Ck; }
    else                      { W = Wv; bias = bv; C = Cv; }
    gemm_body<__half>(A, W, bias, bscale, C, M, N, K);
}

__global__ __launch_bounds__(256, 2) void gemm_out_kernel(
    const __half* __restrict__ A, const __half* __restrict__ W,
    const float* __restrict__ bias, float* __restrict__ C,
    int M, int N, int K)
{
    gemm_body<float>(A, W, bias, 1.0f, C, M, N, K);
}

// ---------------------------------------------------------------------------
// Fused masked flash attention, fp16 mma, warp-local softmax, P in registers.
// Q pre-scaled by 1/sqrt(HD)*log2(e) -> softmax uses raw ex2.
// q-tile=128 (8 warps x 16 rows), k-tile=64, 4-stage cp.async K/V pipeline.
// ---------------------------------------------------------------------------
#define KV_PITCH 72                            // halves (144B = 9x16B)
#define KV_TILE_H (64 * KV_PITCH)              // 4608
#define KV_STAGE_H (2 * KV_TILE_H)             // 9216
#define ASTAGES 4
#define QS_OFF (ASTAGES * KV_STAGE_H)          // 36864
#define ATTN_SMEM_BYTES ((QS_OFF + 128 * KV_PITCH) * 2)   // 92160

__global__ __launch_bounds__(256, 2) void attn_f16_kernel(
    const __half* __restrict__ q, const __half* __restrict__ k,
    const __half* __restrict__ v, const unsigned* __restrict__ mbits,
    __half* __restrict__ o)
{
    extern __shared__ __half smh[];
    __half* QS = smh + QS_OFF;

    const int tid  = threadIdx.x;
    const int warp = tid >> 5;
    const int lane = tid & 31;
    const int gid = lane >> 2, tig = lane & 3;
    const int rsel = (lane & 7) + ((lane >> 3) & 1) * 8;
    const int csel = (lane >> 4) * 8;

    const int q0 = blockIdx.x * 128;
    const int h  = blockIdx.y;
    const int b  = blockIdx.z;
    const int row0 = warp * 16;

    const __half* qbase = q + (size_t)b * N_ * D_ + h * HD_;
    const __half* kbase = k + (size_t)b * N_ * D_ + h * HD_;
    const __half* vbase = v + (size_t)b * N_ * D_ + h * HD_;

    auto load_kv = [&](int st, int k0) {
        __half* KS = smh + st * KV_STAGE_H;
        __half* VS = KS + KV_TILE_H;
        #pragma unroll
        for (int p = 0; p < 4; p++) {
            int idx = tid + p * 256;             // 0..1023
            int mat = idx >> 9;                  // 0 = K, 1 = V
            int rem = idx & 511;
            int r = rem >> 3, ch = rem & 7;
            const __half* src = (mat ? vbase : kbase)
                                + (size_t)(k0 + r) * D_ + ch * 8;
            __half* dst = (mat ? VS : KS) + r * KV_PITCH + ch * 8;
            cp_async16(dst, src);
        }
    };

    #pragma unroll
    for (int s = 0; s < ASTAGES - 1; s++) {
        load_kv(s, s * 64);
        cp_commit();
    }

    // stage Q (already pre-scaled) into QS, hoist frags
    #pragma unroll
    for (int p = 0; p < 4; p++) {
        int idx = tid + p * 256;                 // 0..1023
        int r = idx >> 3, ch = idx & 7;
        *(uint4*)&QS[r * KV_PITCH + ch * 8] =
            *(const uint4*)(qbase + (size_t)(q0 + r) * D_ + ch * 8);
    }
    __syncthreads();

    unsigned qf[4][4];
    #pragma unroll
    for (int ks = 0; ks < 4; ks++)
        ldsm_x4(qf[ks], &QS[(row0 + rsel) * KV_PITCH + ks * 16 + csel]);

    float O[8][4];
    #pragma unroll
    for (int nt = 0; nt < 8; nt++)
        #pragma unroll
        for (int i = 0; i < 4; i++) O[nt][i] = 0.f;
    float mA = -1e30f, mB = -1e30f, lA = 0.f, lB = 0.f;

    const int rowA = q0 + row0 + gid;
    const int rowB = rowA + 8;
    const unsigned* mrowA = mbits + (size_t)rowA * (N_ / 32);
    const unsigned* mrowB = mbits + (size_t)rowB * (N_ / 32);

    const int iters = N_ / 64;                   // 32
    for (int it = 0; it < iters; it++) {
        const int k0 = it * 64;

        cp_wait<ASTAGES - 2>();
        __syncthreads();

        int pre = it + ASTAGES - 1;
        if (pre < iters) load_kv(pre & (ASTAGES - 1), pre * 64);
        cp_commit();

        uint2 ma2 = *(const uint2*)(mrowA + (k0 >> 5));
        uint2 mb2 = *(const uint2*)(mrowB + (k0 >> 5));
        uint64_t maskA = (uint64_t)ma2.x | ((uint64_t)ma2.y << 32);
        uint64_t maskB = (uint64_t)mb2.x | ((uint64_t)mb2.y << 32);

        const int st = it & (ASTAGES - 1);
        const __half* KS = smh + st * KV_STAGE_H;
        const __half* VS = KS + KV_TILE_H;

        // ---- S = Q @ K^T (log2-domain logits) ----
        float s[8][4];
        #pragma unroll
        for (int nt = 0; nt < 8; nt++)
            #pragma unroll
            for (int i = 0; i < 4; i++) s[nt][i] = 0.f;

        #pragma unroll
        for (int ks = 0; ks < 4; ks++) {
            unsigned kb[4][4];
            #pragma unroll
            for (int np = 0; np < 4; np++)
                ldsm_x4(kb[np], &KS[(np * 16 + rsel) * KV_PITCH + ks * 16 + csel]);
            #pragma unroll
            for (int nt = 0; nt < 8; nt++)
                mma_f16(s[nt], qf[ks],
                        kb[nt >> 1][nt & 1], kb[nt >> 1][2 + (nt & 1)]);
        }

        // ---- mask ----
        #pragma unroll
        for (int nt = 0; nt < 8; nt++) {
            int c = nt * 8 + tig * 2;
            if (!((maskA >> c) & 1))       s[nt][0] -= MASKC;
            if (!((maskA >> (c + 1)) & 1)) s[nt][1] -= MASKC;
            if (!((maskB >> c) & 1))       s[nt][2] -= MASKC;
            if (!((maskB >> (c + 1)) & 1)) s[nt][3] -= MASKC;
        }

        // ---- warp-local online softmax (base-2) ----
        float mxA = -1e30f, mxB = -1e30f;
        #pragma unroll
        for (int nt = 0; nt < 8; nt++) {
            mxA = fmaxf(mxA, fmaxf(s[nt][0], s[nt][1]));
            mxB = fmaxf(mxB, fmaxf(s[nt][2], s[nt][3]));
        }
        mxA = fmaxf(mxA, __shfl_xor_sync(0xffffffffu, mxA, 1));
        mxA = fmaxf(mxA, __shfl_xor_sync(0xffffffffu, mxA, 2));
        mxB = fmaxf(mxB, __shfl_xor_sync(0xffffffffu, mxB, 1));
        mxB = fmaxf(mxB, __shfl_xor_sync(0xffffffffu, mxB, 2));

        float mnA = fmaxf(mA, mxA), mnB = fmaxf(mB, mxB);
        float alA = ex2f(mA - mnA), alB = ex2f(mB - mnB);
        mA = mnA; mB = mnB;

        unsigned ph[8][2];
        float rsA = 0.f, rsB = 0.f;
        #pragma unroll
        for (int nt = 0; nt < 8; nt++) {
            float p0 = ex2f(s[nt][0] - mnA);
            float p1 = ex2f(s[nt][1] - mnA);
            float p2 = ex2f(s[nt][2] - mnB);
            float p3 = ex2f(s[nt][3] - mnB);
            rsA += p0 + p1;
            rsB += p2 + p3;
            ph[nt][0] = h2pack(p0, p1);
            ph[nt][1] = h2pack(p2, p3);
            O[nt][0] *= alA; O[nt][1] *= alA;
            O[nt][2] *= alB; O[nt][3] *= alB;
        }
        rsA += __shfl_xor_sync(0xffffffffu, rsA, 1);
        rsA += __shfl_xor_sync(0xffffffffu, rsA, 2);
        rsB += __shfl_xor_sync(0xffffffffu, rsB, 1);
        rsB += __shfl_xor_sync(0xffffffffu, rsB, 2);
        lA = lA * alA + rsA;
        lB = lB * alB + rsB;

        // ---- O += P @ V (P straight from registers) ----
        #pragma unroll
        for (int ks = 0; ks < 4; ks++) {
            unsigned vb[4][4];
            #pragma unroll
            for (int dp = 0; dp < 4; dp++)
                ldsm_x4_t(vb[dp], &VS[(ks * 16 + rsel) * KV_PITCH + dp * 16 + csel]);
            unsigned pa[4] = { ph[2 * ks][0], ph[2 * ks][1],
                               ph[2 * ks + 1][0], ph[2 * ks + 1][1] };
            #pragma unroll
            for (int nt = 0; nt < 8; nt++)
                mma_f16(O[nt], pa,
                        vb[nt >> 1][(nt & 1) * 2], vb[nt >> 1][(nt & 1) * 2 + 1]);
        }
    }

    // Finalize -> fp16 attention output
    float invA = 1.0f / lA, invB = 1.0f / lB;
    __half* obase = o + (size_t)b * N_ * D_ + h * HD_;
    #pragma unroll
    for (int nt = 0; nt < 8; nt++) {
        int c = nt * 8 + tig * 2;
        *(unsigned*)(obase + (size_t)rowA * D_ + c) =
            h2pack(O[nt][0] * invA, O[nt][1] * invA);
        *(unsigned*)(obase + (size_t)rowB * D_ + c) =
            h2pack(O[nt][2] * invB, O[nt][3] * invB);
    }
}

// ---------------------------------------------------------------------------
extern "C" void kernel_launch(void* const* d_in, const int* in_sizes, int n_in,
                              void* d_out, int out_size)
{
    const float* x   = (const float*)d_in[0];
    const float* adj = (const float*)d_in[1];
    const float* Wq  = (const float*)d_in[2];
    const float* bq  = (const float*)d_in[3];
    const float* Wk  = (const float*)d_in[4];
    const float* bk  = (const float*)d_in[5];
    const float* Wv  = (const float*)d_in[6];
    const float* bv  = (const float*)d_in[7];
    const float* Wo  = (const float*)d_in[8];
    const float* bo  = (const float*)d_in[9];
    float* out = (float*)d_out;

    __half *pxh, *pwqh, *pwkh, *pwvh, *pwoh, *pq, *pk, *pv, *pa;
    unsigned* pbits;
    cudaGetSymbolAddress((void**)&pxh,  g_xh);
    cudaGetSymbolAddress((void**)&pwqh, g_wqh);
    cudaGetSymbolAddress((void**)&pwkh, g_wkh);
    cudaGetSymbolAddress((void**)&pwvh, g_wvh);
    cudaGetSymbolAddress((void**)&pwoh, g_woh);
    cudaGetSymbolAddress((void**)&pq,   g_q);
    cudaGetSymbolAddress((void**)&pk,   g_k);
    cudaGetSymbolAddress((void**)&pv,   g_v);
    cudaGetSymbolAddress((void**)&pa,   g_ao);
    cudaGetSymbolAddress((void**)&pbits, g_adjbits);

    prep_kernel<<<3072, 256>>>(adj, pbits, x, pxh,
                               Wq, pwqh, Wk, pwkh, Wv, pwvh, Wo, pwoh);

    const int M = B_ * N_;                    // 8192
    dim3 qkvGrid(D_ / 128, M / 128, 3);       // (4, 64, 3)
    dim3 oGrid(D_ / 128, M / 128);            // (4, 64)

    cudaFuncSetAttribute(gemm_qkv_kernel,
                         cudaFuncAttributeMaxDynamicSharedMemorySize,
                         GEMM_SMEM_BYTES);
    cudaFuncSetAttribute(gemm_out_kernel,
                         cudaFuncAttributeMaxDynamicSharedMemorySize,
                         GEMM_SMEM_BYTES);
    cudaFuncSetAttribute(attn_f16_kernel,
                         cudaFuncAttributeMaxDynamicSharedMemorySize,
                         ATTN_SMEM_BYTES);

    gemm_qkv_kernel<<<qkvGrid, 256, GEMM_SMEM_BYTES>>>(
        pxh, pwqh, pwkh, pwvh, bq, bk, bv, pq, pk, pv, M, D_, D_);

    attn_f16_kernel<<<dim3(N_ / 128, H_, B_), 256, ATTN_SMEM_BYTES>>>(
        pq, pk, pv, pbits, pa);

    gemm_out_kernel<<<oGrid, 256, GEMM_SMEM_BYTES>>>(
        pa, pwoh, bo, out, M, D_, D_);
}

// round 13
// speedup vs baseline: 7.3153x; 1.0689x over previous
#include <cuda_runtime.h>
#include <cuda_fp16.h>
#include <cstdint>

// Problem constants
#define B_  4
#define N_  2048
#define D_  512
#define H_  8
#define HD_ 64

// Q pre-scale: 1/sqrt(HD) * log2(e), applied to Wq/bq in fp32 before rounding
#define QW_SCALE 0.1803368801111137f
// mask constant in log2 domain: 1e9 * log2(e)
#define MASKC 1.4426950408e9f

// Scratch (allocation-free rule: __device__ globals)
static __device__ __half g_xh [B_ * N_ * D_];
static __device__ __half g_wqh[D_ * D_];
static __device__ __half g_wkh[D_ * D_];
static __device__ __half g_wvh[D_ * D_];
static __device__ __half g_woh[D_ * D_];
static __device__ __half g_q  [B_ * N_ * D_];
static __device__ __half g_k  [B_ * N_ * D_];
static __device__ __half g_v  [B_ * N_ * D_];
static __device__ __half g_ao [B_ * N_ * D_];
static __device__ unsigned g_adjbits[N_ * (N_ / 32)];   // 512 KB bitmask

// ---------------------------------------------------------------------------
// helpers
// ---------------------------------------------------------------------------
__device__ __forceinline__ unsigned h2pack(float a, float b) {
    __half2 h = __floats2half2_rn(a, b);
    return *reinterpret_cast<unsigned*>(&h);
}

__device__ __forceinline__ float ex2f(float x) {
    float r;
    asm("ex2.approx.ftz.f32 %0, %1;" : "=f"(r) : "f"(x));
    return r;
}

// pack two fp32 to half2, then 2^x on both halves with ONE MUFU op.
// Overflowed negative args round to -inf -> ex2 -> +0 (exact mask behavior).
__device__ __forceinline__ unsigned ex2_h2(float a, float b) {
    unsigned h = h2pack(a, b);
    unsigned r;
    asm("ex2.approx.f16x2 %0, %1;" : "=r"(r) : "r"(h));
    return r;
}

__device__ __forceinline__ void mma_f16(float c[4], const unsigned a[4],
                                        unsigned b0, unsigned b1)
{
    asm volatile(
        "mma.sync.aligned.m16n8k16.row.col.f32.f16.f16.f32 "
        "{%0,%1,%2,%3}, {%4,%5,%6,%7}, {%8,%9}, {%0,%1,%2,%3};\n"
        : "+f"(c[0]), "+f"(c[1]), "+f"(c[2]), "+f"(c[3])
        : "r"(a[0]), "r"(a[1]), "r"(a[2]), "r"(a[3]), "r"(b0), "r"(b1));
}

__device__ __forceinline__ void ldsm_x4(unsigned r[4], const __half* p) {
    unsigned addr = (unsigned)__cvta_generic_to_shared(p);
    asm volatile(
        "ldmatrix.sync.aligned.m8n8.x4.shared.b16 {%0,%1,%2,%3}, [%4];\n"
        : "=r"(r[0]), "=r"(r[1]), "=r"(r[2]), "=r"(r[3]) : "r"(addr));
}

__device__ __forceinline__ void ldsm_x4_t(unsigned r[4], const __half* p) {
    unsigned addr = (unsigned)__cvta_generic_to_shared(p);
    asm volatile(
        "ldmatrix.sync.aligned.m8n8.x4.trans.shared.b16 {%0,%1,%2,%3}, [%4];\n"
        : "=r"(r[0]), "=r"(r[1]), "=r"(r[2]), "=r"(r[3]) : "r"(addr));
}

__device__ __forceinline__ void cp_async16(__half* dst, const void* src) {
    unsigned d = (unsigned)__cvta_generic_to_shared(dst);
    asm volatile("cp.async.ca.shared.global [%0], [%1], 16;\n"
                 :: "r"(d), "l"(src));
}
__device__ __forceinline__ void cp_commit() {
    asm volatile("cp.async.commit_group;\n");
}
template<int NMAX> __device__ __forceinline__ void cp_wait() {
    asm volatile("cp.async.wait_group %0;\n" :: "n"(NMAX));
}

__device__ __forceinline__ void store2(float* C, size_t off, float a, float b) {
    *(float2*)(C + off) = make_float2(a, b);
}
__device__ __forceinline__ void store2(__half* C, size_t off, float a, float b) {
    *(unsigned*)(C + off) = h2pack(a, b);
}

// ---------------------------------------------------------------------------
// Fused prologue: adj bit-pack + all f32->f16 conversions (Wq pre-scaled).
// ---------------------------------------------------------------------------
__global__ __launch_bounds__(256) void prep_kernel(
    const float* __restrict__ adj, unsigned* __restrict__ bits,
    const float* __restrict__ x,  __half* __restrict__ xh,
    const float* __restrict__ Wq, __half* __restrict__ wqh,
    const float* __restrict__ Wk, __half* __restrict__ wkh,
    const float* __restrict__ Wv, __half* __restrict__ wvh,
    const float* __restrict__ Wo, __half* __restrict__ woh)
{
    const int blk = blockIdx.x;
    const int tid = threadIdx.x;

    if (blk < 512) {
        int idx = blk * 256 + tid;
        const float* p = adj + (size_t)idx * 32;
        unsigned m = 0;
        #pragma unroll
        for (int j = 0; j < 32; j += 4) {
            float4 v = *(const float4*)(p + j);
            m |= (v.x != 0.f ? 1u : 0u) << (j + 0);
            m |= (v.y != 0.f ? 1u : 0u) << (j + 1);
            m |= (v.z != 0.f ? 1u : 0u) << (j + 2);
            m |= (v.w != 0.f ? 1u : 0u) << (j + 3);
        }
        bits[idx] = m;
        return;
    }

    const float* in; __half* out; int rb; float scale = 1.0f;
    if (blk < 2560)      { in = x;  out = xh;  rb = blk - 512; }
    else if (blk < 2688) { in = Wq; out = wqh; rb = blk - 2560; scale = QW_SCALE; }
    else if (blk < 2816) { in = Wk; out = wkh; rb = blk - 2688; }
    else if (blk < 2944) { in = Wv; out = wvh; rb = blk - 2816; }
    else                 { in = Wo; out = woh; rb = blk - 2944; }

    size_t idx = ((size_t)rb * 256 + tid) * 8;
    float4 a = *(const float4*)(in + idx);
    float4 b = *(const float4*)(in + idx + 4);
    uint4 r = make_uint4(h2pack(a.x * scale, a.y * scale),
                         h2pack(a.z * scale, a.w * scale),
                         h2pack(b.x * scale, b.y * scale),
                         h2pack(b.z * scale, b.w * scale));
    *(uint4*)(out + idx) = r;
}

// ---------------------------------------------------------------------------
// FP16 GEMM body: C[M,N] = A[M,K](f16) @ W[K,N](f16) + bias(f32)*bscale.
// BM=128, BN=128, BK=32; 8 warps (4x2), warp tile 32x64.
// 4-stage cp.async pipeline. As[m][k] (LDSM), Bs[k][n] (trans LDSM).
// ---------------------------------------------------------------------------
#define GSTAGES 4
#define GA_PITCH 40                   // halves (80B = 5x16B)
#define GB_PITCH 136                  // halves (272B = 17x16B)
#define GA_H (128 * GA_PITCH)         // 5120
#define GB_H (32 * GB_PITCH)          // 4352
#define GEMM_SMEM_BYTES (GSTAGES * (GA_H + GB_H) * 2)   // 75776

template<typename OutT>
__device__ __forceinline__ void gemm_body(
    const __half* __restrict__ A, const __half* __restrict__ W,
    const float* __restrict__ bias, float bscale, OutT* __restrict__ C,
    int M, int N, int K)
{
    extern __shared__ __half gsm[];
    __half* Abase = gsm;
    __half* Bbase = gsm + GSTAGES * GA_H;

    const int tid  = threadIdx.x;
    const int warp = tid >> 5;
    const int lane = tid & 31;
    const int wm = warp >> 1, wn = warp & 1;
    const int gid = lane >> 2, tig = lane & 3;
    const int rsel = (lane & 7) + ((lane >> 3) & 1) * 8;
    const int csel = (lane >> 4) * 8;

    const int rowBase = blockIdx.y * 128;
    const int colBase = blockIdx.x * 128;

    const int aRow0 = tid >> 2;          // 0..63 (2 passes of 64)
    const int aCh   = tid & 3;
    const int bRow0 = tid >> 4;          // 0..15 (2 passes of 16)
    const int bCh   = tid & 15;

    float acc[2][8][4];
    #pragma unroll
    for (int mt = 0; mt < 2; mt++)
        #pragma unroll
        for (int nt = 0; nt < 8; nt++)
            #pragma unroll
            for (int i = 0; i < 4; i++) acc[mt][nt][i] = 0.f;

    auto load_stage = [&](int st, int k0) {
        __half* As = Abase + st * GA_H;
        __half* Bs = Bbase + st * GB_H;
        #pragma unroll
        for (int p = 0; p < 2; p++) {
            int r = aRow0 + p * 64;
            cp_async16(&As[r * GA_PITCH + aCh * 8],
                       A + (size_t)(rowBase + r) * K + k0 + aCh * 8);
        }
        #pragma unroll
        for (int p = 0; p < 2; p++) {
            int r = bRow0 + p * 16;
            cp_async16(&Bs[r * GB_PITCH + bCh * 8],
                       W + (size_t)(k0 + r) * N + colBase + bCh * 8);
        }
    };

    const int iters = K >> 5;            // 16
    #pragma unroll
    for (int s = 0; s < GSTAGES - 1; s++) {
        load_stage(s, s * 32);
        cp_commit();
    }

    for (int it = 0; it < iters; it++) {
        cp_wait<GSTAGES - 2>();
        __syncthreads();

        int pre = it + GSTAGES - 1;
        if (pre < iters) load_stage(pre & (GSTAGES - 1), pre * 32);
        cp_commit();

        const int st = it & (GSTAGES - 1);
        const __half* As = Abase + st * GA_H;
        const __half* Bs = Bbase + st * GB_H;

        #pragma unroll
        for (int ks = 0; ks < 2; ks++) {
            unsigned a[2][4];
            #pragma unroll
            for (int mt = 0; mt < 2; mt++)
                ldsm_x4(a[mt], &As[(wm * 32 + mt * 16 + rsel) * GA_PITCH
                                   + ks * 16 + csel]);
            unsigned bb[4][4];
            #pragma unroll
            for (int np = 0; np < 4; np++)
                ldsm_x4_t(bb[np], &Bs[(ks * 16 + rsel) * GB_PITCH
                                      + wn * 64 + np * 16 + csel]);
            #pragma unroll
            for (int nt = 0; nt < 8; nt++)
                #pragma unroll
                for (int mt = 0; mt < 2; mt++)
                    mma_f16(acc[mt][nt], a[mt],
                            bb[nt >> 1][(nt & 1) * 2], bb[nt >> 1][(nt & 1) * 2 + 1]);
        }
    }

    #pragma unroll
    for (int mt = 0; mt < 2; mt++) {
        int r0 = rowBase + wm * 32 + mt * 16 + gid;
        #pragma unroll
        for (int nt = 0; nt < 8; nt++) {
            int col = colBase + wn * 64 + nt * 8 + tig * 2;
            float2 bv = *(const float2*)(bias + col);
            store2(C, (size_t)r0 * N + col,
                   acc[mt][nt][0] + bv.x * bscale, acc[mt][nt][1] + bv.y * bscale);
            store2(C, (size_t)(r0 + 8) * N + col,
                   acc[mt][nt][2] + bv.x * bscale, acc[mt][nt][3] + bv.y * bscale);
        }
    }
}

// fused QKV: blockIdx.z selects weight/bias/output; Q path has scaled bias
__global__ __launch_bounds__(256, 2) void gemm_qkv_kernel(
    const __half* __restrict__ A,
    const __half* __restrict__ Wq, const __half* __restrict__ Wk,
    const __half* __restrict__ Wv,
    const float* __restrict__ bq, const float* __restrict__ bk,
    const float* __restrict__ bv,
    __half* __restrict__ Cq, __half* __restrict__ Ck, __half* __restrict__ Cv,
    int M, int N, int K)
{
    const __half* W; const float* bias; __half* C; float bscale = 1.0f;
    if (blockIdx.z == 0)      { W = Wq; bias = bq; C = Cq; bscale = QW_SCALE; }
    else if (blockIdx.z == 1) { W = Wk; bias = bk; C = Ck; }
    else                      { W = Wv; bias = bv; C = Cv; }
    gemm_body<__half>(A, W, bias, bscale, C, M, N, K);
}

__global__ __launch_bounds__(256, 2) void gemm_out_kernel(
    const __half* __restrict__ A, const __half* __restrict__ W,
    const float* __restrict__ bias, float* __restrict__ C,
    int M, int N, int K)
{
    gemm_body<float>(A, W, bias, 1.0f, C, M, N, K);
}

// ---------------------------------------------------------------------------
// Fused masked flash attention, fp16 mma, warp-local softmax, P in registers.
// Q pre-scaled by 1/sqrt(HD)*log2(e) -> base-2 softmax.
// exp via ex2.approx.f16x2 (2 exps / MUFU op); row-sum l via ones-column mma.
// q-tile=128 (8 warps x 16 rows), k-tile=64, 4-stage cp.async K/V pipeline.
// ---------------------------------------------------------------------------
#define KV_PITCH 72                            // halves (144B = 9x16B)
#define KV_TILE_H (64 * KV_PITCH)              // 4608
#define KV_STAGE_H (2 * KV_TILE_H)             // 9216
#define ASTAGES 4
#define QS_OFF (ASTAGES * KV_STAGE_H)          // 36864
#define ATTN_SMEM_BYTES ((QS_OFF + 128 * KV_PITCH) * 2)   // 92160

__global__ __launch_bounds__(256, 2) void attn_f16_kernel(
    const __half* __restrict__ q, const __half* __restrict__ k,
    const __half* __restrict__ v, const unsigned* __restrict__ mbits,
    __half* __restrict__ o)
{
    extern __shared__ __half smh[];
    __half* QS = smh + QS_OFF;

    const int tid  = threadIdx.x;
    const int warp = tid >> 5;
    const int lane = tid & 31;
    const int gid = lane >> 2, tig = lane & 3;
    const int rsel = (lane & 7) + ((lane >> 3) & 1) * 8;
    const int csel = (lane >> 4) * 8;

    const int q0 = blockIdx.x * 128;
    const int h  = blockIdx.y;
    const int b  = blockIdx.z;
    const int row0 = warp * 16;

    const __half* qbase = q + (size_t)b * N_ * D_ + h * HD_;
    const __half* kbase = k + (size_t)b * N_ * D_ + h * HD_;
    const __half* vbase = v + (size_t)b * N_ * D_ + h * HD_;

    auto load_kv = [&](int st, int k0) {
        __half* KS = smh + st * KV_STAGE_H;
        __half* VS = KS + KV_TILE_H;
        #pragma unroll
        for (int p = 0; p < 4; p++) {
            int idx = tid + p * 256;             // 0..1023
            int mat = idx >> 9;                  // 0 = K, 1 = V
            int rem = idx & 511;
            int r = rem >> 3, ch = rem & 7;
            const __half* src = (mat ? vbase : kbase)
                                + (size_t)(k0 + r) * D_ + ch * 8;
            __half* dst = (mat ? VS : KS) + r * KV_PITCH + ch * 8;
            cp_async16(dst, src);
        }
    };

    #pragma unroll
    for (int s = 0; s < ASTAGES - 1; s++) {
        load_kv(s, s * 64);
        cp_commit();
    }

    // stage Q (already pre-scaled) into QS, hoist frags
    #pragma unroll
    for (int p = 0; p < 4; p++) {
        int idx = tid + p * 256;                 // 0..1023
        int r = idx >> 3, ch = idx & 7;
        *(uint4*)&QS[r * KV_PITCH + ch * 8] =
            *(const uint4*)(qbase + (size_t)(q0 + r) * D_ + ch * 8);
    }
    __syncthreads();

    unsigned qf[4][4];
    #pragma unroll
    for (int ks = 0; ks < 4; ks++)
        ldsm_x4(qf[ks], &QS[(row0 + rsel) * KV_PITCH + ks * 16 + csel]);

    float O[8][4];
    #pragma unroll
    for (int nt = 0; nt < 8; nt++)
        #pragma unroll
        for (int i = 0; i < 4; i++) O[nt][i] = 0.f;
    float mA = -1e30f, mB = -1e30f;

    // l accumulated as an mma C-fragment: P @ onesColumn.
    // B frag: column 0 all-ones -> lanes 0..3 hold {1,1} in both b regs.
    float l_frag[4] = {0.f, 0.f, 0.f, 0.f};
    const unsigned onesB = (lane < 4) ? 0x3C003C00u : 0u;

    const int rowA = q0 + row0 + gid;
    const int rowB = rowA + 8;
    const unsigned* mrowA = mbits + (size_t)rowA * (N_ / 32);
    const unsigned* mrowB = mbits + (size_t)rowB * (N_ / 32);

    const int iters = N_ / 64;                   // 32
    for (int it = 0; it < iters; it++) {
        const int k0 = it * 64;

        cp_wait<ASTAGES - 2>();
        __syncthreads();

        int pre = it + ASTAGES - 1;
        if (pre < iters) load_kv(pre & (ASTAGES - 1), pre * 64);
        cp_commit();

        uint2 ma2 = *(const uint2*)(mrowA + (k0 >> 5));
        uint2 mb2 = *(const uint2*)(mrowB + (k0 >> 5));
        uint64_t maskA = (uint64_t)ma2.x | ((uint64_t)ma2.y << 32);
        uint64_t maskB = (uint64_t)mb2.x | ((uint64_t)mb2.y << 32);

        const int st = it & (ASTAGES - 1);
        const __half* KS = smh + st * KV_STAGE_H;
        const __half* VS = KS + KV_TILE_H;

        // ---- S = Q @ K^T (log2-domain logits) ----
        float s[8][4];
        #pragma unroll
        for (int nt = 0; nt < 8; nt++)
            #pragma unroll
            for (int i = 0; i < 4; i++) s[nt][i] = 0.f;

        #pragma unroll
        for (int ks = 0; ks < 4; ks++) {
            unsigned kb[4][4];
            #pragma unroll
            for (int np = 0; np < 4; np++)
                ldsm_x4(kb[np], &KS[(np * 16 + rsel) * KV_PITCH + ks * 16 + csel]);
            #pragma unroll
            for (int nt = 0; nt < 8; nt++)
                mma_f16(s[nt], qf[ks],
                        kb[nt >> 1][nt & 1], kb[nt >> 1][2 + (nt & 1)]);
        }

        // ---- mask ----
        #pragma unroll
        for (int nt = 0; nt < 8; nt++) {
            int c = nt * 8 + tig * 2;
            if (!((maskA >> c) & 1))       s[nt][0] -= MASKC;
            if (!((maskA >> (c + 1)) & 1)) s[nt][1] -= MASKC;
            if (!((maskB >> c) & 1))       s[nt][2] -= MASKC;
            if (!((maskB >> (c + 1)) & 1)) s[nt][3] -= MASKC;
        }

        // ---- warp-local online softmax (base-2) ----
        float mxA = -1e30f, mxB = -1e30f;
        #pragma unroll
        for (int nt = 0; nt < 8; nt++) {
            mxA = fmaxf(mxA, fmaxf(s[nt][0], s[nt][1]));
            mxB = fmaxf(mxB, fmaxf(s[nt][2], s[nt][3]));
        }
        mxA = fmaxf(mxA, __shfl_xor_sync(0xffffffffu, mxA, 1));
        mxA = fmaxf(mxA, __shfl_xor_sync(0xffffffffu, mxA, 2));
        mxB = fmaxf(mxB, __shfl_xor_sync(0xffffffffu, mxB, 1));
        mxB = fmaxf(mxB, __shfl_xor_sync(0xffffffffu, mxB, 2));

        float mnA = fmaxf(mA, mxA), mnB = fmaxf(mB, mxB);
        float alA = ex2f(mA - mnA), alB = ex2f(mB - mnB);
        mA = mnA; mB = mnB;

        // rescale l fragment and O, exp via f16x2 MUFU (1 op per 2 exps)
        l_frag[0] *= alA; l_frag[1] *= alA;
        l_frag[2] *= alB; l_frag[3] *= alB;

        unsigned ph[8][2];
        #pragma unroll
        for (int nt = 0; nt < 8; nt++) {
            ph[nt][0] = ex2_h2(s[nt][0] - mnA, s[nt][1] - mnA);
            ph[nt][1] = ex2_h2(s[nt][2] - mnB, s[nt][3] - mnB);
            O[nt][0] *= alA; O[nt][1] *= alA;
            O[nt][2] *= alB; O[nt][3] *= alB;
        }

        // ---- O += P @ V ; l += P @ ones (both from P registers) ----
        #pragma unroll
        for (int ks = 0; ks < 4; ks++) {
            unsigned vb[4][4];
            #pragma unroll
            for (int dp = 0; dp < 4; dp++)
                ldsm_x4_t(vb[dp], &VS[(ks * 16 + rsel) * KV_PITCH + dp * 16 + csel]);
            unsigned pa[4] = { ph[2 * ks][0], ph[2 * ks][1],
                               ph[2 * ks + 1][0], ph[2 * ks + 1][1] };
            mma_f16(l_frag, pa, onesB, onesB);
            #pragma unroll
            for (int nt = 0; nt < 8; nt++)
                mma_f16(O[nt], pa,
                        vb[nt >> 1][(nt & 1) * 2], vb[nt >> 1][(nt & 1) * 2 + 1]);
        }
    }

    // Finalize: l lives in column 0 of the C fragment (tig==0 lanes)
    float lA = __shfl_sync(0xffffffffu, l_frag[0], lane & 28);
    float lB = __shfl_sync(0xffffffffu, l_frag[2], lane & 28);
    float invA = 1.0f / lA, invB = 1.0f / lB;
    __half* obase = o + (size_t)b * N_ * D_ + h * HD_;
    #pragma unroll
    for (int nt = 0; nt < 8; nt++) {
        int c = nt * 8 + tig * 2;
        *(unsigned*)(obase + (size_t)rowA * D_ + c) =
            h2pack(O[nt][0] * invA, O[nt][1] * invA);
        *(unsigned*)(obase + (size_t)rowB * D_ + c) =
            h2pack(O[nt][2] * invB, O[nt][3] * invB);
    }
}

// ---------------------------------------------------------------------------
extern "C" void kernel_launch(void* const* d_in, const int* in_sizes, int n_in,
                              void* d_out, int out_size)
{
    const float* x   = (const float*)d_in[0];
    const float* adj = (const float*)d_in[1];
    const float* Wq  = (const float*)d_in[2];
    const float* bq  = (const float*)d_in[3];
    const float* Wk  = (const float*)d_in[4];
    const float* bk  = (const float*)d_in[5];
    const float* Wv  = (const float*)d_in[6];
    const float* bv  = (const float*)d_in[7];
    const float* Wo  = (const float*)d_in[8];
    const float* bo  = (const float*)d_in[9];
    float* out = (float*)d_out;

    __half *pxh, *pwqh, *pwkh, *pwvh, *pwoh, *pq, *pk, *pv, *pa;
    unsigned* pbits;
    cudaGetSymbolAddress((void**)&pxh,  g_xh);
    cudaGetSymbolAddress((void**)&pwqh, g_wqh);
    cudaGetSymbolAddress((void**)&pwkh, g_wkh);
    cudaGetSymbolAddress((void**)&pwvh, g_wvh);
    cudaGetSymbolAddress((void**)&pwoh, g_woh);
    cudaGetSymbolAddress((void**)&pq,   g_q);
    cudaGetSymbolAddress((void**)&pk,   g_k);
    cudaGetSymbolAddress((void**)&pv,   g_v);
    cudaGetSymbolAddress((void**)&pa,   g_ao);
    cudaGetSymbolAddress((void**)&pbits, g_adjbits);

    prep_kernel<<<3072, 256>>>(adj, pbits, x, pxh,
                               Wq, pwqh, Wk, pwkh, Wv, pwvh, Wo, pwoh);

    const int M = B_ * N_;                    // 8192
    dim3 qkvGrid(D_ / 128, M / 128, 3);       // (4, 64, 3)
    dim3 oGrid(D_ / 128, M / 128);            // (4, 64)

    cudaFuncSetAttribute(gemm_qkv_kernel,
                         cudaFuncAttributeMaxDynamicSharedMemorySize,
                         GEMM_SMEM_BYTES);
    cudaFuncSetAttribute(gemm_out_kernel,
                         cudaFuncAttributeMaxDynamicSharedMemorySize,
                         GEMM_SMEM_BYTES);
    cudaFuncSetAttribute(attn_f16_kernel,
                         cudaFuncAttributeMaxDynamicSharedMemorySize,
                         ATTN_SMEM_BYTES);

    gemm_qkv_kernel<<<qkvGrid, 256, GEMM_SMEM_BYTES>>>(
        pxh, pwqh, pwkh, pwvh, bq, bk, bv, pq, pk, pv, M, D_, D_);

    attn_f16_kernel<<<dim3(N_ / 128, H_, B_), 256, ATTN_SMEM_BYTES>>>(
        pq, pk, pv, pbits, pa);

    gemm_out_kernel<<<oGrid, 256, GEMM_SMEM_BYTES>>>(
        pa, pwoh, bo, out, M, D_, D_);
}

// round 17
// speedup vs baseline: 7.3175x; 1.0003x over previous
#include <cuda_runtime.h>
#include <cuda_fp16.h>
#include <cstdint>

// Problem constants
#define B_  4
#define N_  2048
#define D_  512
#define H_  8
#define HD_ 64

// Q pre-scale: 1/sqrt(HD) * log2(e), applied to Wq/bq in fp32 before rounding
#define QW_SCALE 0.1803368801111137f
// mask constant in log2 domain: 1e9 * log2(e)
#define MASKC 1.4426950408e9f

// Scratch (allocation-free rule: __device__ globals)
static __device__ __half g_xh [B_ * N_ * D_];
static __device__ __half g_wqh[D_ * D_];
static __device__ __half g_wkh[D_ * D_];
static __device__ __half g_wvh[D_ * D_];
static __device__ __half g_woh[D_ * D_];
static __device__ __half g_q  [B_ * N_ * D_];
static __device__ __half g_k  [B_ * N_ * D_];
static __device__ __half g_v  [B_ * N_ * D_];
static __device__ __half g_ao [B_ * N_ * D_];
static __device__ unsigned g_adjbits[N_ * (N_ / 32)];   // 512 KB bitmask

// ---------------------------------------------------------------------------
// helpers
// ---------------------------------------------------------------------------
__device__ __forceinline__ unsigned h2pack(float a, float b) {
    __half2 h = __floats2half2_rn(a, b);
    return *reinterpret_cast<unsigned*>(&h);
}

__device__ __forceinline__ float ex2f(float x) {
    float r;
    asm("ex2.approx.ftz.f32 %0, %1;" : "=f"(r) : "f"(x));
    return r;
}

// pack two fp32 to half2, then 2^x on both halves with ONE MUFU op.
__device__ __forceinline__ unsigned ex2_h2(float a, float b) {
    unsigned h = h2pack(a, b);
    unsigned r;
    asm("ex2.approx.f16x2 %0, %1;" : "=r"(r) : "r"(h));
    return r;
}

__device__ __forceinline__ void mma_f16(float c[4], const unsigned a[4],
                                        unsigned b0, unsigned b1)
{
    asm volatile(
        "mma.sync.aligned.m16n8k16.row.col.f32.f16.f16.f32 "
        "{%0,%1,%2,%3}, {%4,%5,%6,%7}, {%8,%9}, {%0,%1,%2,%3};\n"
        : "+f"(c[0]), "+f"(c[1]), "+f"(c[2]), "+f"(c[3])
        : "r"(a[0]), "r"(a[1]), "r"(a[2]), "r"(a[3]), "r"(b0), "r"(b1));
}

__device__ __forceinline__ void ldsm_x4(unsigned r[4], const __half* p) {
    unsigned addr = (unsigned)__cvta_generic_to_shared(p);
    asm volatile(
        "ldmatrix.sync.aligned.m8n8.x4.shared.b16 {%0,%1,%2,%3}, [%4];\n"
        : "=r"(r[0]), "=r"(r[1]), "=r"(r[2]), "=r"(r[3]) : "r"(addr));
}

__device__ __forceinline__ void ldsm_x4_t(unsigned r[4], const __half* p) {
    unsigned addr = (unsigned)__cvta_generic_to_shared(p);
    asm volatile(
        "ldmatrix.sync.aligned.m8n8.x4.trans.shared.b16 {%0,%1,%2,%3}, [%4];\n"
        : "=r"(r[0]), "=r"(r[1]), "=r"(r[2]), "=r"(r[3]) : "r"(addr));
}

__device__ __forceinline__ void cp_async16(__half* dst, const void* src) {
    unsigned d = (unsigned)__cvta_generic_to_shared(dst);
    asm volatile("cp.async.ca.shared.global [%0], [%1], 16;\n"
                 :: "r"(d), "l"(src));
}
__device__ __forceinline__ void cp_commit() {
    asm volatile("cp.async.commit_group;\n");
}
template<int NMAX> __device__ __forceinline__ void cp_wait() {
    asm volatile("cp.async.wait_group %0;\n" :: "n"(NMAX));
}

__device__ __forceinline__ void store2(float* C, size_t off, float a, float b) {
    *(float2*)(C + off) = make_float2(a, b);
}
__device__ __forceinline__ void store2(__half* C, size_t off, float a, float b) {
    *(unsigned*)(C + off) = h2pack(a, b);
}

// ---------------------------------------------------------------------------
// Fused prologue: adj bit-pack + all f32->f16 conversions (Wq pre-scaled).
// Block ranges (1536 blocks):
//   [0,256)      : pack adj, 2 words / thread
//   [256,1280)   : cvt x,  16 elems / thread
//   [1280,1344)  : cvt Wq * QW_SCALE
//   [1344,1408)  : cvt Wk
//   [1408,1472)  : cvt Wv
//   [1472,1536)  : cvt Wo
// ---------------------------------------------------------------------------
__global__ __launch_bounds__(256) void prep_kernel(
    const float* __restrict__ adj, unsigned* __restrict__ bits,
    const float* __restrict__ x,  __half* __restrict__ xh,
    const float* __restrict__ Wq, __half* __restrict__ wqh,
    const float* __restrict__ Wk, __half* __restrict__ wkh,
    const float* __restrict__ Wv, __half* __restrict__ wvh,
    const float* __restrict__ Wo, __half* __restrict__ woh)
{
    const int blk = blockIdx.x;
    const int tid = threadIdx.x;

    if (blk < 256) {
        int base = (blk * 256 + tid) * 2;
        #pragma unroll
        for (int w = 0; w < 2; w++) {
            int idx = base + w;
            const float* p = adj + (size_t)idx * 32;
            unsigned m = 0;
            #pragma unroll
            for (int j = 0; j < 32; j += 4) {
                float4 v = *(const float4*)(p + j);
                m |= (v.x != 0.f ? 1u : 0u) << (j + 0);
                m |= (v.y != 0.f ? 1u : 0u) << (j + 1);
                m |= (v.z != 0.f ? 1u : 0u) << (j + 2);
                m |= (v.w != 0.f ? 1u : 0u) << (j + 3);
            }
            bits[idx] = m;
        }
        return;
    }

    const float* in; __half* out; int rb; float scale = 1.0f;
    if (blk < 1280)      { in = x;  out = xh;  rb = blk - 256; }
    else if (blk < 1344) { in = Wq; out = wqh; rb = blk - 1280; scale = QW_SCALE; }
    else if (blk < 1408) { in = Wk; out = wkh; rb = blk - 1344; }
    else if (blk < 1472) { in = Wv; out = wvh; rb = blk - 1408; }
    else                 { in = Wo; out = woh; rb = blk - 1472; }

    size_t idx = ((size_t)rb * 256 + tid) * 16;
    #pragma unroll
    for (int h = 0; h < 2; h++) {
        float4 a = *(const float4*)(in + idx + h * 8);
        float4 b = *(const float4*)(in + idx + h * 8 + 4);
        uint4 r = make_uint4(h2pack(a.x * scale, a.y * scale),
                             h2pack(a.z * scale, a.w * scale),
                             h2pack(b.x * scale, b.y * scale),
                             h2pack(b.z * scale, b.w * scale));
        *(uint4*)(out + idx + h * 8) = r;
    }
}

// ---------------------------------------------------------------------------
// FP16 GEMM body: C[M,N] = A[M,K](f16) @ W[K,N](f16) + bias(f32)*bscale.
// BM=128, BN=128, BK=32; 8 warps (4x2), warp tile 32x64.
// 4-stage cp.async pipeline. As[m][k] (LDSM), Bs[k][n] (trans LDSM).
// ---------------------------------------------------------------------------
#define GSTAGES 4
#define GA_PITCH 40                   // halves (80B = 5x16B)
#define GB_PITCH 136                  // halves (272B = 17x16B)
#define GA_H (128 * GA_PITCH)         // 5120
#define GB_H (32 * GB_PITCH)          // 4352
#define GEMM_SMEM_BYTES (GSTAGES * (GA_H + GB_H) * 2)   // 75776

template<typename OutT>
__device__ __forceinline__ void gemm_body(
    const __half* __restrict__ A, const __half* __restrict__ W,
    const float* __restrict__ bias, float bscale, OutT* __restrict__ C,
    int M, int N, int K)
{
    extern __shared__ __half gsm[];
    __half* Abase = gsm;
    __half* Bbase = gsm + GSTAGES * GA_H;

    const int tid  = threadIdx.x;
    const int warp = tid >> 5;
    const int lane = tid & 31;
    const int wm = warp >> 1, wn = warp & 1;
    const int gid = lane >> 2, tig = lane & 3;
    const int rsel = (lane & 7) + ((lane >> 3) & 1) * 8;
    const int csel = (lane >> 4) * 8;

    const int rowBase = blockIdx.y * 128;
    const int colBase = blockIdx.x * 128;

    const int aRow0 = tid >> 2;          // 0..63 (2 passes of 64)
    const int aCh   = tid & 3;
    const int bRow0 = tid >> 4;          // 0..15 (2 passes of 16)
    const int bCh   = tid & 15;

    float acc[2][8][4];
    #pragma unroll
    for (int mt = 0; mt < 2; mt++)
        #pragma unroll
        for (int nt = 0; nt < 8; nt++)
            #pragma unroll
            for (int i = 0; i < 4; i++) acc[mt][nt][i] = 0.f;

    auto load_stage = [&](int st, int k0) {
        __half* As = Abase + st * GA_H;
        __half* Bs = Bbase + st * GB_H;
        #pragma unroll
        for (int p = 0; p < 2; p++) {
            int r = aRow0 + p * 64;
            cp_async16(&As[r * GA_PITCH + aCh * 8],
                       A + (size_t)(rowBase + r) * K + k0 + aCh * 8);
        }
        #pragma unroll
        for (int p = 0; p < 2; p++) {
            int r = bRow0 + p * 16;
            cp_async16(&Bs[r * GB_PITCH + bCh * 8],
                       W + (size_t)(k0 + r) * N + colBase + bCh * 8);
        }
    };

    const int iters = K >> 5;            // 16
    #pragma unroll
    for (int s = 0; s < GSTAGES - 1; s++) {
        load_stage(s, s * 32);
        cp_commit();
    }

    for (int it = 0; it < iters; it++) {
        cp_wait<GSTAGES - 2>();
        __syncthreads();

        int pre = it + GSTAGES - 1;
        if (pre < iters) load_stage(pre & (GSTAGES - 1), pre * 32);
        cp_commit();

        const int st = it & (GSTAGES - 1);
        const __half* As = Abase + st * GA_H;
        const __half* Bs = Bbase + st * GB_H;

        #pragma unroll
        for (int ks = 0; ks < 2; ks++) {
            unsigned a[2][4];
            #pragma unroll
            for (int mt = 0; mt < 2; mt++)
                ldsm_x4(a[mt], &As[(wm * 32 + mt * 16 + rsel) * GA_PITCH
                                   + ks * 16 + csel]);
            unsigned bb[4][4];
            #pragma unroll
            for (int np = 0; np < 4; np++)
                ldsm_x4_t(bb[np], &Bs[(ks * 16 + rsel) * GB_PITCH
                                      + wn * 64 + np * 16 + csel]);
            #pragma unroll
            for (int nt = 0; nt < 8; nt++)
                #pragma unroll
                for (int mt = 0; mt < 2; mt++)
                    mma_f16(acc[mt][nt], a[mt],
                            bb[nt >> 1][(nt & 1) * 2], bb[nt >> 1][(nt & 1) * 2 + 1]);
        }
    }

    #pragma unroll
    for (int mt = 0; mt < 2; mt++) {
        int r0 = rowBase + wm * 32 + mt * 16 + gid;
        #pragma unroll
        for (int nt = 0; nt < 8; nt++) {
            int col = colBase + wn * 64 + nt * 8 + tig * 2;
            float2 bv = *(const float2*)(bias + col);
            store2(C, (size_t)r0 * N + col,
                   acc[mt][nt][0] + bv.x * bscale, acc[mt][nt][1] + bv.y * bscale);
            store2(C, (size_t)(r0 + 8) * N + col,
                   acc[mt][nt][2] + bv.x * bscale, acc[mt][nt][3] + bv.y * bscale);
        }
    }
}

// fused QKV: blockIdx.z selects weight/bias/output; Q path has scaled bias
__global__ __launch_bounds__(256, 2) void gemm_qkv_kernel(
    const __half* __restrict__ A,
    const __half* __restrict__ Wq, const __half* __restrict__ Wk,
    const __half* __restrict__ Wv,
    const float* __restrict__ bq, const float* __restrict__ bk,
    const float* __restrict__ bv,
    __half* __restrict__ Cq, __half* __restrict__ Ck, __half* __restrict__ Cv,
    int M, int N, int K)
{
    const __half* W; const float* bias; __half* C; float bscale = 1.0f;
    if (blockIdx.z == 0)      { W = Wq; bias = bq; C = Cq; bscale = QW_SCALE; }
    else if (blockIdx.z == 1) { W = Wk; bias = bk; C = Ck; }
    else                      { W = Wv; bias = bv; C = Cv; }
    gemm_body<__half>(A, W, bias, bscale, C, M, N, K);
}

__global__ __launch_bounds__(256, 2) void gemm_out_kernel(
    const __half* __restrict__ A, const __half* __restrict__ W,
    const float* __restrict__ bias, float* __restrict__ C,
    int M, int N, int K)
{
    gemm_body<float>(A, W, bias, 1.0f, C, M, N, K);
}

// ---------------------------------------------------------------------------
// Fused masked flash attention, fp16 mma, warp-local softmax, P in registers.
// Q pre-scaled by 1/sqrt(HD)*log2(e) -> base-2 softmax; ex2.f16x2 exps;
// row-sum l via ones-column mma.
// q-tile=256 (16 warps x 16 rows, 512 threads, 1 CTA/SM), k-tile=64,
// 4-stage cp.async K/V pipeline. K/V smem traffic per q-row HALVED vs q=128.
// ---------------------------------------------------------------------------
#define ATHREADS 512
#define KV_PITCH 72                            // halves (144B = 9x16B)
#define KV_TILE_H (64 * KV_PITCH)              // 4608
#define KV_STAGE_H (2 * KV_TILE_H)             // 9216
#define ASTAGES 4
#define QS_OFF (ASTAGES * KV_STAGE_H)          // 36864
#define ATTN_SMEM_BYTES ((QS_OFF + 256 * KV_PITCH) * 2)   // 110592

__global__ __launch_bounds__(ATHREADS, 1) void attn_f16_kernel(
    const __half* __restrict__ q, const __half* __restrict__ k,
    const __half* __restrict__ v, const unsigned* __restrict__ mbits,
    __half* __restrict__ o)
{
    extern __shared__ __half smh[];
    __half* QS = smh + QS_OFF;

    const int tid  = threadIdx.x;
    const int warp = tid >> 5;
    const int lane = tid & 31;
    const int gid = lane >> 2, tig = lane & 3;
    const int rsel = (lane & 7) + ((lane >> 3) & 1) * 8;
    const int csel = (lane >> 4) * 8;

    const int q0 = blockIdx.x * 256;
    const int h  = blockIdx.y;
    const int b  = blockIdx.z;
    const int row0 = warp * 16;

    const __half* qbase = q + (size_t)b * N_ * D_ + h * HD_;
    const __half* kbase = k + (size_t)b * N_ * D_ + h * HD_;
    const __half* vbase = v + (size_t)b * N_ * D_ + h * HD_;

    // one K/V stage: 1024 x 16B chunks, 2 per thread
    auto load_kv = [&](int st, int k0) {
        __half* KS = smh + st * KV_STAGE_H;
        __half* VS = KS + KV_TILE_H;
        #pragma unroll
        for (int p = 0; p < 2; p++) {
            int idx = tid + p * ATHREADS;        // 0..1023
            int mat = idx >> 9;                  // 0 = K, 1 = V
            int rem = idx & 511;
            int r = rem >> 3, ch = rem & 7;
            const __half* src = (mat ? vbase : kbase)
                                + (size_t)(k0 + r) * D_ + ch * 8;
            __half* dst = (mat ? VS : KS) + r * KV_PITCH + ch * 8;
            cp_async16(dst, src);
        }
    };

    #pragma unroll
    for (int s = 0; s < ASTAGES - 1; s++) {
        load_kv(s, s * 64);
        cp_commit();
    }

    // stage Q (already pre-scaled): 2048 chunks, 4 per thread
    #pragma unroll
    for (int p = 0; p < 4; p++) {
        int idx = tid + p * ATHREADS;            // 0..2047
        int r = idx >> 3, ch = idx & 7;
        *(uint4*)&QS[r * KV_PITCH + ch * 8] =
            *(const uint4*)(qbase + (size_t)(q0 + r) * D_ + ch * 8);
    }
    __syncthreads();

    unsigned qf[4][4];
    #pragma unroll
    for (int ks = 0; ks < 4; ks++)
        ldsm_x4(qf[ks], &QS[(row0 + rsel) * KV_PITCH + ks * 16 + csel]);

    float O[8][4];
    #pragma unroll
    for (int nt = 0; nt < 8; nt++)
        #pragma unroll
        for (int i = 0; i < 4; i++) O[nt][i] = 0.f;
    float mA = -1e30f, mB = -1e30f;

    float l_frag[4] = {0.f, 0.f, 0.f, 0.f};
    const unsigned onesB = (lane < 4) ? 0x3C003C00u : 0u;

    const int rowA = q0 + row0 + gid;
    const int rowB = rowA + 8;
    const unsigned* mrowA = mbits + (size_t)rowA * (N_ / 32);
    const unsigned* mrowB = mbits + (size_t)rowB * (N_ / 32);

    const int iters = N_ / 64;                   // 32
    for (int it = 0; it < iters; it++) {
        const int k0 = it * 64;

        cp_wait<ASTAGES - 2>();
        __syncthreads();

        int pre = it + ASTAGES - 1;
        if (pre < iters) load_kv(pre & (ASTAGES - 1), pre * 64);
        cp_commit();

        uint2 ma2 = *(const uint2*)(mrowA + (k0 >> 5));
        uint2 mb2 = *(const uint2*)(mrowB + (k0 >> 5));
        uint64_t maskA = (uint64_t)ma2.x | ((uint64_t)ma2.y << 32);
        uint64_t maskB = (uint64_t)mb2.x | ((uint64_t)mb2.y << 32);

        const int st = it & (ASTAGES - 1);
        const __half* KS = smh + st * KV_STAGE_H;
        const __half* VS = KS + KV_TILE_H;

        // ---- S = Q @ K^T (log2-domain logits) ----
        float s[8][4];
        #pragma unroll
        for (int nt = 0; nt < 8; nt++)
            #pragma unroll
            for (int i = 0; i < 4; i++) s[nt][i] = 0.f;

        #pragma unroll
        for (int ks = 0; ks < 4; ks++) {
            unsigned kb[4][4];
            #pragma unroll
            for (int np = 0; np < 4; np++)
                ldsm_x4(kb[np], &KS[(np * 16 + rsel) * KV_PITCH + ks * 16 + csel]);
            #pragma unroll
            for (int nt = 0; nt < 8; nt++)
                mma_f16(s[nt], qf[ks],
                        kb[nt >> 1][nt & 1], kb[nt >> 1][2 + (nt & 1)]);
        }

        // ---- mask ----
        #pragma unroll
        for (int nt = 0; nt < 8; nt++) {
            int c = nt * 8 + tig * 2;
            if (!((maskA >> c) & 1))       s[nt][0] -= MASKC;
            if (!((maskA >> (c + 1)) & 1)) s[nt][1] -= MASKC;
            if (!((maskB >> c) & 1))       s[nt][2] -= MASKC;
            if (!((maskB >> (c + 1)) & 1)) s[nt][3] -= MASKC;
        }

        // ---- warp-local online softmax (base-2) ----
        float mxA = -1e30f, mxB = -1e30f;
        #pragma unroll
        for (int nt = 0; nt < 8; nt++) {
            mxA = fmaxf(mxA, fmaxf(s[nt][0], s[nt][1]));
            mxB = fmaxf(mxB, fmaxf(s[nt][2], s[nt][3]));
        }
        mxA = fmaxf(mxA, __shfl_xor_sync(0xffffffffu, mxA, 1));
        mxA = fmaxf(mxA, __shfl_xor_sync(0xffffffffu, mxA, 2));
        mxB = fmaxf(mxB, __shfl_xor_sync(0xffffffffu, mxB, 1));
        mxB = fmaxf(mxB, __shfl_xor_sync(0xffffffffu, mxB, 2));

        float mnA = fmaxf(mA, mxA), mnB = fmaxf(mB, mxB);
        float alA = ex2f(mA - mnA), alB = ex2f(mB - mnB);
        mA = mnA; mB = mnB;

        l_frag[0] *= alA; l_frag[1] *= alA;
        l_frag[2] *= alB; l_frag[3] *= alB;

        unsigned ph[8][2];
        #pragma unroll
        for (int nt = 0; nt < 8; nt++) {
            ph[nt][0] = ex2_h2(s[nt][0] - mnA, s[nt][1] - mnA);
            ph[nt][1] = ex2_h2(s[nt][2] - mnB, s[nt][3] - mnB);
            O[nt][0] *= alA; O[nt][1] *= alA;
            O[nt][2] *= alB; O[nt][3] *= alB;
        }

        // ---- O += P @ V ; l += P @ ones (both from P registers) ----
        #pragma unroll
        for (int ks = 0; ks < 4; ks++) {
            unsigned vb[4][4];
            #pragma unroll
            for (int dp = 0; dp < 4; dp++)
                ldsm_x4_t(vb[dp], &VS[(ks * 16 + rsel) * KV_PITCH + dp * 16 + csel]);
            unsigned pa[4] = { ph[2 * ks][0], ph[2 * ks][1],
                               ph[2 * ks + 1][0], ph[2 * ks + 1][1] };
            mma_f16(l_frag, pa, onesB, onesB);
            #pragma unroll
            for (int nt = 0; nt < 8; nt++)
                mma_f16(O[nt], pa,
                        vb[nt >> 1][(nt & 1) * 2], vb[nt >> 1][(nt & 1) * 2 + 1]);
        }
    }

    // Finalize: l lives in column 0 of the C fragment (tig==0 lanes)
    float lA = __shfl_sync(0xffffffffu, l_frag[0], lane & 28);
    float lB = __shfl_sync(0xffffffffu, l_frag[2], lane & 28);
    float invA = 1.0f / lA, invB = 1.0f / lB;
    __half* obase = o + (size_t)b * N_ * D_ + h * HD_;
    #pragma unroll
    for (int nt = 0; nt < 8; nt++) {
        int c = nt * 8 + tig * 2;
        *(unsigned*)(obase + (size_t)rowA * D_ + c) =
            h2pack(O[nt][0] * invA, O[nt][1] * invA);
        *(unsigned*)(obase + (size_t)rowB * D_ + c) =
            h2pack(O[nt][2] * invB, O[nt][3] * invB);
    }
}

// ---------------------------------------------------------------------------
extern "C" void kernel_launch(void* const* d_in, const int* in_sizes, int n_in,
                              void* d_out, int out_size)
{
    const float* x   = (const float*)d_in[0];
    const float* adj = (const float*)d_in[1];
    const float* Wq  = (const float*)d_in[2];
    const float* bq  = (const float*)d_in[3];
    const float* Wk  = (const float*)d_in[4];
    const float* bk  = (const float*)d_in[5];
    const float* Wv  = (const float*)d_in[6];
    const float* bv  = (const float*)d_in[7];
    const float* Wo  = (const float*)d_in[8];
    const float* bo  = (const float*)d_in[9];
    float* out = (float*)d_out;

    __half *pxh, *pwqh, *pwkh, *pwvh, *pwoh, *pq, *pk, *pv, *pa;
    unsigned* pbits;
    cudaGetSymbolAddress((void**)&pxh,  g_xh);
    cudaGetSymbolAddress((void**)&pwqh, g_wqh);
    cudaGetSymbolAddress((void**)&pwkh, g_wkh);
    cudaGetSymbolAddress((void**)&pwvh, g_wvh);
    cudaGetSymbolAddress((void**)&pwoh, g_woh);
    cudaGetSymbolAddress((void**)&pq,   g_q);
    cudaGetSymbolAddress((void**)&pk,   g_k);
    cudaGetSymbolAddress((void**)&pv,   g_v);
    cudaGetSymbolAddress((void**)&pa,   g_ao);
    cudaGetSymbolAddress((void**)&pbits, g_adjbits);

    prep_kernel<<<1536, 256>>>(adj, pbits, x, pxh,
                               Wq, pwqh, Wk, pwkh, Wv, pwvh, Wo, pwoh);

    const int M = B_ * N_;                    // 8192
    dim3 qkvGrid(D_ / 128, M / 128, 3);       // (4, 64, 3)
    dim3 oGrid(D_ / 128, M / 128);            // (4, 64)

    cudaFuncSetAttribute(gemm_qkv_kernel,
                         cudaFuncAttributeMaxDynamicSharedMemorySize,
                         GEMM_SMEM_BYTES);
    cudaFuncSetAttribute(gemm_out_kernel,
                         cudaFuncAttributeMaxDynamicSharedMemorySize,
                         GEMM_SMEM_BYTES);
    cudaFuncSetAttribute(attn_f16_kernel,
                         cudaFuncAttributeMaxDynamicSharedMemorySize,
                         ATTN_SMEM_BYTES);

    gemm_qkv_kernel<<<qkvGrid, 256, GEMM_SMEM_BYTES>>>(
        pxh, pwqh, pwkh, pwvh, bq, bk, bv, pq, pk, pv, M, D_, D_);

    attn_f16_kernel<<<dim3(N_ / 256, H_, B_), ATHREADS, ATTN_SMEM_BYTES>>>(
        pq, pk, pv, pbits, pa);

    gemm_out_kernel<<<oGrid, 256, GEMM_SMEM_BYTES>>>(
        pa, pwoh, bo, out, M, D_, D_);
}